// round 1
// baseline (speedup 1.0000x reference)
#include <cuda_runtime.h>
#include <math.h>

#define BB 2
#define TT 2048
#define DD 1024
#define NHEAD 16
#define HDIM 64
#define FFN 4096
#define BT (BB*TT)
#define NGV 50000

// ---------------- scratch (device globals; no allocation) ----------------
__device__ float g_xn[BT*DD];
__device__ float g_q[BT*DD];
__device__ float g_k[BT*DD];
__device__ float g_v[BT*DD];
__device__ float g_o[BT*DD];
__device__ float g_h[BT*DD];
__device__ float g_hn[BT*DD];
__device__ float g_gate[(size_t)BT*FFN];
__device__ float g_up[(size_t)BT*FFN];
__device__ float g_emb[BT*DD];
__device__ float g_keye[BT*DD];
__device__ float g_vale[BT*DD];
__device__ float g_value[BT*DD];

// ---------------- RMSNorm: one block per row, 256 threads ----------------
__global__ void rmsnorm_k(const float* __restrict__ x, const float* __restrict__ w,
                          float* __restrict__ y) {
    int row = blockIdx.x, tid = threadIdx.x;
    const float4* xp = (const float4*)(x + (size_t)row * DD);
    float4 xv = xp[tid];
    float ss = xv.x*xv.x + xv.y*xv.y + xv.z*xv.z + xv.w*xv.w;
    #pragma unroll
    for (int o = 16; o; o >>= 1) ss += __shfl_xor_sync(0xffffffffu, ss, o);
    __shared__ float red[8];
    if ((tid & 31) == 0) red[tid >> 5] = ss;
    __syncthreads();
    float tot = 0.f;
    #pragma unroll
    for (int i = 0; i < 8; i++) tot += red[i];
    float inv = rsqrtf(tot * (1.0f / DD) + 1e-6f);
    float4 wv = ((const float4*)w)[tid];
    float4 r;
    r.x = xv.x * inv * wv.x; r.y = xv.y * inv * wv.y;
    r.z = xv.z * inv * wv.z; r.w = xv.w * inv * wv.w;
    ((float4*)(y + (size_t)row * DD))[tid] = r;
}

// ---------------- SGEMM NT: C[M,N] = A[M,K] * B[N,K]^T (+bias[n]) (+addC) --
// 128x128 tile, BK=8, 256 threads, 8x8 micro-tile.
__global__ void __launch_bounds__(256, 2) sgemm_nt(
    const float* __restrict__ A, const float* __restrict__ Bm,
    float* __restrict__ C, const float* __restrict__ addC,
    const float* __restrict__ bias, int M, int N, int K)
{
    __shared__ float As[8][128];
    __shared__ float Bs[8][128];
    const int tid = threadIdx.x;
    const int tx = tid & 15, ty = tid >> 4;
    const int lr = tid >> 1;
    const int lc = (tid & 1) * 4;
    const float* Ap = A + (size_t)(blockIdx.y * 128 + lr) * K + lc;
    const float* Bp = Bm + (size_t)(blockIdx.x * 128 + lr) * K + lc;
    float4 av = *(const float4*)Ap;
    float4 bv = *(const float4*)Bp;
    float acc[8][8];
    #pragma unroll
    for (int i = 0; i < 8; i++)
        #pragma unroll
        for (int j = 0; j < 8; j++) acc[i][j] = 0.f;

    for (int k0 = 0; k0 < K; k0 += 8) {
        As[lc+0][lr] = av.x; As[lc+1][lr] = av.y; As[lc+2][lr] = av.z; As[lc+3][lr] = av.w;
        Bs[lc+0][lr] = bv.x; Bs[lc+1][lr] = bv.y; Bs[lc+2][lr] = bv.z; Bs[lc+3][lr] = bv.w;
        __syncthreads();
        if (k0 + 8 < K) {
            av = *(const float4*)(Ap + k0 + 8);
            bv = *(const float4*)(Bp + k0 + 8);
        }
        #pragma unroll
        for (int kk = 0; kk < 8; kk++) {
            float4 a0 = *(const float4*)&As[kk][ty*8];
            float4 a1 = *(const float4*)&As[kk][ty*8+4];
            float4 b0 = *(const float4*)&Bs[kk][tx*8];
            float4 b1 = *(const float4*)&Bs[kk][tx*8+4];
            float ar[8] = {a0.x,a0.y,a0.z,a0.w,a1.x,a1.y,a1.z,a1.w};
            float br[8] = {b0.x,b0.y,b0.z,b0.w,b1.x,b1.y,b1.z,b1.w};
            #pragma unroll
            for (int i = 0; i < 8; i++)
                #pragma unroll
                for (int j = 0; j < 8; j++)
                    acc[i][j] += ar[i] * br[j];
        }
        __syncthreads();
    }

    const int cn = blockIdx.x * 128 + tx * 8;
    float4 bi0 = make_float4(0,0,0,0), bi1 = make_float4(0,0,0,0);
    if (bias) {
        bi0 = *(const float4*)(bias + cn);
        bi1 = *(const float4*)(bias + cn + 4);
    }
    #pragma unroll
    for (int i = 0; i < 8; i++) {
        size_t m = (size_t)blockIdx.y * 128 + ty * 8 + i;
        float* cp = C + m * N + cn;
        float4 r0 = make_float4(acc[i][0]+bi0.x, acc[i][1]+bi0.y, acc[i][2]+bi0.z, acc[i][3]+bi0.w);
        float4 r1 = make_float4(acc[i][4]+bi1.x, acc[i][5]+bi1.y, acc[i][6]+bi1.z, acc[i][7]+bi1.w);
        if (addC) {
            const float* ap2 = addC + m * N + cn;
            float4 d0 = *(const float4*)ap2;
            float4 d1 = *(const float4*)(ap2 + 4);
            r0.x += d0.x; r0.y += d0.y; r0.z += d0.z; r0.w += d0.w;
            r1.x += d1.x; r1.y += d1.y; r1.z += d1.z; r1.w += d1.w;
        }
        *(float4*)cp = r0;
        *(float4*)(cp + 4) = r1;
    }
}

// ---------------- RoPE in-place on q,k ----------------
__global__ void rope_k(float* __restrict__ q, float* __restrict__ k) {
    int idx = blockIdx.x * 256 + threadIdx.x;  // BT*16*32
    int i = idx & 31;
    int bth = idx >> 5;
    int h = bth & 15;
    int bt = bth >> 4;
    int t = bt & (TT - 1);
    // inv_freq = 10000^(-2i/64)
    float invf = expf(-(float)(2 * i) * (1.0f / 64.0f) * 9.2103403719761836f);
    float ang = (float)t * invf;
    float s, c;
    sincosf(ang, &s, &c);
    size_t base = (size_t)bt * DD + h * 64 + i;
    float a = q[base], b = q[base + 32];
    q[base]      = a * c - b * s;
    q[base + 32] = b * c + a * s;
    float ak = k[base], bk = k[base + 32];
    k[base]      = ak * c - bk * s;
    k[base + 32] = bk * c + ak * s;
}

// ---------------- Flash attention (fp32, causal) ----------------
// grid: (T/64, B*H), 256 threads. smem: Qs,Ks,Vs,Ps each [64][68].
#define FSTR 68
extern __shared__ float fsm[];
__global__ void __launch_bounds__(256) flash_attn(
    const float* __restrict__ q, const float* __restrict__ k,
    const float* __restrict__ v, float* __restrict__ o)
{
    float* Qs = fsm;
    float* Ks = Qs + 64 * FSTR;
    float* Vs = Ks + 64 * FSTR;
    float* Ps = Vs + 64 * FSTR;
    int qt = blockIdx.x;
    int bh = blockIdx.y;
    int b = bh >> 4, h = bh & 15;
    int q0 = qt * 64;
    int tid = threadIdx.x;
    int tx = tid & 15, ty = tid >> 4;
    const float* qbase = q + (size_t)b * TT * DD + h * HDIM;
    const float* kbase = k + (size_t)b * TT * DD + h * HDIM;
    const float* vbase = v + (size_t)b * TT * DD + h * HDIM;

    // load Q tile transposed: Qs[d][m]
    for (int i4 = tid; i4 < 1024; i4 += 256) {
        int m = i4 >> 4, d4 = (i4 & 15) << 2;
        float4 qv = *(const float4*)(qbase + (size_t)(q0 + m) * DD + d4);
        Qs[(d4+0)*FSTR + m] = qv.x; Qs[(d4+1)*FSTR + m] = qv.y;
        Qs[(d4+2)*FSTR + m] = qv.z; Qs[(d4+3)*FSTR + m] = qv.w;
    }

    float m_i[4], l_i[4], accO[4][4];
    #pragma unroll
    for (int i = 0; i < 4; i++) {
        m_i[i] = -1e30f; l_i[i] = 0.f;
        #pragma unroll
        for (int j = 0; j < 4; j++) accO[i][j] = 0.f;
    }

    for (int kt = 0; kt <= qt; kt++) {
        __syncthreads();  // protect Ks/Vs/Ps reuse
        for (int i4 = tid; i4 < 1024; i4 += 256) {
            int n = i4 >> 4, d4 = (i4 & 15) << 2;
            float4 kv = *(const float4*)(kbase + (size_t)(kt*64 + n) * DD + d4);
            Ks[(d4+0)*FSTR + n] = kv.x; Ks[(d4+1)*FSTR + n] = kv.y;
            Ks[(d4+2)*FSTR + n] = kv.z; Ks[(d4+3)*FSTR + n] = kv.w;
            float4 vv = *(const float4*)(vbase + (size_t)(kt*64 + n) * DD + d4);
            *(float4*)&Vs[n*FSTR + d4] = vv;
        }
        __syncthreads();

        float s[4][4];
        #pragma unroll
        for (int i = 0; i < 4; i++)
            #pragma unroll
            for (int j = 0; j < 4; j++) s[i][j] = 0.f;
        #pragma unroll 4
        for (int d = 0; d < 64; d++) {
            float4 qa = *(const float4*)&Qs[d*FSTR + ty*4];
            float4 kb = *(const float4*)&Ks[d*FSTR + tx*4];
            float aq[4] = {qa.x,qa.y,qa.z,qa.w};
            float bk[4] = {kb.x,kb.y,kb.z,kb.w};
            #pragma unroll
            for (int i = 0; i < 4; i++)
                #pragma unroll
                for (int j = 0; j < 4; j++)
                    s[i][j] += aq[i] * bk[j];
        }
        // scale + causal mask
        #pragma unroll
        for (int i = 0; i < 4; i++) {
            int qrow = q0 + ty*4 + i;
            #pragma unroll
            for (int j = 0; j < 4; j++) {
                int kcol = kt*64 + tx*4 + j;
                float val = s[i][j] * 0.125f;
                if (kcol > qrow) val = -1e9f;
                s[i][j] = val;
            }
        }
        // online softmax (row groups = 16 contiguous lanes)
        #pragma unroll
        for (int i = 0; i < 4; i++) {
            float rmax = fmaxf(fmaxf(s[i][0], s[i][1]), fmaxf(s[i][2], s[i][3]));
            #pragma unroll
            for (int off = 8; off; off >>= 1)
                rmax = fmaxf(rmax, __shfl_xor_sync(0xffffffffu, rmax, off));
            float mnew = fmaxf(m_i[i], rmax);
            float corr = __expf(m_i[i] - mnew);
            float rsum = 0.f;
            #pragma unroll
            for (int j = 0; j < 4; j++) {
                float p = __expf(s[i][j] - mnew);
                s[i][j] = p;
                rsum += p;
            }
            #pragma unroll
            for (int off = 8; off; off >>= 1)
                rsum += __shfl_xor_sync(0xffffffffu, rsum, off);
            l_i[i] = l_i[i] * corr + rsum;
            m_i[i] = mnew;
            #pragma unroll
            for (int j = 0; j < 4; j++) accO[i][j] *= corr;
            #pragma unroll
            for (int j = 0; j < 4; j++)
                Ps[(tx*4 + j)*FSTR + ty*4 + i] = s[i][j];
        }
        __syncthreads();
        // accO += P @ V
        #pragma unroll 4
        for (int n = 0; n < 64; n++) {
            float4 pf = *(const float4*)&Ps[n*FSTR + ty*4];
            float4 vf = *(const float4*)&Vs[n*FSTR + tx*4];
            float pp[4] = {pf.x,pf.y,pf.z,pf.w};
            float vv[4] = {vf.x,vf.y,vf.z,vf.w};
            #pragma unroll
            for (int i = 0; i < 4; i++)
                #pragma unroll
                for (int j = 0; j < 4; j++)
                    accO[i][j] += pp[i] * vv[j];
        }
    }

    float* obase = o + (size_t)b * TT * DD + h * HDIM;
    #pragma unroll
    for (int i = 0; i < 4; i++) {
        float inv = 1.0f / l_i[i];
        float4 r = make_float4(accO[i][0]*inv, accO[i][1]*inv, accO[i][2]*inv, accO[i][3]*inv);
        *(float4*)(obase + (size_t)(q0 + ty*4 + i) * DD + tx*4) = r;
    }
}

// ---------------- silu(g) * u ----------------
__global__ void silumul_k(const float* __restrict__ g, const float* __restrict__ u,
                          float* __restrict__ o) {
    size_t i = (size_t)blockIdx.x * 256 + threadIdx.x;
    float4 gv = ((const float4*)g)[i];
    float4 uv = ((const float4*)u)[i];
    float4 r;
    r.x = gv.x / (1.f + expf(-gv.x)) * uv.x;
    r.y = gv.y / (1.f + expf(-gv.y)) * uv.y;
    r.z = gv.z / (1.f + expf(-gv.z)) * uv.z;
    r.w = gv.w / (1.f + expf(-gv.w)) * uv.w;
    ((float4*)o)[i] = r;
}

// ---------------- engram hash + gather ----------------
__global__ void gather_k(const int* __restrict__ ids, const float* __restrict__ tables,
                         const int* __restrict__ hm, float* __restrict__ emb) {
    int tok = blockIdx.x;           // b*T + t
    int t = tok & (TT - 1);
    int id0 = ids[tok];
    int id1 = (t >= 1) ? ids[tok - 1] : 0;
    int id2 = (t >= 2) ? ids[tok - 2] : 0;
    unsigned m0 = (unsigned)hm[0], m1 = (unsigned)hm[1], m2 = (unsigned)hm[2];
    unsigned h2 = (unsigned)id0 * m0 ^ (unsigned)id1 * m1;
    unsigned h3 = h2 ^ (unsigned)id2 * m2;
    int tid = threadIdx.x;
    float* out = emb + (size_t)tok * 1024;
    #pragma unroll
    for (int r = 0; r < 4; r++) {
        int e = tid + r * 256;
        int tt = e >> 6, ee = e & 63;
        int head = tt & 7;
        unsigned hh = ((tt < 8) ? h2 : h3) + (unsigned)(head * 7919);
        int sv = (int)hh;
        int idx = sv % NGV;
        if (idx < 0) idx += NGV;
        out[e] = tables[((size_t)tt * NGV + idx) * 64 + ee];
    }
}

// ---------------- gate: rms(key_e)·rms(hn) -> sigmoid -> value = g*val_e ---
__global__ void gate_k(const float* __restrict__ hn, const float* __restrict__ keye,
                       const float* __restrict__ vale, const float* __restrict__ nkw,
                       const float* __restrict__ nqw, float* __restrict__ value) {
    int row = blockIdx.x, tid = threadIdx.x;
    float4 kv = ((const float4*)(keye + (size_t)row * DD))[tid];
    float4 hv = ((const float4*)(hn + (size_t)row * DD))[tid];
    float4 wk = ((const float4*)nkw)[tid];
    float4 wq = ((const float4*)nqw)[tid];
    float skk = kv.x*kv.x + kv.y*kv.y + kv.z*kv.z + kv.w*kv.w;
    float shh = hv.x*hv.x + hv.y*hv.y + hv.z*hv.z + hv.w*hv.w;
    float sdt = kv.x*wk.x*hv.x*wq.x + kv.y*wk.y*hv.y*wq.y
              + kv.z*wk.z*hv.z*wq.z + kv.w*wk.w*hv.w*wq.w;
    #pragma unroll
    for (int o = 16; o; o >>= 1) {
        skk += __shfl_xor_sync(0xffffffffu, skk, o);
        shh += __shfl_xor_sync(0xffffffffu, shh, o);
        sdt += __shfl_xor_sync(0xffffffffu, sdt, o);
    }
    __shared__ float r1[8], r2[8], r3[8];
    if ((tid & 31) == 0) { r1[tid>>5] = skk; r2[tid>>5] = shh; r3[tid>>5] = sdt; }
    __syncthreads();
    float tkk = 0, thh = 0, tdt = 0;
    #pragma unroll
    for (int i = 0; i < 8; i++) { tkk += r1[i]; thh += r2[i]; tdt += r3[i]; }
    float nk = rsqrtf(tkk * (1.0f / DD) + 1e-6f);
    float nh = rsqrtf(thh * (1.0f / DD) + 1e-6f);
    float g = tdt * nk * nh * (1.0f / 32.0f);   // /sqrt(D)
    float ab = fabsf(g);
    float rt = sqrtf(fmaxf(ab, 1e-6f));
    float sgn = (g > 0.f) ? 1.f : ((g < 0.f) ? -1.f : 0.f);
    float gs = rt * sgn;
    float sig = 1.f / (1.f + expf(-gs));
    float4 vv = ((const float4*)(vale + (size_t)row * DD))[tid];
    float4 r = make_float4(sig*vv.x, sig*vv.y, sig*vv.z, sig*vv.w);
    ((float4*)(value + (size_t)row * DD))[tid] = r;
}

// ---------------- final: out += value + silu(depthwise causal conv) -------
__global__ void final_k(const float* __restrict__ value, const float* __restrict__ cw,
                        float* __restrict__ out) {
    int idx = blockIdx.x * 256 + threadIdx.x;   // BT*D
    int d = idx & (DD - 1);
    int bt = idx >> 10;
    int t = bt & (TT - 1);
    float c = 0.f;
    #pragma unroll
    for (int kk = 0; kk < 4; kk++) {
        int tt = t - 3 + kk;
        if (tt >= 0)
            c += value[(size_t)(bt - 3 + kk) * DD + d] * cw[d * 4 + kk];
    }
    float vv = value[idx];
    float sc = c / (1.f + expf(-c));
    out[idx] += vv + sc;
}

// ---------------- host ----------------
static float* symaddr(const void* sym) {
    void* p = nullptr;
    cudaGetSymbolAddress(&p, sym);
    return (float*)p;
}

extern "C" void kernel_launch(void* const* d_in, const int* in_sizes, int n_in,
                              void* d_out, int out_size) {
    const float* x     = (const float*)d_in[0];
    const int*   ids   = (const int*)d_in[1];
    // d_in[2] = mask (causal, reproduced by index compare)
    const float* wq    = (const float*)d_in[3];
    const float* wk    = (const float*)d_in[4];
    const float* wv    = (const float*)d_in[5];
    const float* wo    = (const float*)d_in[6];
    const float* attnw = (const float*)d_in[7];
    const float* ffnw  = (const float*)d_in[8];
    const float* gatew = (const float*)d_in[9];
    const float* upw   = (const float*)d_in[10];
    const float* downw = (const float*)d_in[11];
    const float* embt  = (const float*)d_in[12];
    const float* keyw  = (const float*)d_in[13];
    const float* keyb  = (const float*)d_in[14];
    const float* valw  = (const float*)d_in[15];
    const float* valb  = (const float*)d_in[16];
    const float* normk = (const float*)d_in[17];
    const float* normq = (const float*)d_in[18];
    const float* convw = (const float*)d_in[19];
    const int*   hm    = (const int*)d_in[20];

    float* p_xn   = symaddr(g_xn);
    float* p_q    = symaddr(g_q);
    float* p_k    = symaddr(g_k);
    float* p_v    = symaddr(g_v);
    float* p_o    = symaddr(g_o);
    float* p_h    = symaddr(g_h);
    float* p_hn   = symaddr(g_hn);
    float* p_gate = symaddr(g_gate);
    float* p_up   = symaddr(g_up);
    float* p_emb  = symaddr(g_emb);
    float* p_keye = symaddr(g_keye);
    float* p_vale = symaddr(g_vale);
    float* p_val  = symaddr(g_value);

    float* out = (float*)d_out;

    dim3 blk(256);
    dim3 gD(DD / 128, BT / 128);     // N=1024 GEMMs
    dim3 gF(FFN / 128, BT / 128);    // N=4096 GEMMs

    // attention
    rmsnorm_k<<<BT, blk>>>(x, attnw, p_xn);
    sgemm_nt<<<gD, blk>>>(p_xn, wq, p_q, nullptr, nullptr, BT, DD, DD);
    sgemm_nt<<<gD, blk>>>(p_xn, wk, p_k, nullptr, nullptr, BT, DD, DD);
    sgemm_nt<<<gD, blk>>>(p_xn, wv, p_v, nullptr, nullptr, BT, DD, DD);
    rope_k<<<(BT * NHEAD * 32) / 256, blk>>>(p_q, p_k);

    cudaFuncSetAttribute(flash_attn, cudaFuncAttributeMaxDynamicSharedMemorySize, 4 * 64 * FSTR * 4);
    flash_attn<<<dim3(TT / 64, BB * NHEAD), blk, 4 * 64 * FSTR * 4>>>(p_q, p_k, p_v, p_o);

    sgemm_nt<<<gD, blk>>>(p_o, wo, p_h, x, nullptr, BT, DD, DD);

    // FFN
    rmsnorm_k<<<BT, blk>>>(p_h, ffnw, p_hn);
    sgemm_nt<<<gF, blk>>>(p_hn, gatew, p_gate, nullptr, nullptr, BT, FFN, DD);
    sgemm_nt<<<gF, blk>>>(p_hn, upw, p_up, nullptr, nullptr, BT, FFN, DD);
    silumul_k<<<((size_t)BT * FFN) / 1024, blk>>>(p_gate, p_up, p_gate);
    sgemm_nt<<<gD, blk>>>(p_gate, downw, out, p_h, nullptr, BT, DD, FFN);

    // engram
    gather_k<<<BT, blk>>>(ids, embt, hm, p_emb);
    sgemm_nt<<<gD, blk>>>(p_emb, keyw, p_keye, nullptr, keyb, BT, DD, DD);
    sgemm_nt<<<gD, blk>>>(p_emb, valw, p_vale, nullptr, valb, BT, DD, DD);
    gate_k<<<BT, blk>>>(p_hn, p_keye, p_vale, normk, normq, p_val);
    final_k<<<(BT * DD) / 256, blk>>>(p_val, convw, out);
}

// round 3
// speedup vs baseline: 1.9715x; 1.9715x over previous
#include <cuda_runtime.h>
#include <cuda_bf16.h>
#include <math.h>
#include <stdint.h>

#define BB 2
#define TT 2048
#define DD 1024
#define NHEAD 16
#define HDIM 64
#define FFN 4096
#define BT (BB*TT)
#define NGV 50000

typedef __nv_bfloat16 bf16;

// ---------------- scratch (device globals; no allocation) ----------------
__device__ float g_q[BT*DD];
__device__ float g_k[BT*DD];
__device__ float g_v[BT*DD];
__device__ float g_h[BT*DD];
__device__ float g_hn[BT*DD];
__device__ float g_gate[(size_t)BT*FFN];
__device__ float g_up[(size_t)BT*FFN];
__device__ float g_keye[BT*DD];
__device__ float g_vale[BT*DD];
__device__ float g_value[BT*DD];
// bf16 split buffers: A up to BTxFFN, B (weights) up to FFNxDD
__device__ __align__(16) bf16 g_ah[(size_t)BT*FFN];
__device__ __align__(16) bf16 g_al[(size_t)BT*FFN];
__device__ __align__(16) bf16 g_bh[(size_t)FFN*DD];
__device__ __align__(16) bf16 g_bl[(size_t)FFN*DD];

extern __shared__ char dynsmem[];

// ================= low-level helpers =================
__device__ __forceinline__ uint32_t smem_u32(const void* p) {
    uint32_t a;
    asm("{ .reg .u64 t; cvta.to.shared.u64 t, %1; cvt.u32.u64 %0, t; }" : "=r"(a) : "l"(p));
    return a;
}
__device__ __forceinline__ void cp16(uint32_t s, const void* g) {
    asm volatile("cp.async.cg.shared.global [%0], [%1], 16;" :: "r"(s), "l"(g));
}
#define CP_COMMIT() asm volatile("cp.async.commit_group;")
#define CP_WAIT1()  asm volatile("cp.async.wait_group 1;")

__device__ __forceinline__ void ldsm4(uint32_t* r, uint32_t addr) {
    asm volatile("ldmatrix.sync.aligned.m8n8.x4.shared.b16 {%0,%1,%2,%3}, [%4];"
        : "=r"(r[0]), "=r"(r[1]), "=r"(r[2]), "=r"(r[3]) : "r"(addr));
}
__device__ __forceinline__ void mma16816(float* d, const uint32_t* a, const uint32_t* b) {
    asm volatile("mma.sync.aligned.m16n8k16.row.col.f32.bf16.bf16.f32 "
        "{%0,%1,%2,%3}, {%4,%5,%6,%7}, {%8,%9}, {%0,%1,%2,%3};"
        : "+f"(d[0]), "+f"(d[1]), "+f"(d[2]), "+f"(d[3])
        : "r"(a[0]), "r"(a[1]), "r"(a[2]), "r"(a[3]), "r"(b[0]), "r"(b[1]));
}
__device__ __forceinline__ void split1(float v, bf16& h, bf16& l) {
    h = __float2bfloat16(v);
    l = __float2bfloat16(v - __bfloat162float(h));
}

// ================= split-bf16 mma.sync GEMM =================
// C[M,N] = A[M,K]*B[N,K]^T (+bias[n]) (+addC)  -- fp32 via AhBh + AhBl + AlBh
// CTA 128x128, BK=32, 3 stages cp.async. 8 warps: 4(M) x 2(N), warp tile 32x64.
#define LDT 40
#define TILE_B (128*LDT*2)       // 10240 bytes per operand tile
#define STAGE_B (4*TILE_B)       // 40960
#define GEMM_SMEM (3*STAGE_B)    // 122880

__global__ void __launch_bounds__(256, 1) gemm_mma(
    const bf16* __restrict__ a_hi, const bf16* __restrict__ a_lo,
    const bf16* __restrict__ b_hi, const bf16* __restrict__ b_lo,
    float* __restrict__ C, const float* __restrict__ addC,
    const float* __restrict__ bias, int M, int N, int K)
{
    const uint32_t sb = smem_u32(dynsmem);
    const int tid = threadIdx.x;
    const int wid = tid >> 5, lane = tid & 31;
    const int wm = wid & 3, wn = wid >> 2;
    const int m0 = blockIdx.y * 128, n0 = blockIdx.x * 128;
    const int NT = K >> 5;

    float acc[2][8][4];
    #pragma unroll
    for (int i = 0; i < 2; i++)
        #pragma unroll
        for (int j = 0; j < 8; j++)
            #pragma unroll
            for (int q = 0; q < 4; q++) acc[i][j][q] = 0.f;

    // loader lambda: stage s, k-offset kk
    const int ch0 = tid, ch1 = tid + 256;
    const int r0 = ch0 >> 2, c0 = (ch0 & 3) << 3;
    const int r1 = ch1 >> 2, c1 = (ch1 & 3) << 3;
    const uint32_t so0 = (uint32_t)(r0 * LDT + c0) * 2;
    const uint32_t so1 = (uint32_t)(r1 * LDT + c1) * 2;

    auto ldst = [&](int s, int kk) {
        uint32_t st = sb + s * STAGE_B;
        {
            size_t ga = (size_t)(m0 + r0) * K + kk + c0;
            size_t gb = (size_t)(n0 + r0) * K + kk + c0;
            cp16(st + so0,              a_hi + ga);
            cp16(st + TILE_B + so0,     a_lo + ga);
            cp16(st + 2*TILE_B + so0,   b_hi + gb);
            cp16(st + 3*TILE_B + so0,   b_lo + gb);
        }
        {
            size_t ga = (size_t)(m0 + r1) * K + kk + c1;
            size_t gb = (size_t)(n0 + r1) * K + kk + c1;
            cp16(st + so1,              a_hi + ga);
            cp16(st + TILE_B + so1,     a_lo + ga);
            cp16(st + 2*TILE_B + so1,   b_hi + gb);
            cp16(st + 3*TILE_B + so1,   b_lo + gb);
        }
        CP_COMMIT();
    };

    ldst(0, 0);
    ldst(1, 32);

    // precomputed ldmatrix intra-warp offsets
    const int a_r = (lane & 15), a_c = (lane >> 4) << 3;
    const int b_r = ((lane & 16) >> 1) + (lane & 7), b_c = (lane & 8);

    for (int kt = 0; kt < NT; kt++) {
        CP_WAIT1();
        __syncthreads();
        uint32_t st = sb + (kt % 3) * STAGE_B;
        #pragma unroll
        for (int k16 = 0; k16 < 2; k16++) {
            const int kof = k16 * 16;
            uint32_t ah[2][4], alr[2][4];
            #pragma unroll
            for (int mt = 0; mt < 2; mt++) {
                int row = wm * 32 + mt * 16 + a_r;
                uint32_t off = (uint32_t)(row * LDT + kof + a_c) * 2;
                ldsm4(ah[mt],  st + off);
                ldsm4(alr[mt], st + TILE_B + off);
            }
            uint32_t bh[4][4], blr[4][4];
            #pragma unroll
            for (int p = 0; p < 4; p++) {
                int row = wn * 64 + p * 16 + b_r;
                uint32_t off = (uint32_t)(row * LDT + kof + b_c) * 2;
                ldsm4(bh[p],  st + 2*TILE_B + off);
                ldsm4(blr[p], st + 3*TILE_B + off);
            }
            #pragma unroll
            for (int mt = 0; mt < 2; mt++)
                #pragma unroll
                for (int nt = 0; nt < 8; nt++) {
                    const uint32_t* bhp = &bh[nt >> 1][(nt & 1) * 2];
                    const uint32_t* blp = &blr[nt >> 1][(nt & 1) * 2];
                    mma16816(acc[mt][nt], ah[mt],  bhp);
                    mma16816(acc[mt][nt], ah[mt],  blp);
                    mma16816(acc[mt][nt], alr[mt], bhp);
                }
        }
        if (kt + 2 < NT) ldst((kt + 2) % 3, (kt + 2) * 32);
        else CP_COMMIT();
    }

    // epilogue
    const int g = lane >> 2, t2 = (lane & 3) * 2;
    #pragma unroll
    for (int mt = 0; mt < 2; mt++) {
        #pragma unroll
        for (int nt = 0; nt < 8; nt++) {
            int grow = m0 + wm * 32 + mt * 16 + g;
            int gcol = n0 + wn * 64 + nt * 8 + t2;
            float2 v0 = make_float2(acc[mt][nt][0], acc[mt][nt][1]);
            float2 v1 = make_float2(acc[mt][nt][2], acc[mt][nt][3]);
            if (bias) {
                float2 bv = *(const float2*)(bias + gcol);
                v0.x += bv.x; v0.y += bv.y; v1.x += bv.x; v1.y += bv.y;
            }
            if (addC) {
                float2 d0 = *(const float2*)(addC + (size_t)grow * N + gcol);
                float2 d1 = *(const float2*)(addC + (size_t)(grow + 8) * N + gcol);
                v0.x += d0.x; v0.y += d0.y; v1.x += d1.x; v1.y += d1.y;
            }
            *(float2*)(C + (size_t)grow * N + gcol) = v0;
            *(float2*)(C + (size_t)(grow + 8) * N + gcol) = v1;
        }
    }
}

// ---------------- fp32 -> bf16 hi/lo split (weights) ----------------
__global__ void split_k(const float* __restrict__ x, bf16* __restrict__ hi,
                        bf16* __restrict__ lo, int n4) {
    int i = blockIdx.x * 256 + threadIdx.x;
    if (i >= n4) return;
    float4 v = ((const float4*)x)[i];
    bf16 h0, h1, h2, h3, l0, l1, l2, l3;
    split1(v.x, h0, l0); split1(v.y, h1, l1);
    split1(v.z, h2, l2); split1(v.w, h3, l3);
    ((__nv_bfloat162*)hi)[2*i]   = __nv_bfloat162(h0, h1);
    ((__nv_bfloat162*)hi)[2*i+1] = __nv_bfloat162(h2, h3);
    ((__nv_bfloat162*)lo)[2*i]   = __nv_bfloat162(l0, l1);
    ((__nv_bfloat162*)lo)[2*i+1] = __nv_bfloat162(l2, l3);
}

// ---------------- RMSNorm (writes fp32 + bf16 hi/lo) ----------------
__global__ void rmsnorm_k(const float* __restrict__ x, const float* __restrict__ w,
                          float* __restrict__ y, bf16* __restrict__ hi,
                          bf16* __restrict__ lo) {
    int row = blockIdx.x, tid = threadIdx.x;
    float4 xv = ((const float4*)(x + (size_t)row * DD))[tid];
    float ss = xv.x*xv.x + xv.y*xv.y + xv.z*xv.z + xv.w*xv.w;
    #pragma unroll
    for (int o = 16; o; o >>= 1) ss += __shfl_xor_sync(0xffffffffu, ss, o);
    __shared__ float red[8];
    if ((tid & 31) == 0) red[tid >> 5] = ss;
    __syncthreads();
    float tot = 0.f;
    #pragma unroll
    for (int i = 0; i < 8; i++) tot += red[i];
    float inv = rsqrtf(tot * (1.0f / DD) + 1e-6f);
    float4 wv = ((const float4*)w)[tid];
    float4 r;
    r.x = xv.x * inv * wv.x; r.y = xv.y * inv * wv.y;
    r.z = xv.z * inv * wv.z; r.w = xv.w * inv * wv.w;
    if (y) ((float4*)(y + (size_t)row * DD))[tid] = r;
    bf16 h0,h1,h2,h3,l0,l1,l2,l3;
    split1(r.x,h0,l0); split1(r.y,h1,l1); split1(r.z,h2,l2); split1(r.w,h3,l3);
    size_t base = (size_t)row * DD;
    ((__nv_bfloat162*)(hi + base))[2*tid]   = __nv_bfloat162(h0,h1);
    ((__nv_bfloat162*)(hi + base))[2*tid+1] = __nv_bfloat162(h2,h3);
    ((__nv_bfloat162*)(lo + base))[2*tid]   = __nv_bfloat162(l0,l1);
    ((__nv_bfloat162*)(lo + base))[2*tid+1] = __nv_bfloat162(l2,l3);
}

// ---------------- RoPE ----------------
__global__ void rope_k(float* __restrict__ q, float* __restrict__ k) {
    int idx = blockIdx.x * 256 + threadIdx.x;
    int i = idx & 31;
    int bth = idx >> 5;
    int h = bth & 15;
    int bt = bth >> 4;
    int t = bt & (TT - 1);
    float invf = expf(-(float)(2 * i) * (1.0f / 64.0f) * 9.2103403719761836f);
    float ang = (float)t * invf;
    float s, c;
    sincosf(ang, &s, &c);
    size_t base = (size_t)bt * DD + h * 64 + i;
    float a = q[base], b = q[base + 32];
    q[base]      = a * c - b * s;
    q[base + 32] = b * c + a * s;
    float ak = k[base], bk = k[base + 32];
    k[base]      = ak * c - bk * s;
    k[base + 32] = bk * c + ak * s;
}

// ---------------- Flash attention (fp32, causal); writes bf16 hi/lo output --
#define FSTR 68
__global__ void __launch_bounds__(256) flash_attn(
    const float* __restrict__ q, const float* __restrict__ k,
    const float* __restrict__ v, bf16* __restrict__ ohi, bf16* __restrict__ olo)
{
    float* fsm = (float*)dynsmem;
    float* Qs = fsm;
    float* Ks = Qs + 64 * FSTR;
    float* Vs = Ks + 64 * FSTR;
    float* Ps = Vs + 64 * FSTR;
    int qt = blockIdx.x;
    int bh = blockIdx.y;
    int b = bh >> 4, h = bh & 15;
    int q0 = qt * 64;
    int tid = threadIdx.x;
    int tx = tid & 15, ty = tid >> 4;
    const float* qbase = q + (size_t)b * TT * DD + h * HDIM;
    const float* kbase = k + (size_t)b * TT * DD + h * HDIM;
    const float* vbase = v + (size_t)b * TT * DD + h * HDIM;

    for (int i4 = tid; i4 < 1024; i4 += 256) {
        int m = i4 >> 4, d4 = (i4 & 15) << 2;
        float4 qv = *(const float4*)(qbase + (size_t)(q0 + m) * DD + d4);
        Qs[(d4+0)*FSTR + m] = qv.x; Qs[(d4+1)*FSTR + m] = qv.y;
        Qs[(d4+2)*FSTR + m] = qv.z; Qs[(d4+3)*FSTR + m] = qv.w;
    }

    float m_i[4], l_i[4], accO[4][4];
    #pragma unroll
    for (int i = 0; i < 4; i++) {
        m_i[i] = -1e30f; l_i[i] = 0.f;
        #pragma unroll
        for (int j = 0; j < 4; j++) accO[i][j] = 0.f;
    }

    for (int kt = 0; kt <= qt; kt++) {
        __syncthreads();
        for (int i4 = tid; i4 < 1024; i4 += 256) {
            int n = i4 >> 4, d4 = (i4 & 15) << 2;
            float4 kv = *(const float4*)(kbase + (size_t)(kt*64 + n) * DD + d4);
            Ks[(d4+0)*FSTR + n] = kv.x; Ks[(d4+1)*FSTR + n] = kv.y;
            Ks[(d4+2)*FSTR + n] = kv.z; Ks[(d4+3)*FSTR + n] = kv.w;
            float4 vv = *(const float4*)(vbase + (size_t)(kt*64 + n) * DD + d4);
            *(float4*)&Vs[n*FSTR + d4] = vv;
        }
        __syncthreads();

        float s[4][4];
        #pragma unroll
        for (int i = 0; i < 4; i++)
            #pragma unroll
            for (int j = 0; j < 4; j++) s[i][j] = 0.f;
        #pragma unroll 4
        for (int d = 0; d < 64; d++) {
            float4 qa = *(const float4*)&Qs[d*FSTR + ty*4];
            float4 kb = *(const float4*)&Ks[d*FSTR + tx*4];
            float aq[4] = {qa.x,qa.y,qa.z,qa.w};
            float bk[4] = {kb.x,kb.y,kb.z,kb.w};
            #pragma unroll
            for (int i = 0; i < 4; i++)
                #pragma unroll
                for (int j = 0; j < 4; j++)
                    s[i][j] += aq[i] * bk[j];
        }
        #pragma unroll
        for (int i = 0; i < 4; i++) {
            int qrow = q0 + ty*4 + i;
            #pragma unroll
            for (int j = 0; j < 4; j++) {
                int kcol = kt*64 + tx*4 + j;
                float val = s[i][j] * 0.125f;
                if (kcol > qrow) val = -1e9f;
                s[i][j] = val;
            }
        }
        #pragma unroll
        for (int i = 0; i < 4; i++) {
            float rmax = fmaxf(fmaxf(s[i][0], s[i][1]), fmaxf(s[i][2], s[i][3]));
            #pragma unroll
            for (int off = 8; off; off >>= 1)
                rmax = fmaxf(rmax, __shfl_xor_sync(0xffffffffu, rmax, off));
            float mnew = fmaxf(m_i[i], rmax);
            float corr = __expf(m_i[i] - mnew);
            float rsum = 0.f;
            #pragma unroll
            for (int j = 0; j < 4; j++) {
                float p = __expf(s[i][j] - mnew);
                s[i][j] = p;
                rsum += p;
            }
            #pragma unroll
            for (int off = 8; off; off >>= 1)
                rsum += __shfl_xor_sync(0xffffffffu, rsum, off);
            l_i[i] = l_i[i] * corr + rsum;
            m_i[i] = mnew;
            #pragma unroll
            for (int j = 0; j < 4; j++) accO[i][j] *= corr;
            #pragma unroll
            for (int j = 0; j < 4; j++)
                Ps[(tx*4 + j)*FSTR + ty*4 + i] = s[i][j];
        }
        __syncthreads();
        #pragma unroll 4
        for (int n = 0; n < 64; n++) {
            float4 pf = *(const float4*)&Ps[n*FSTR + ty*4];
            float4 vf = *(const float4*)&Vs[n*FSTR + tx*4];
            float pp[4] = {pf.x,pf.y,pf.z,pf.w};
            float vv[4] = {vf.x,vf.y,vf.z,vf.w};
            #pragma unroll
            for (int i = 0; i < 4; i++)
                #pragma unroll
                for (int j = 0; j < 4; j++)
                    accO[i][j] += pp[i] * vv[j];
        }
    }

    size_t obase = (size_t)b * TT * DD + h * HDIM;
    #pragma unroll
    for (int i = 0; i < 4; i++) {
        float inv = 1.0f / l_i[i];
        size_t adr = obase + (size_t)(q0 + ty*4 + i) * DD + tx*4;
        bf16 h0,h1,h2,h3,l0,l1,l2,l3;
        split1(accO[i][0]*inv, h0, l0);
        split1(accO[i][1]*inv, h1, l1);
        split1(accO[i][2]*inv, h2, l2);
        split1(accO[i][3]*inv, h3, l3);
        *(__nv_bfloat162*)(ohi + adr)     = __nv_bfloat162(h0,h1);
        *(__nv_bfloat162*)(ohi + adr + 2) = __nv_bfloat162(h2,h3);
        *(__nv_bfloat162*)(olo + adr)     = __nv_bfloat162(l0,l1);
        *(__nv_bfloat162*)(olo + adr + 2) = __nv_bfloat162(l2,l3);
    }
}

// ---------------- silu(g)*u -> bf16 hi/lo ----------------
__global__ void silumul_k(const float* __restrict__ g, const float* __restrict__ u,
                          bf16* __restrict__ hi, bf16* __restrict__ lo) {
    size_t i = (size_t)blockIdx.x * 256 + threadIdx.x;
    float4 gv = ((const float4*)g)[i];
    float4 uv = ((const float4*)u)[i];
    float4 r;
    r.x = gv.x / (1.f + expf(-gv.x)) * uv.x;
    r.y = gv.y / (1.f + expf(-gv.y)) * uv.y;
    r.z = gv.z / (1.f + expf(-gv.z)) * uv.z;
    r.w = gv.w / (1.f + expf(-gv.w)) * uv.w;
    bf16 h0,h1,h2,h3,l0,l1,l2,l3;
    split1(r.x,h0,l0); split1(r.y,h1,l1); split1(r.z,h2,l2); split1(r.w,h3,l3);
    ((__nv_bfloat162*)hi)[2*i]   = __nv_bfloat162(h0,h1);
    ((__nv_bfloat162*)hi)[2*i+1] = __nv_bfloat162(h2,h3);
    ((__nv_bfloat162*)lo)[2*i]   = __nv_bfloat162(l0,l1);
    ((__nv_bfloat162*)lo)[2*i+1] = __nv_bfloat162(l2,l3);
}

// ---------------- engram hash + gather -> bf16 hi/lo ----------------
__global__ void gather_k(const int* __restrict__ ids, const float* __restrict__ tables,
                         const int* __restrict__ hm, bf16* __restrict__ hi,
                         bf16* __restrict__ lo) {
    int tok = blockIdx.x;
    int t = tok & (TT - 1);
    int id0 = ids[tok];
    int id1 = (t >= 1) ? ids[tok - 1] : 0;
    int id2 = (t >= 2) ? ids[tok - 2] : 0;
    unsigned m0 = (unsigned)hm[0], m1 = (unsigned)hm[1], m2 = (unsigned)hm[2];
    unsigned h2 = (unsigned)id0 * m0 ^ (unsigned)id1 * m1;
    unsigned h3 = h2 ^ (unsigned)id2 * m2;
    int tid = threadIdx.x;
    size_t ob = (size_t)tok * 1024;
    #pragma unroll
    for (int r = 0; r < 4; r++) {
        int e = tid + r * 256;
        int tt = e >> 6, ee = e & 63;
        int head = tt & 7;
        unsigned hh = ((tt < 8) ? h2 : h3) + (unsigned)(head * 7919);
        int sv = (int)hh;
        int idx = sv % NGV;
        if (idx < 0) idx += NGV;
        float f = tables[((size_t)tt * NGV + idx) * 64 + ee];
        bf16 hb, lb;
        split1(f, hb, lb);
        hi[ob + e] = hb;
        lo[ob + e] = lb;
    }
}

// ---------------- gate ----------------
__global__ void gate_k(const float* __restrict__ hn, const float* __restrict__ keye,
                       const float* __restrict__ vale, const float* __restrict__ nkw,
                       const float* __restrict__ nqw, float* __restrict__ value) {
    int row = blockIdx.x, tid = threadIdx.x;
    float4 kv = ((const float4*)(keye + (size_t)row * DD))[tid];
    float4 hv = ((const float4*)(hn + (size_t)row * DD))[tid];
    float4 wk = ((const float4*)nkw)[tid];
    float4 wq = ((const float4*)nqw)[tid];
    float skk = kv.x*kv.x + kv.y*kv.y + kv.z*kv.z + kv.w*kv.w;
    float shh = hv.x*hv.x + hv.y*hv.y + hv.z*hv.z + hv.w*hv.w;
    float sdt = kv.x*wk.x*hv.x*wq.x + kv.y*wk.y*hv.y*wq.y
              + kv.z*wk.z*hv.z*wq.z + kv.w*wk.w*hv.w*wq.w;
    #pragma unroll
    for (int o = 16; o; o >>= 1) {
        skk += __shfl_xor_sync(0xffffffffu, skk, o);
        shh += __shfl_xor_sync(0xffffffffu, shh, o);
        sdt += __shfl_xor_sync(0xffffffffu, sdt, o);
    }
    __shared__ float r1[8], r2[8], r3[8];
    if ((tid & 31) == 0) { r1[tid>>5] = skk; r2[tid>>5] = shh; r3[tid>>5] = sdt; }
    __syncthreads();
    float tkk = 0, thh = 0, tdt = 0;
    #pragma unroll
    for (int i = 0; i < 8; i++) { tkk += r1[i]; thh += r2[i]; tdt += r3[i]; }
    float nk = rsqrtf(tkk * (1.0f / DD) + 1e-6f);
    float nh = rsqrtf(thh * (1.0f / DD) + 1e-6f);
    float g = tdt * nk * nh * (1.0f / 32.0f);
    float ab = fabsf(g);
    float rt = sqrtf(fmaxf(ab, 1e-6f));
    float sgn = (g > 0.f) ? 1.f : ((g < 0.f) ? -1.f : 0.f);
    float gs = rt * sgn;
    float sig = 1.f / (1.f + expf(-gs));
    float4 vv = ((const float4*)(vale + (size_t)row * DD))[tid];
    float4 r = make_float4(sig*vv.x, sig*vv.y, sig*vv.z, sig*vv.w);
    ((float4*)(value + (size_t)row * DD))[tid] = r;
}

// ---------------- final ----------------
__global__ void final_k(const float* __restrict__ value, const float* __restrict__ cw,
                        float* __restrict__ out) {
    int idx = blockIdx.x * 256 + threadIdx.x;
    int d = idx & (DD - 1);
    int bt = idx >> 10;
    int t = bt & (TT - 1);
    float c = 0.f;
    #pragma unroll
    for (int kk = 0; kk < 4; kk++) {
        int tt = t - 3 + kk;
        if (tt >= 0)
            c += value[(size_t)(bt - 3 + kk) * DD + d] * cw[d * 4 + kk];
    }
    float vv = value[idx];
    float sc = c / (1.f + expf(-c));
    out[idx] += vv + sc;
}

// ================= host =================
static float* symaddr(const void* sym) {
    void* p = nullptr;
    cudaGetSymbolAddress(&p, sym);
    return (float*)p;
}

extern "C" void kernel_launch(void* const* d_in, const int* in_sizes, int n_in,
                              void* d_out, int out_size) {
    const float* x     = (const float*)d_in[0];
    const int*   ids   = (const int*)d_in[1];
    const float* wq    = (const float*)d_in[3];
    const float* wk    = (const float*)d_in[4];
    const float* wv    = (const float*)d_in[5];
    const float* wo    = (const float*)d_in[6];
    const float* attnw = (const float*)d_in[7];
    const float* ffnw  = (const float*)d_in[8];
    const float* gatew = (const float*)d_in[9];
    const float* upw   = (const float*)d_in[10];
    const float* downw = (const float*)d_in[11];
    const float* embt  = (const float*)d_in[12];
    const float* keyw  = (const float*)d_in[13];
    const float* keyb  = (const float*)d_in[14];
    const float* valw  = (const float*)d_in[15];
    const float* valb  = (const float*)d_in[16];
    const float* normk = (const float*)d_in[17];
    const float* normq = (const float*)d_in[18];
    const float* convw = (const float*)d_in[19];
    const int*   hm    = (const int*)d_in[20];

    float* p_q    = symaddr(g_q);
    float* p_k    = symaddr(g_k);
    float* p_v    = symaddr(g_v);
    float* p_h    = symaddr(g_h);
    float* p_hn   = symaddr(g_hn);
    float* p_gate = symaddr(g_gate);
    float* p_up   = symaddr(g_up);
    float* p_keye = symaddr(g_keye);
    float* p_vale = symaddr(g_vale);
    float* p_val  = symaddr(g_value);
    bf16* p_ah = (bf16*)symaddr(g_ah);
    bf16* p_al = (bf16*)symaddr(g_al);
    bf16* p_bh = (bf16*)symaddr(g_bh);
    bf16* p_bl = (bf16*)symaddr(g_bl);

    float* out = (float*)d_out;

    static bool attrs_set = false;
    if (!attrs_set) {
        cudaFuncSetAttribute(gemm_mma, cudaFuncAttributeMaxDynamicSharedMemorySize, GEMM_SMEM);
        cudaFuncSetAttribute(flash_attn, cudaFuncAttributeMaxDynamicSharedMemorySize, 4 * 64 * FSTR * 4);
        attrs_set = true;
    }

    dim3 blk(256);
    dim3 gD(DD / 128, BT / 128);    // N=1024
    dim3 gF(FFN / 128, BT / 128);   // N=4096
    const int szDW = DD * DD / 4 / 256;        // weight split blocks (1024x1024)
    const int szFW = (FFN * DD / 4 + 255) / 256;

    // ---- attention ----
    rmsnorm_k<<<BT, blk>>>(x, attnw, nullptr, p_ah, p_al);
    split_k<<<szDW, blk>>>(wq, p_bh, p_bl, DD * DD / 4);
    gemm_mma<<<gD, blk, GEMM_SMEM>>>(p_ah, p_al, p_bh, p_bl, p_q, nullptr, nullptr, BT, DD, DD);
    split_k<<<szDW, blk>>>(wk, p_bh, p_bl, DD * DD / 4);
    gemm_mma<<<gD, blk, GEMM_SMEM>>>(p_ah, p_al, p_bh, p_bl, p_k, nullptr, nullptr, BT, DD, DD);
    split_k<<<szDW, blk>>>(wv, p_bh, p_bl, DD * DD / 4);
    gemm_mma<<<gD, blk, GEMM_SMEM>>>(p_ah, p_al, p_bh, p_bl, p_v, nullptr, nullptr, BT, DD, DD);

    rope_k<<<(BT * NHEAD * 32) / 256, blk>>>(p_q, p_k);
    flash_attn<<<dim3(TT / 64, BB * NHEAD), blk, 4 * 64 * FSTR * 4>>>(p_q, p_k, p_v, p_ah, p_al);

    split_k<<<szDW, blk>>>(wo, p_bh, p_bl, DD * DD / 4);
    gemm_mma<<<gD, blk, GEMM_SMEM>>>(p_ah, p_al, p_bh, p_bl, p_h, x, nullptr, BT, DD, DD);

    // ---- FFN ----
    rmsnorm_k<<<BT, blk>>>(p_h, ffnw, p_hn, p_ah, p_al);
    split_k<<<szFW, blk>>>(gatew, p_bh, p_bl, FFN * DD / 4);
    gemm_mma<<<gF, blk, GEMM_SMEM>>>(p_ah, p_al, p_bh, p_bl, p_gate, nullptr, nullptr, BT, FFN, DD);
    split_k<<<szFW, blk>>>(upw, p_bh, p_bl, FFN * DD / 4);
    gemm_mma<<<gF, blk, GEMM_SMEM>>>(p_ah, p_al, p_bh, p_bl, p_up, nullptr, nullptr, BT, FFN, DD);
    silumul_k<<<((size_t)BT * FFN) / 1024, blk>>>(p_gate, p_up, p_ah, p_al);
    split_k<<<szFW, blk>>>(downw, p_bh, p_bl, FFN * DD / 4);
    gemm_mma<<<gD, blk, GEMM_SMEM>>>(p_ah, p_al, p_bh, p_bl, out, p_h, nullptr, BT, DD, FFN);

    // ---- engram ----
    gather_k<<<BT, blk>>>(ids, embt, hm, p_ah, p_al);
    split_k<<<szDW, blk>>>(keyw, p_bh, p_bl, DD * DD / 4);
    gemm_mma<<<gD, blk, GEMM_SMEM>>>(p_ah, p_al, p_bh, p_bl, p_keye, nullptr, keyb, BT, DD, DD);
    split_k<<<szDW, blk>>>(valw, p_bh, p_bl, DD * DD / 4);
    gemm_mma<<<gD, blk, GEMM_SMEM>>>(p_ah, p_al, p_bh, p_bl, p_vale, nullptr, valb, BT, DD, DD);

    gate_k<<<BT, blk>>>(p_hn, p_keye, p_vale, normk, normq, p_val);
    final_k<<<(BT * DD) / 256, blk>>>(p_val, convw, out);
}

// round 4
// speedup vs baseline: 3.0744x; 1.5594x over previous
#include <cuda_runtime.h>
#include <cuda_bf16.h>
#include <cuda.h>
#include <math.h>
#include <stdint.h>

#define BB 2
#define TT 2048
#define DD 1024
#define NHEAD 16
#define HDIM 64
#define FFN 4096
#define BT (BB*TT)
#define NGV 50000

typedef __nv_bfloat16 bf16;

// ---------------- scratch (device globals; no allocation) ----------------
__device__ float g_q[BT*DD];
__device__ float g_k[BT*DD];
__device__ float g_v[BT*DD];
__device__ float g_h[BT*DD];
__device__ float g_hn[BT*DD];
__device__ float g_gate[(size_t)BT*FFN];
__device__ float g_up[(size_t)BT*FFN];
__device__ float g_keye[BT*DD];
__device__ float g_vale[BT*DD];
__device__ float g_value[BT*DD];
__device__ __align__(1024) bf16 g_ah[(size_t)BT*FFN];
__device__ __align__(1024) bf16 g_al[(size_t)BT*FFN];
__device__ __align__(1024) bf16 g_bh[(size_t)FFN*DD];
__device__ __align__(1024) bf16 g_bl[(size_t)FFN*DD];

extern __shared__ char dynsmem[];

// ================= low-level helpers =================
__device__ __forceinline__ uint32_t smem_u32(const void* p) {
    uint32_t a;
    asm("{ .reg .u64 t; cvta.to.shared.u64 t, %1; cvt.u32.u64 %0, t; }" : "=r"(a) : "l"(p));
    return a;
}
__device__ __forceinline__ uint32_t swz(uint32_t o) { return o ^ ((o >> 3) & 0x70); }

#define MBAR_INIT(addr, cnt) \
    asm volatile("mbarrier.init.shared.b64 [%0], %1;" :: "r"((uint32_t)(addr)), "r"((uint32_t)(cnt)) : "memory")
#define MBAR_EXPECT_TX(addr, bytes) \
    asm volatile("mbarrier.arrive.expect_tx.shared.b64 _, [%0], %1;" :: "r"((uint32_t)(addr)), "r"((uint32_t)(bytes)) : "memory")
#define MBAR_WAIT(addr, parity) do { \
    uint32_t _m = (uint32_t)(addr); uint32_t _p = (uint32_t)(parity); uint32_t _d; \
    asm volatile("{\n\t.reg .pred p;\n\t" \
        "mbarrier.try_wait.parity.acquire.cta.shared::cta.b64 p, [%1], %2;\n\t" \
        "selp.b32 %0, 1, 0, p;\n\t}" : "=r"(_d) : "r"(_m), "r"(_p) : "memory"); \
    if (!_d) { \
        asm volatile("{\n\t.reg .pred P1;\n\t" \
            "WL_%=:\n\t" \
            "mbarrier.try_wait.parity.acquire.cta.shared::cta.b64 P1, [%0], %1, 0x989680;\n\t" \
            "@P1 bra.uni WD_%=;\n\t" \
            "bra.uni WL_%=;\n\t" \
            "WD_%=:\n\t}" :: "r"(_m), "r"(_p) : "memory"); \
    } \
} while (0)

#define TMA_LOAD2D(smem_addr, map_ptr, cx, cy, mbar) \
    asm volatile("cp.async.bulk.tensor.2d.shared::cta.global.tile.mbarrier::complete_tx::bytes " \
        "[%0], [%1, {%2, %3}], [%4];" \
        :: "r"((uint32_t)(smem_addr)), "l"(map_ptr), "r"((int)(cx)), "r"((int)(cy)), \
           "r"((uint32_t)(mbar)) : "memory")

__device__ __forceinline__ void ldsm4(uint32_t* r, uint32_t addr) {
    asm volatile("ldmatrix.sync.aligned.m8n8.x4.shared.b16 {%0,%1,%2,%3}, [%4];"
        : "=r"(r[0]), "=r"(r[1]), "=r"(r[2]), "=r"(r[3]) : "r"(addr));
}
__device__ __forceinline__ void mma16816(float* d, const uint32_t* a, const uint32_t* b) {
    asm volatile("mma.sync.aligned.m16n8k16.row.col.f32.bf16.bf16.f32 "
        "{%0,%1,%2,%3}, {%4,%5,%6,%7}, {%8,%9}, {%0,%1,%2,%3};"
        : "+f"(d[0]), "+f"(d[1]), "+f"(d[2]), "+f"(d[3])
        : "r"(a[0]), "r"(a[1]), "r"(a[2]), "r"(a[3]), "r"(b[0]), "r"(b[1]));
}
__device__ __forceinline__ void split1(float v, bf16& h, bf16& l) {
    h = __float2bfloat16(v);
    l = __float2bfloat16(v - __bfloat162float(h));
}
__device__ __forceinline__ void pack_split(float x, float y, uint32_t& hi, uint32_t& lo) {
    bf16 hx, lx, hy, ly;
    split1(x, hx, lx); split1(y, hy, ly);
    __nv_bfloat162 h2(hx, hy), l2(lx, ly);
    hi = *(uint32_t*)&h2; lo = *(uint32_t*)&l2;
}

// ================= TMA + mma.sync split-bf16 GEMM =================
// C[M,N] = A[M,K]*B[N,K]^T (+bias) (+addC). CTA 128x128, BK=64, 3 TMA stages.
// Tiles per stage: Ah, Al, Bh, Bl, each 128x64 bf16 = 16KB (SW128).
#define NSTG 3
#define TIL 16384
#define STG_B (4*TIL)
#define GEMM_SMEM (1024 + NSTG*STG_B)

__global__ void __launch_bounds__(256, 1) gemm_tma(
    const __grid_constant__ CUtensorMap mah,
    const __grid_constant__ CUtensorMap mal,
    const __grid_constant__ CUtensorMap mbh,
    const __grid_constant__ CUtensorMap mbl,
    float* __restrict__ C, const float* __restrict__ addC,
    const float* __restrict__ bias, int M, int N, int K)
{
    const uint32_t sb = smem_u32(dynsmem);
    const uint32_t fullb = sb;           // 3 barriers, 8B each
    const uint32_t stg0 = sb + 1024;
    const int tid = threadIdx.x;
    const int wid = tid >> 5, lane = tid & 31;
    const int wm = wid & 3, wn = wid >> 2;
    const int m0 = blockIdx.y * 128, n0 = blockIdx.x * 128;
    const int NT = K >> 6;

    if (tid == 0) {
        #pragma unroll
        for (int s = 0; s < NSTG; s++) MBAR_INIT(fullb + 8*s, 1);
    }
    __syncthreads();
    if (tid == 0) {
        #pragma unroll
        for (int s = 0; s < 2; s++) {
            uint32_t st = stg0 + s * STG_B;
            MBAR_EXPECT_TX(fullb + 8*s, STG_B);
            TMA_LOAD2D(st,         &mah, s*64, m0, fullb + 8*s);
            TMA_LOAD2D(st + TIL,   &mal, s*64, m0, fullb + 8*s);
            TMA_LOAD2D(st + 2*TIL, &mbh, s*64, n0, fullb + 8*s);
            TMA_LOAD2D(st + 3*TIL, &mbl, s*64, n0, fullb + 8*s);
        }
    }

    float acc[2][8][4];
    #pragma unroll
    for (int i = 0; i < 2; i++)
        #pragma unroll
        for (int j = 0; j < 8; j++)
            #pragma unroll
            for (int q = 0; q < 4; q++) acc[i][j][q] = 0.f;

    // ldmatrix lane geometry (same logical mapping as R3, + SW128 swizzle)
    const int a_rb0 = (wm * 32 + (lane & 15)) * 128;
    const int a_rb1 = (wm * 32 + 16 + (lane & 15)) * 128;
    const int a_cb = ((lane >> 4) << 3);
    const int b_rr = ((lane & 16) >> 1) + (lane & 7);
    const int b_cb = (lane & 8);

    for (int kt = 0; kt < NT; kt++) {
        int s = kt % NSTG;
        MBAR_WAIT(fullb + 8*s, (kt / NSTG) & 1);
        uint32_t st = stg0 + s * STG_B;
        #pragma unroll
        for (int k16 = 0; k16 < 4; k16++) {
            const int kof = k16 * 16;
            uint32_t ah[2][4], al[2][4];
            {
                uint32_t o0 = swz(a_rb0 + (kof + a_cb) * 2);
                uint32_t o1 = swz(a_rb1 + (kof + a_cb) * 2);
                ldsm4(ah[0], st + o0);        ldsm4(ah[1], st + o1);
                ldsm4(al[0], st + TIL + o0);  ldsm4(al[1], st + TIL + o1);
            }
            uint32_t bh[4][4], bl[4][4];
            #pragma unroll
            for (int p = 0; p < 4; p++) {
                uint32_t off = swz((uint32_t)((wn * 64 + p * 16 + b_rr) * 128 + (kof + b_cb) * 2));
                ldsm4(bh[p], st + 2*TIL + off);
                ldsm4(bl[p], st + 3*TIL + off);
            }
            // products-outer to keep acc chains independent
            #pragma unroll
            for (int mt = 0; mt < 2; mt++)
                #pragma unroll
                for (int nt = 0; nt < 8; nt++)
                    mma16816(acc[mt][nt], ah[mt], &bh[nt >> 1][(nt & 1) * 2]);
            #pragma unroll
            for (int mt = 0; mt < 2; mt++)
                #pragma unroll
                for (int nt = 0; nt < 8; nt++)
                    mma16816(acc[mt][nt], ah[mt], &bl[nt >> 1][(nt & 1) * 2]);
            #pragma unroll
            for (int mt = 0; mt < 2; mt++)
                #pragma unroll
                for (int nt = 0; nt < 8; nt++)
                    mma16816(acc[mt][nt], al[mt], &bh[nt >> 1][(nt & 1) * 2]);
        }
        __syncthreads();
        if (tid == 0 && kt + 2 < NT) {
            int s2 = (kt + 2) % NSTG;
            uint32_t st2 = stg0 + s2 * STG_B;
            MBAR_EXPECT_TX(fullb + 8*s2, STG_B);
            TMA_LOAD2D(st2,         &mah, (kt+2)*64, m0, fullb + 8*s2);
            TMA_LOAD2D(st2 + TIL,   &mal, (kt+2)*64, m0, fullb + 8*s2);
            TMA_LOAD2D(st2 + 2*TIL, &mbh, (kt+2)*64, n0, fullb + 8*s2);
            TMA_LOAD2D(st2 + 3*TIL, &mbl, (kt+2)*64, n0, fullb + 8*s2);
        }
    }

    // epilogue
    const int g = lane >> 2, t2 = (lane & 3) * 2;
    #pragma unroll
    for (int mt = 0; mt < 2; mt++) {
        #pragma unroll
        for (int nt = 0; nt < 8; nt++) {
            int grow = m0 + wm * 32 + mt * 16 + g;
            int gcol = n0 + wn * 64 + nt * 8 + t2;
            float2 v0 = make_float2(acc[mt][nt][0], acc[mt][nt][1]);
            float2 v1 = make_float2(acc[mt][nt][2], acc[mt][nt][3]);
            if (bias) {
                float2 bv = *(const float2*)(bias + gcol);
                v0.x += bv.x; v0.y += bv.y; v1.x += bv.x; v1.y += bv.y;
            }
            if (addC) {
                float2 d0 = *(const float2*)(addC + (size_t)grow * N + gcol);
                float2 d1 = *(const float2*)(addC + (size_t)(grow + 8) * N + gcol);
                v0.x += d0.x; v0.y += d0.y; v1.x += d1.x; v1.y += d1.y;
            }
            *(float2*)(C + (size_t)grow * N + gcol) = v0;
            *(float2*)(C + (size_t)(grow + 8) * N + gcol) = v1;
        }
    }
}

// ---------------- fp32 -> bf16 hi/lo split (weights) ----------------
__global__ void split_k(const float* __restrict__ x, bf16* __restrict__ hi,
                        bf16* __restrict__ lo, int n4) {
    int i = blockIdx.x * 256 + threadIdx.x;
    if (i >= n4) return;
    float4 v = ((const float4*)x)[i];
    uint32_t h0, l0, h1, l1;
    pack_split(v.x, v.y, h0, l0);
    pack_split(v.z, v.w, h1, l1);
    ((uint32_t*)hi)[2*i] = h0; ((uint32_t*)hi)[2*i+1] = h1;
    ((uint32_t*)lo)[2*i] = l0; ((uint32_t*)lo)[2*i+1] = l1;
}

// ---------------- RMSNorm (fp32 out optional + bf16 hi/lo) ----------------
__global__ void rmsnorm_k(const float* __restrict__ x, const float* __restrict__ w,
                          float* __restrict__ y, bf16* __restrict__ hi,
                          bf16* __restrict__ lo) {
    int row = blockIdx.x, tid = threadIdx.x;
    float4 xv = ((const float4*)(x + (size_t)row * DD))[tid];
    float ss = xv.x*xv.x + xv.y*xv.y + xv.z*xv.z + xv.w*xv.w;
    #pragma unroll
    for (int o = 16; o; o >>= 1) ss += __shfl_xor_sync(0xffffffffu, ss, o);
    __shared__ float red[8];
    if ((tid & 31) == 0) red[tid >> 5] = ss;
    __syncthreads();
    float tot = 0.f;
    #pragma unroll
    for (int i = 0; i < 8; i++) tot += red[i];
    float inv = rsqrtf(tot * (1.0f / DD) + 1e-6f);
    float4 wv = ((const float4*)w)[tid];
    float4 r;
    r.x = xv.x * inv * wv.x; r.y = xv.y * inv * wv.y;
    r.z = xv.z * inv * wv.z; r.w = xv.w * inv * wv.w;
    if (y) ((float4*)(y + (size_t)row * DD))[tid] = r;
    uint32_t h0, l0, h1, l1;
    pack_split(r.x, r.y, h0, l0);
    pack_split(r.z, r.w, h1, l1);
    size_t base = (size_t)row * DD;
    ((uint32_t*)(hi + base))[2*tid] = h0; ((uint32_t*)(hi + base))[2*tid+1] = h1;
    ((uint32_t*)(lo + base))[2*tid] = l0; ((uint32_t*)(lo + base))[2*tid+1] = l1;
}

// ---------------- RoPE ----------------
__global__ void rope_k(float* __restrict__ q, float* __restrict__ k) {
    int idx = blockIdx.x * 256 + threadIdx.x;
    int i = idx & 31;
    int bth = idx >> 5;
    int h = bth & 15;
    int bt = bth >> 4;
    int t = bt & (TT - 1);
    float invf = expf(-(float)(2 * i) * (1.0f / 64.0f) * 9.2103403719761836f);
    float ang = (float)t * invf;
    float s, c;
    sincosf(ang, &s, &c);
    size_t base = (size_t)bt * DD + h * 64 + i;
    float a = q[base], b = q[base + 32];
    q[base]      = a * c - b * s;
    q[base + 32] = b * c + a * s;
    float ak = k[base], bk = k[base + 32];
    k[base]      = ak * c - bk * s;
    k[base + 32] = bk * c + ak * s;
}

// ---------------- Flash attention via mma.sync (split-bf16, causal) ------
// 128 threads (4 warps); warp w owns q-rows w*16..w*16+15 of a 64-row tile.
#define FP 72
#define FTE (64*FP)
#define FLASH_SMEM (6*FTE*2)

__global__ void __launch_bounds__(128) flash_mma(
    const float* __restrict__ q, const float* __restrict__ k,
    const float* __restrict__ v, bf16* __restrict__ ohi, bf16* __restrict__ olo)
{
    bf16* Qh = (bf16*)dynsmem;
    bf16* Ql = Qh + FTE;
    bf16* Kh = Ql + FTE;
    bf16* Kl = Kh + FTE;
    bf16* Vh = Kl + FTE;   // transposed: [d][token]
    bf16* Vl = Vh + FTE;
    const uint32_t uQh = smem_u32(Qh), uQl = smem_u32(Ql);
    const uint32_t uKh = smem_u32(Kh), uKl = smem_u32(Kl);
    const uint32_t uVh = smem_u32(Vh), uVl = smem_u32(Vl);

    const int qt = blockIdx.x, bh = blockIdx.y;
    const int b = bh >> 4, h = bh & 15;
    const int q0 = qt * 64;
    const int tid = threadIdx.x;
    const int wid = tid >> 5, lane = tid & 31;
    const int g = lane >> 2, t2 = (lane & 3) * 2;
    const float* qbase = q + (size_t)b * TT * DD + h * HDIM;
    const float* kbase = k + (size_t)b * TT * DD + h * HDIM;
    const float* vbase = v + (size_t)b * TT * DD + h * HDIM;

    // load Q tile -> Qh/Ql [m][d]
    for (int i = tid; i < 1024; i += 128) {
        int m = i >> 4, d4 = (i & 15) << 2;
        float4 qv = *(const float4*)(qbase + (size_t)(q0 + m) * DD + d4);
        uint32_t h0, l0, h1, l1;
        pack_split(qv.x, qv.y, h0, l0);
        pack_split(qv.z, qv.w, h1, l1);
        int e = m * FP + d4;
        *(uint32_t*)(Qh + e) = h0; *(uint32_t*)(Qh + e + 2) = h1;
        *(uint32_t*)(Ql + e) = l0; *(uint32_t*)(Ql + e + 2) = l1;
    }

    float m0r = -1e30f, m1r = -1e30f, l0r = 0.f, l1r = 0.f;
    float oacc[8][4];
    #pragma unroll
    for (int i = 0; i < 8; i++)
        #pragma unroll
        for (int j = 0; j < 4; j++) oacc[i][j] = 0.f;

    // ldmatrix geometry
    const int a_rb = (wid * 16 + (lane & 15)) * FP;
    const int a_cb = ((lane >> 4) << 3);
    const int b_rr = ((lane & 16) >> 1) + (lane & 7);
    const int b_cb = (lane & 8);

    for (int kt = 0; kt <= qt; kt++) {
        __syncthreads();
        for (int i = tid; i < 1024; i += 128) {
            int n = i >> 4, d4 = (i & 15) << 2;
            float4 kv = *(const float4*)(kbase + (size_t)(kt*64 + n) * DD + d4);
            uint32_t h0, l0, h1, l1;
            pack_split(kv.x, kv.y, h0, l0);
            pack_split(kv.z, kv.w, h1, l1);
            int e = n * FP + d4;
            *(uint32_t*)(Kh + e) = h0; *(uint32_t*)(Kh + e + 2) = h1;
            *(uint32_t*)(Kl + e) = l0; *(uint32_t*)(Kl + e + 2) = l1;
            float4 vv = *(const float4*)(vbase + (size_t)(kt*64 + n) * DD + d4);
            bf16 vh0, vl0;
            split1(vv.x, vh0, vl0); Vh[(d4+0)*FP + n] = vh0; Vl[(d4+0)*FP + n] = vl0;
            split1(vv.y, vh0, vl0); Vh[(d4+1)*FP + n] = vh0; Vl[(d4+1)*FP + n] = vl0;
            split1(vv.z, vh0, vl0); Vh[(d4+2)*FP + n] = vh0; Vl[(d4+2)*FP + n] = vl0;
            split1(vv.w, vh0, vl0); Vh[(d4+3)*FP + n] = vh0; Vl[(d4+3)*FP + n] = vl0;
        }
        __syncthreads();

        // S = Q K^T (3 bf16 products)
        float sacc[8][4];
        #pragma unroll
        for (int i = 0; i < 8; i++)
            #pragma unroll
            for (int j = 0; j < 4; j++) sacc[i][j] = 0.f;
        #pragma unroll
        for (int k16 = 0; k16 < 4; k16++) {
            const int kof = k16 * 16;
            uint32_t ahf[4], alf[4];
            uint32_t oq = (uint32_t)(a_rb + kof + a_cb) * 2;
            ldsm4(ahf, uQh + oq);
            ldsm4(alf, uQl + oq);
            uint32_t bhf[4][4], blf[4][4];
            #pragma unroll
            for (int p = 0; p < 4; p++) {
                uint32_t ob = (uint32_t)((p * 16 + b_rr) * FP + kof + b_cb) * 2;
                ldsm4(bhf[p], uKh + ob);
                ldsm4(blf[p], uKl + ob);
            }
            #pragma unroll
            for (int nt = 0; nt < 8; nt++)
                mma16816(sacc[nt], ahf, &bhf[nt >> 1][(nt & 1) * 2]);
            #pragma unroll
            for (int nt = 0; nt < 8; nt++)
                mma16816(sacc[nt], ahf, &blf[nt >> 1][(nt & 1) * 2]);
            #pragma unroll
            for (int nt = 0; nt < 8; nt++)
                mma16816(sacc[nt], alf, &bhf[nt >> 1][(nt & 1) * 2]);
        }

        // scale + mask
        const int qrow0 = q0 + wid * 16 + g;
        const int qrow1 = qrow0 + 8;
        #pragma unroll
        for (int nt = 0; nt < 8; nt++) {
            int c0 = kt * 64 + nt * 8 + t2;
            float v0 = sacc[nt][0] * 0.125f;
            float v1 = sacc[nt][1] * 0.125f;
            float v2 = sacc[nt][2] * 0.125f;
            float v3 = sacc[nt][3] * 0.125f;
            if (c0 > qrow0) v0 = -1e30f;
            if (c0 + 1 > qrow0) v1 = -1e30f;
            if (c0 > qrow1) v2 = -1e30f;
            if (c0 + 1 > qrow1) v3 = -1e30f;
            sacc[nt][0] = v0; sacc[nt][1] = v1; sacc[nt][2] = v2; sacc[nt][3] = v3;
        }
        // online softmax (rows g, g+8; reduce over 4 lanes sharing a row)
        float rm0 = -1e30f, rm1 = -1e30f;
        #pragma unroll
        for (int nt = 0; nt < 8; nt++) {
            rm0 = fmaxf(rm0, fmaxf(sacc[nt][0], sacc[nt][1]));
            rm1 = fmaxf(rm1, fmaxf(sacc[nt][2], sacc[nt][3]));
        }
        rm0 = fmaxf(rm0, __shfl_xor_sync(0xffffffffu, rm0, 1));
        rm0 = fmaxf(rm0, __shfl_xor_sync(0xffffffffu, rm0, 2));
        rm1 = fmaxf(rm1, __shfl_xor_sync(0xffffffffu, rm1, 1));
        rm1 = fmaxf(rm1, __shfl_xor_sync(0xffffffffu, rm1, 2));
        float mn0 = fmaxf(m0r, rm0), mn1 = fmaxf(m1r, rm1);
        float cor0 = __expf(m0r - mn0), cor1 = __expf(m1r - mn1);
        float sum0 = 0.f, sum1 = 0.f;
        #pragma unroll
        for (int nt = 0; nt < 8; nt++) {
            sacc[nt][0] = __expf(sacc[nt][0] - mn0);
            sacc[nt][1] = __expf(sacc[nt][1] - mn0);
            sacc[nt][2] = __expf(sacc[nt][2] - mn1);
            sacc[nt][3] = __expf(sacc[nt][3] - mn1);
            sum0 += sacc[nt][0] + sacc[nt][1];
            sum1 += sacc[nt][2] + sacc[nt][3];
        }
        sum0 += __shfl_xor_sync(0xffffffffu, sum0, 1);
        sum0 += __shfl_xor_sync(0xffffffffu, sum0, 2);
        sum1 += __shfl_xor_sync(0xffffffffu, sum1, 1);
        sum1 += __shfl_xor_sync(0xffffffffu, sum1, 2);
        l0r = l0r * cor0 + sum0; m0r = mn0;
        l1r = l1r * cor1 + sum1; m1r = mn1;
        #pragma unroll
        for (int dt = 0; dt < 8; dt++) {
            oacc[dt][0] *= cor0; oacc[dt][1] *= cor0;
            oacc[dt][2] *= cor1; oacc[dt][3] *= cor1;
        }

        // O += P V  (P in regs from sacc; V^T in smem; 3 bf16 products)
        #pragma unroll
        for (int j = 0; j < 4; j++) {      // token k16 step
            uint32_t ph[4], pl[4];
            pack_split(sacc[2*j][0],   sacc[2*j][1],   ph[0], pl[0]);
            pack_split(sacc[2*j][2],   sacc[2*j][3],   ph[1], pl[1]);
            pack_split(sacc[2*j+1][0], sacc[2*j+1][1], ph[2], pl[2]);
            pack_split(sacc[2*j+1][2], sacc[2*j+1][3], ph[3], pl[3]);
            #pragma unroll
            for (int dp = 0; dp < 4; dp++) {
                uint32_t ov = (uint32_t)((dp * 16 + b_rr) * FP + 16*j + b_cb) * 2;
                uint32_t vbh[4], vbl[4];
                ldsm4(vbh, uVh + ov);
                ldsm4(vbl, uVl + ov);
                mma16816(oacc[2*dp],   ph, &vbh[0]);
                mma16816(oacc[2*dp+1], ph, &vbh[2]);
                mma16816(oacc[2*dp],   ph, &vbl[0]);
                mma16816(oacc[2*dp+1], ph, &vbl[2]);
                mma16816(oacc[2*dp],   pl, &vbh[0]);
                mma16816(oacc[2*dp+1], pl, &vbh[2]);
            }
        }
    }

    // normalize + store split output
    float inv0 = 1.0f / l0r, inv1 = 1.0f / l1r;
    size_t ob0 = (size_t)b * TT * DD + (size_t)(q0 + wid * 16 + g) * DD + h * HDIM;
    size_t ob1 = ob0 + 8 * DD;
    #pragma unroll
    for (int dt = 0; dt < 8; dt++) {
        uint32_t hh, ll;
        pack_split(oacc[dt][0] * inv0, oacc[dt][1] * inv0, hh, ll);
        *(uint32_t*)(ohi + ob0 + dt*8 + t2) = hh;
        *(uint32_t*)(olo + ob0 + dt*8 + t2) = ll;
        pack_split(oacc[dt][2] * inv1, oacc[dt][3] * inv1, hh, ll);
        *(uint32_t*)(ohi + ob1 + dt*8 + t2) = hh;
        *(uint32_t*)(olo + ob1 + dt*8 + t2) = ll;
    }
}

// ---------------- silu(g)*u -> bf16 hi/lo ----------------
__global__ void silumul_k(const float* __restrict__ g, const float* __restrict__ u,
                          bf16* __restrict__ hi, bf16* __restrict__ lo) {
    size_t i = (size_t)blockIdx.x * 256 + threadIdx.x;
    float4 gv = ((const float4*)g)[i];
    float4 uv = ((const float4*)u)[i];
    float4 r;
    r.x = gv.x / (1.f + expf(-gv.x)) * uv.x;
    r.y = gv.y / (1.f + expf(-gv.y)) * uv.y;
    r.z = gv.z / (1.f + expf(-gv.z)) * uv.z;
    r.w = gv.w / (1.f + expf(-gv.w)) * uv.w;
    uint32_t h0, l0, h1, l1;
    pack_split(r.x, r.y, h0, l0);
    pack_split(r.z, r.w, h1, l1);
    ((uint32_t*)hi)[2*i] = h0; ((uint32_t*)hi)[2*i+1] = h1;
    ((uint32_t*)lo)[2*i] = l0; ((uint32_t*)lo)[2*i+1] = l1;
}

// ---------------- engram hash + gather -> bf16 hi/lo ----------------
__global__ void gather_k(const int* __restrict__ ids, const float* __restrict__ tables,
                         const int* __restrict__ hm, bf16* __restrict__ hi,
                         bf16* __restrict__ lo) {
    int tok = blockIdx.x;
    int t = tok & (TT - 1);
    int id0 = ids[tok];
    int id1 = (t >= 1) ? ids[tok - 1] : 0;
    int id2 = (t >= 2) ? ids[tok - 2] : 0;
    unsigned m0 = (unsigned)hm[0], m1 = (unsigned)hm[1], m2 = (unsigned)hm[2];
    unsigned h2 = (unsigned)id0 * m0 ^ (unsigned)id1 * m1;
    unsigned h3 = h2 ^ (unsigned)id2 * m2;
    int tid = threadIdx.x;
    size_t ob = (size_t)tok * 1024;
    #pragma unroll
    for (int r = 0; r < 4; r++) {
        int e = tid + r * 256;
        int tt = e >> 6, ee = e & 63;
        int head = tt & 7;
        unsigned hh = ((tt < 8) ? h2 : h3) + (unsigned)(head * 7919);
        int sv = (int)hh;
        int idx = sv % NGV;
        if (idx < 0) idx += NGV;
        float f = tables[((size_t)tt * NGV + idx) * 64 + ee];
        bf16 hb, lb;
        split1(f, hb, lb);
        hi[ob + e] = hb;
        lo[ob + e] = lb;
    }
}

// ---------------- gate ----------------
__global__ void gate_k(const float* __restrict__ hn, const float* __restrict__ keye,
                       const float* __restrict__ vale, const float* __restrict__ nkw,
                       const float* __restrict__ nqw, float* __restrict__ value) {
    int row = blockIdx.x, tid = threadIdx.x;
    float4 kv = ((const float4*)(keye + (size_t)row * DD))[tid];
    float4 hv = ((const float4*)(hn + (size_t)row * DD))[tid];
    float4 wk = ((const float4*)nkw)[tid];
    float4 wq = ((const float4*)nqw)[tid];
    float skk = kv.x*kv.x + kv.y*kv.y + kv.z*kv.z + kv.w*kv.w;
    float shh = hv.x*hv.x + hv.y*hv.y + hv.z*hv.z + hv.w*hv.w;
    float sdt = kv.x*wk.x*hv.x*wq.x + kv.y*wk.y*hv.y*wq.y
              + kv.z*wk.z*hv.z*wq.z + kv.w*wk.w*hv.w*wq.w;
    #pragma unroll
    for (int o = 16; o; o >>= 1) {
        skk += __shfl_xor_sync(0xffffffffu, skk, o);
        shh += __shfl_xor_sync(0xffffffffu, shh, o);
        sdt += __shfl_xor_sync(0xffffffffu, sdt, o);
    }
    __shared__ float r1[8], r2[8], r3[8];
    if ((tid & 31) == 0) { r1[tid>>5] = skk; r2[tid>>5] = shh; r3[tid>>5] = sdt; }
    __syncthreads();
    float tkk = 0, thh = 0, tdt = 0;
    #pragma unroll
    for (int i = 0; i < 8; i++) { tkk += r1[i]; thh += r2[i]; tdt += r3[i]; }
    float nk = rsqrtf(tkk * (1.0f / DD) + 1e-6f);
    float nh = rsqrtf(thh * (1.0f / DD) + 1e-6f);
    float gg = tdt * nk * nh * (1.0f / 32.0f);
    float ab = fabsf(gg);
    float rt = sqrtf(fmaxf(ab, 1e-6f));
    float sgn = (gg > 0.f) ? 1.f : ((gg < 0.f) ? -1.f : 0.f);
    float gs = rt * sgn;
    float sig = 1.f / (1.f + expf(-gs));
    float4 vv = ((const float4*)(vale + (size_t)row * DD))[tid];
    float4 r = make_float4(sig*vv.x, sig*vv.y, sig*vv.z, sig*vv.w);
    ((float4*)(value + (size_t)row * DD))[tid] = r;
}

// ---------------- final ----------------
__global__ void final_k(const float* __restrict__ value, const float* __restrict__ cw,
                        float* __restrict__ out) {
    int idx = blockIdx.x * 256 + threadIdx.x;
    int d = idx & (DD - 1);
    int bt = idx >> 10;
    int t = bt & (TT - 1);
    float c = 0.f;
    #pragma unroll
    for (int kk = 0; kk < 4; kk++) {
        int tt = t - 3 + kk;
        if (tt >= 0)
            c += value[(size_t)(bt - 3 + kk) * DD + d] * cw[d * 4 + kk];
    }
    float vv = value[idx];
    float sc = c / (1.f + expf(-c));
    out[idx] += vv + sc;
}

// ================= host =================
typedef CUresult (*PFN_encode)(CUtensorMap*, CUtensorMapDataType, cuuint32_t, void*,
                               const cuuint64_t*, const cuuint64_t*, const cuuint32_t*,
                               const cuuint32_t*, CUtensorMapInterleave, CUtensorMapSwizzle,
                               CUtensorMapL2promotion, CUtensorMapFloatOOBfill);
static PFN_encode get_encoder() {
    static PFN_encode fn = nullptr;
    if (!fn) {
        void* p = nullptr;
        cudaDriverEntryPointQueryResult qr;
        cudaGetDriverEntryPoint("cuTensorMapEncodeTiled", &p, cudaEnableDefault, &qr);
        fn = (PFN_encode)p;
    }
    return fn;
}
static void make_map(CUtensorMap* m, void* ptr, uint64_t Kdim, uint64_t Rows) {
    cuuint64_t dims[2] = {Kdim, Rows};
    cuuint64_t strides[1] = {Kdim * 2};
    cuuint32_t box[2] = {64, 128};
    cuuint32_t es[2] = {1, 1};
    get_encoder()(m, CU_TENSOR_MAP_DATA_TYPE_BFLOAT16, 2, ptr, dims, strides, box, es,
                  CU_TENSOR_MAP_INTERLEAVE_NONE, CU_TENSOR_MAP_SWIZZLE_128B,
                  CU_TENSOR_MAP_L2_PROMOTION_L2_128B, CU_TENSOR_MAP_FLOAT_OOB_FILL_NONE);
}
static float* symaddr(const void* sym) {
    void* p = nullptr;
    cudaGetSymbolAddress(&p, sym);
    return (float*)p;
}
static void run_gemm(bf16* ah, bf16* al, bf16* bh, bf16* bl,
                     float* C, const float* addC, const float* bias,
                     int M, int N, int K) {
    CUtensorMap mah, mal, mbh, mbl;
    make_map(&mah, ah, K, M);
    make_map(&mal, al, K, M);
    make_map(&mbh, bh, K, N);
    make_map(&mbl, bl, K, N);
    dim3 grid(N / 128, M / 128);
    gemm_tma<<<grid, 256, GEMM_SMEM>>>(mah, mal, mbh, mbl, C, addC, bias, M, N, K);
}

extern "C" void kernel_launch(void* const* d_in, const int* in_sizes, int n_in,
                              void* d_out, int out_size) {
    const float* x     = (const float*)d_in[0];
    const int*   ids   = (const int*)d_in[1];
    const float* wq    = (const float*)d_in[3];
    const float* wk    = (const float*)d_in[4];
    const float* wv    = (const float*)d_in[5];
    const float* wo    = (const float*)d_in[6];
    const float* attnw = (const float*)d_in[7];
    const float* ffnw  = (const float*)d_in[8];
    const float* gatew = (const float*)d_in[9];
    const float* upw   = (const float*)d_in[10];
    const float* downw = (const float*)d_in[11];
    const float* embt  = (const float*)d_in[12];
    const float* keyw  = (const float*)d_in[13];
    const float* keyb  = (const float*)d_in[14];
    const float* valw  = (const float*)d_in[15];
    const float* valb  = (const float*)d_in[16];
    const float* normk = (const float*)d_in[17];
    const float* normq = (const float*)d_in[18];
    const float* convw = (const float*)d_in[19];
    const int*   hm    = (const int*)d_in[20];

    float* p_q    = symaddr(g_q);
    float* p_k    = symaddr(g_k);
    float* p_v    = symaddr(g_v);
    float* p_h    = symaddr(g_h);
    float* p_hn   = symaddr(g_hn);
    float* p_gate = symaddr(g_gate);
    float* p_up   = symaddr(g_up);
    float* p_keye = symaddr(g_keye);
    float* p_vale = symaddr(g_vale);
    float* p_val  = symaddr(g_value);
    bf16* p_ah = (bf16*)symaddr(g_ah);
    bf16* p_al = (bf16*)symaddr(g_al);
    bf16* p_bh = (bf16*)symaddr(g_bh);
    bf16* p_bl = (bf16*)symaddr(g_bl);

    float* out = (float*)d_out;

    static bool attrs_set = false;
    if (!attrs_set) {
        cudaFuncSetAttribute(gemm_tma, cudaFuncAttributeMaxDynamicSharedMemorySize, GEMM_SMEM);
        cudaFuncSetAttribute(flash_mma, cudaFuncAttributeMaxDynamicSharedMemorySize, FLASH_SMEM);
        attrs_set = true;
    }

    dim3 blk(256);
    const int szDW = DD * DD / 4 / 256;
    const int szFW = (FFN * DD / 4 + 255) / 256;

    // ---- attention ----
    rmsnorm_k<<<BT, blk>>>(x, attnw, nullptr, p_ah, p_al);
    split_k<<<szDW, blk>>>(wq, p_bh, p_bl, DD * DD / 4);
    run_gemm(p_ah, p_al, p_bh, p_bl, p_q, nullptr, nullptr, BT, DD, DD);
    split_k<<<szDW, blk>>>(wk, p_bh, p_bl, DD * DD / 4);
    run_gemm(p_ah, p_al, p_bh, p_bl, p_k, nullptr, nullptr, BT, DD, DD);
    split_k<<<szDW, blk>>>(wv, p_bh, p_bl, DD * DD / 4);
    run_gemm(p_ah, p_al, p_bh, p_bl, p_v, nullptr, nullptr, BT, DD, DD);

    rope_k<<<(BT * NHEAD * 32) / 256, blk>>>(p_q, p_k);
    flash_mma<<<dim3(TT / 64, BB * NHEAD), 128, FLASH_SMEM>>>(p_q, p_k, p_v, p_ah, p_al);

    split_k<<<szDW, blk>>>(wo, p_bh, p_bl, DD * DD / 4);
    run_gemm(p_ah, p_al, p_bh, p_bl, p_h, x, nullptr, BT, DD, DD);

    // ---- FFN ----
    rmsnorm_k<<<BT, blk>>>(p_h, ffnw, p_hn, p_ah, p_al);
    split_k<<<szFW, blk>>>(gatew, p_bh, p_bl, FFN * DD / 4);
    run_gemm(p_ah, p_al, p_bh, p_bl, p_gate, nullptr, nullptr, BT, FFN, DD);
    split_k<<<szFW, blk>>>(upw, p_bh, p_bl, FFN * DD / 4);
    run_gemm(p_ah, p_al, p_bh, p_bl, p_up, nullptr, nullptr, BT, FFN, DD);
    silumul_k<<<((size_t)BT * FFN) / 1024, blk>>>(p_gate, p_up, p_ah, p_al);
    split_k<<<szFW, blk>>>(downw, p_bh, p_bl, FFN * DD / 4);
    run_gemm(p_ah, p_al, p_bh, p_bl, out, p_h, nullptr, BT, DD, FFN);

    // ---- engram ----
    gather_k<<<BT, blk>>>(ids, embt, hm, p_ah, p_al);
    split_k<<<szDW, blk>>>(keyw, p_bh, p_bl, DD * DD / 4);
    run_gemm(p_ah, p_al, p_bh, p_bl, p_keye, nullptr, keyb, BT, DD, DD);
    split_k<<<szDW, blk>>>(valw, p_bh, p_bl, DD * DD / 4);
    run_gemm(p_ah, p_al, p_bh, p_bl, p_vale, nullptr, valb, BT, DD, DD);

    gate_k<<<BT, blk>>>(p_hn, p_keye, p_vale, normk, normq, p_val);
    final_k<<<(BT * DD) / 256, blk>>>(p_val, convw, out);
}

// round 5
// speedup vs baseline: 3.2352x; 1.0523x over previous
#include <cuda_runtime.h>
#include <cuda_bf16.h>
#include <cuda.h>
#include <math.h>
#include <stdint.h>

#define BB 2
#define TT 2048
#define DD 1024
#define NHEAD 16
#define HDIM 64
#define FFN 4096
#define BT (BB*TT)
#define NGV 50000

typedef __nv_bfloat16 bf16;

// ---------------- scratch (device globals; no allocation) ----------------
__device__ float g_h[BT*DD];
__device__ float g_hn[BT*DD];
__device__ float g_value[BT*DD];
__device__ float g_kv[(size_t)BT*2048];
__device__ __align__(1024) bf16 g_ah[BT*DD];           // A operands: xn, O, hn
__device__ __align__(1024) bf16 g_al[BT*DD];
__device__ __align__(1024) bf16 g_sh[(size_t)BT*FFN];  // silu output
__device__ __align__(1024) bf16 g_sl[(size_t)BT*FFN];
__device__ __align__(1024) bf16 g_eh[BT*DD];           // engram emb
__device__ __align__(1024) bf16 g_el[BT*DD];
__device__ __align__(1024) bf16 g_qh[(size_t)BT*3072]; // rope'd qkv
__device__ __align__(1024) bf16 g_ql[(size_t)BT*3072];
// all weights, split: [qkv 3M][wo 1M][gate/up interleaved 8M][down 4M][key 1M][val 1M]
#define WOFF_QKV 0
#define WOFF_WO   (3u*1024*1024)
#define WOFF_GU   (4u*1024*1024)
#define WOFF_DOWN (12u*1024*1024)
#define WOFF_KV   (16u*1024*1024)
__device__ __align__(1024) bf16 g_bh[18u*1024*1024];
__device__ __align__(1024) bf16 g_bl[18u*1024*1024];

extern __shared__ char dynsmem[];

// ================= low-level helpers =================
__device__ __forceinline__ uint32_t smem_u32(const void* p) {
    uint32_t a;
    asm("{ .reg .u64 t; cvta.to.shared.u64 t, %1; cvt.u32.u64 %0, t; }" : "=r"(a) : "l"(p));
    return a;
}
__device__ __forceinline__ uint32_t swz64(uint32_t o) { return o ^ ((o >> 3) & 0x30); }

#define MBAR_INIT(addr, cnt) \
    asm volatile("mbarrier.init.shared.b64 [%0], %1;" :: "r"((uint32_t)(addr)), "r"((uint32_t)(cnt)) : "memory")
#define MBAR_EXPECT_TX(addr, bytes) \
    asm volatile("mbarrier.arrive.expect_tx.shared.b64 _, [%0], %1;" :: "r"((uint32_t)(addr)), "r"((uint32_t)(bytes)) : "memory")
#define MBAR_WAIT(addr, parity) do { \
    uint32_t _m = (uint32_t)(addr); uint32_t _p = (uint32_t)(parity); uint32_t _d; \
    asm volatile("{\n\t.reg .pred p;\n\t" \
        "mbarrier.try_wait.parity.acquire.cta.shared::cta.b64 p, [%1], %2;\n\t" \
        "selp.b32 %0, 1, 0, p;\n\t}" : "=r"(_d) : "r"(_m), "r"(_p) : "memory"); \
    if (!_d) { \
        asm volatile("{\n\t.reg .pred P1;\n\t" \
            "WL_%=:\n\t" \
            "mbarrier.try_wait.parity.acquire.cta.shared::cta.b64 P1, [%0], %1, 0x989680;\n\t" \
            "@P1 bra.uni WD_%=;\n\t" \
            "bra.uni WL_%=;\n\t" \
            "WD_%=:\n\t}" :: "r"(_m), "r"(_p) : "memory"); \
    } \
} while (0)

#define TMA_LOAD2D(smem_addr, map_ptr, cx, cy, mbar) \
    asm volatile("cp.async.bulk.tensor.2d.shared::cta.global.tile.mbarrier::complete_tx::bytes " \
        "[%0], [%1, {%2, %3}], [%4];" \
        :: "r"((uint32_t)(smem_addr)), "l"(map_ptr), "r"((int)(cx)), "r"((int)(cy)), \
           "r"((uint32_t)(mbar)) : "memory")

__device__ __forceinline__ void ldsm4(uint32_t* r, uint32_t addr) {
    asm volatile("ldmatrix.sync.aligned.m8n8.x4.shared.b16 {%0,%1,%2,%3}, [%4];"
        : "=r"(r[0]), "=r"(r[1]), "=r"(r[2]), "=r"(r[3]) : "r"(addr));
}
__device__ __forceinline__ void mma16816(float* d, const uint32_t* a, const uint32_t* b) {
    asm volatile("mma.sync.aligned.m16n8k16.row.col.f32.bf16.bf16.f32 "
        "{%0,%1,%2,%3}, {%4,%5,%6,%7}, {%8,%9}, {%0,%1,%2,%3};"
        : "+f"(d[0]), "+f"(d[1]), "+f"(d[2]), "+f"(d[3])
        : "r"(a[0]), "r"(a[1]), "r"(a[2]), "r"(a[3]), "r"(b[0]), "r"(b[1]));
}
__device__ __forceinline__ void split1(float v, bf16& h, bf16& l) {
    h = __float2bfloat16(v);
    l = __float2bfloat16(v - __bfloat162float(h));
}
__device__ __forceinline__ void pack_split(float x, float y, uint32_t& hi, uint32_t& lo) {
    bf16 hx, lx, hy, ly;
    split1(x, hx, lx); split1(y, hy, ly);
    __nv_bfloat162 h2(hx, hy), l2(lx, ly);
    hi = *(uint32_t*)&h2; lo = *(uint32_t*)&l2;
}

// ================= TMA + mma.sync split-bf16 GEMM, occupancy 2 ===========
// C[M,N] = A[M,K]*B[N,K]^T. CTA 128x128, BK=32, 3 stages (32KB each, SW64).
// MODE 0: fp32 C (+addC) (+dual bias split at N/2)
// MODE 1: QKV epilogue -> rope (cols<2048) -> split bf16, stride N
// MODE 2: gate/up interleaved -> silu(g)*u -> split bf16, stride N/2
#define NSTG 3
#define TIL 8192
#define STG_B (4*TIL)
#define GEMM_SMEM (1024 + NSTG*STG_B)

template<int MODE>
__global__ void __launch_bounds__(256, 2) gemm_tma(
    const __grid_constant__ CUtensorMap mah,
    const __grid_constant__ CUtensorMap mal,
    const __grid_constant__ CUtensorMap mbh,
    const __grid_constant__ CUtensorMap mbl,
    float* __restrict__ C, const float* __restrict__ addC,
    const float* __restrict__ bias, const float* __restrict__ bias2,
    bf16* __restrict__ outh, bf16* __restrict__ outl,
    int M, int N, int K)
{
    const uint32_t sb = smem_u32(dynsmem);
    const uint32_t fullb = sb;
    const uint32_t stg0 = sb + 1024;
    const int tid = threadIdx.x;
    const int wid = tid >> 5, lane = tid & 31;
    const int wm = wid & 3, wn = wid >> 2;
    const int m0 = blockIdx.y * 128, n0 = blockIdx.x * 128;
    const int NT = K >> 5;

    if (tid == 0) {
        #pragma unroll
        for (int s = 0; s < NSTG; s++) MBAR_INIT(fullb + 8*s, 1);
    }
    __syncthreads();
    if (tid == 0) {
        #pragma unroll
        for (int s = 0; s < 2; s++) {
            uint32_t st = stg0 + s * STG_B;
            MBAR_EXPECT_TX(fullb + 8*s, STG_B);
            TMA_LOAD2D(st,         &mah, s*32, m0, fullb + 8*s);
            TMA_LOAD2D(st + TIL,   &mal, s*32, m0, fullb + 8*s);
            TMA_LOAD2D(st + 2*TIL, &mbh, s*32, n0, fullb + 8*s);
            TMA_LOAD2D(st + 3*TIL, &mbl, s*32, n0, fullb + 8*s);
        }
    }

    float acc[2][8][4];
    #pragma unroll
    for (int i = 0; i < 2; i++)
        #pragma unroll
        for (int j = 0; j < 8; j++)
            #pragma unroll
            for (int q = 0; q < 4; q++) acc[i][j][q] = 0.f;

    const int a_row0 = wm * 32 + (lane & 15);
    const int acbyte = (lane >> 4) * 16;
    const int b_rr = ((lane & 16) >> 1) + (lane & 7);
    const int bcbyte = (lane & 8) * 2;

    for (int kt = 0; kt < NT; kt++) {
        int s = kt % NSTG;
        MBAR_WAIT(fullb + 8*s, (kt / NSTG) & 1);
        uint32_t st = stg0 + s * STG_B;
        #pragma unroll
        for (int k16 = 0; k16 < 2; k16++) {
            const int kofb = k16 * 32;
            uint32_t ah[2][4], al[2][4];
            uint32_t oa0 = swz64((uint32_t)(a_row0 * 64 + acbyte + kofb));
            uint32_t oa1 = swz64((uint32_t)((a_row0 + 16) * 64 + acbyte + kofb));
            ldsm4(ah[0], st + oa0);        ldsm4(ah[1], st + oa1);
            ldsm4(al[0], st + TIL + oa0);  ldsm4(al[1], st + TIL + oa1);
            #pragma unroll
            for (int p = 0; p < 4; p++) {
                uint32_t ob = swz64((uint32_t)((wn * 64 + p * 16 + b_rr) * 64 + bcbyte + kofb));
                uint32_t bh[4];
                ldsm4(bh, st + 2*TIL + ob);
                mma16816(acc[0][2*p],   ah[0], bh);
                mma16816(acc[0][2*p+1], ah[0], bh + 2);
                mma16816(acc[1][2*p],   ah[1], bh);
                mma16816(acc[1][2*p+1], ah[1], bh + 2);
                mma16816(acc[0][2*p],   al[0], bh);
                mma16816(acc[0][2*p+1], al[0], bh + 2);
                mma16816(acc[1][2*p],   al[1], bh);
                mma16816(acc[1][2*p+1], al[1], bh + 2);
            }
            #pragma unroll
            for (int p = 0; p < 4; p++) {
                uint32_t ob = swz64((uint32_t)((wn * 64 + p * 16 + b_rr) * 64 + bcbyte + kofb));
                uint32_t bl[4];
                ldsm4(bl, st + 3*TIL + ob);
                mma16816(acc[0][2*p],   ah[0], bl);
                mma16816(acc[0][2*p+1], ah[0], bl + 2);
                mma16816(acc[1][2*p],   ah[1], bl);
                mma16816(acc[1][2*p+1], ah[1], bl + 2);
            }
        }
        __syncthreads();
        if (tid == 0 && kt + 2 < NT) {
            int s2 = (kt + 2) % NSTG;
            uint32_t st2 = stg0 + s2 * STG_B;
            MBAR_EXPECT_TX(fullb + 8*s2, STG_B);
            TMA_LOAD2D(st2,         &mah, (kt+2)*32, m0, fullb + 8*s2);
            TMA_LOAD2D(st2 + TIL,   &mal, (kt+2)*32, m0, fullb + 8*s2);
            TMA_LOAD2D(st2 + 2*TIL, &mbh, (kt+2)*32, n0, fullb + 8*s2);
            TMA_LOAD2D(st2 + 3*TIL, &mbl, (kt+2)*32, n0, fullb + 8*s2);
        }
    }

    const int g = lane >> 2, t2 = (lane & 3) * 2;
    const int base_c = n0 + wn * 64;

    if (MODE == 0) {
        #pragma unroll
        for (int mt = 0; mt < 2; mt++)
            #pragma unroll
            for (int nt = 0; nt < 8; nt++) {
                int grow = m0 + wm * 32 + mt * 16 + g;
                int gcol = base_c + nt * 8 + t2;
                float2 v0 = make_float2(acc[mt][nt][0], acc[mt][nt][1]);
                float2 v1 = make_float2(acc[mt][nt][2], acc[mt][nt][3]);
                if (bias) {
                    const float* bp = (gcol < (N >> 1)) ? bias + gcol : bias2 + gcol - (N >> 1);
                    float2 bv = *(const float2*)bp;
                    v0.x += bv.x; v0.y += bv.y; v1.x += bv.x; v1.y += bv.y;
                }
                if (addC) {
                    float2 d0 = *(const float2*)(addC + (size_t)grow * N + gcol);
                    float2 d1 = *(const float2*)(addC + (size_t)(grow + 8) * N + gcol);
                    v0.x += d0.x; v0.y += d0.y; v1.x += d1.x; v1.y += d1.y;
                }
                *(float2*)(C + (size_t)grow * N + gcol) = v0;
                *(float2*)(C + (size_t)(grow + 8) * N + gcol) = v1;
            }
    } else if (MODE == 1) {
        #pragma unroll
        for (int mt = 0; mt < 2; mt++)
            #pragma unroll
            for (int rr = 0; rr < 2; rr++) {
                int row = m0 + wm * 32 + mt * 16 + g + rr * 8;
                float ft = (float)(row & (TT - 1));
                size_t rb = (size_t)row * N;
                if (base_c < 2048) {  // q or k: rope (whole 64-wide warp tile)
                    #pragma unroll
                    for (int nt = 0; nt < 4; nt++) {
                        int cc = base_c + nt * 8 + t2;
                        int d0 = cc & 63;
                        float inv0 = expf(-(float)(2*d0)     * (1.0f/64.0f) * 9.2103403719761836f);
                        float inv1 = expf(-(float)(2*(d0+1)) * (1.0f/64.0f) * 9.2103403719761836f);
                        float s0, c0, s1, c1;
                        sincosf(ft * inv0, &s0, &c0);
                        sincosf(ft * inv1, &s1, &c1);
                        float vl0 = acc[mt][nt][rr*2],   vl1 = acc[mt][nt][rr*2+1];
                        float vh0 = acc[mt][nt+4][rr*2], vh1 = acc[mt][nt+4][rr*2+1];
                        float ol0 = vl0 * c0 - vh0 * s0, oh0 = vh0 * c0 + vl0 * s0;
                        float ol1 = vl1 * c1 - vh1 * s1, oh1 = vh1 * c1 + vl1 * s1;
                        uint32_t ph, pl;
                        pack_split(ol0, ol1, ph, pl);
                        *(uint32_t*)(outh + rb + cc) = ph;
                        *(uint32_t*)(outl + rb + cc) = pl;
                        pack_split(oh0, oh1, ph, pl);
                        *(uint32_t*)(outh + rb + cc + 32) = ph;
                        *(uint32_t*)(outl + rb + cc + 32) = pl;
                    }
                } else {  // v: plain split
                    #pragma unroll
                    for (int nt = 0; nt < 8; nt++) {
                        int cc = base_c + nt * 8 + t2;
                        uint32_t ph, pl;
                        pack_split(acc[mt][nt][rr*2], acc[mt][nt][rr*2+1], ph, pl);
                        *(uint32_t*)(outh + rb + cc) = ph;
                        *(uint32_t*)(outl + rb + cc) = pl;
                    }
                }
            }
    } else {  // MODE 2: silu(gate)*up, interleaved cols
        const int NO = N >> 1;
        #pragma unroll
        for (int mt = 0; mt < 2; mt++)
            #pragma unroll
            for (int rr = 0; rr < 2; rr++) {
                int row = m0 + wm * 32 + mt * 16 + g + rr * 8;
                size_t rb = (size_t)row * NO;
                #pragma unroll
                for (int nt = 0; nt < 8; nt++) {
                    float gg = acc[mt][nt][rr*2];
                    float uu = acc[mt][nt][rr*2+1];
                    float sv = gg / (1.f + expf(-gg)) * uu;
                    bf16 hb, lb;
                    split1(sv, hb, lb);
                    int j = (base_c + nt * 8 + t2) >> 1;
                    outh[rb + j] = hb;
                    outl[rb + j] = lb;
                }
            }
    }
}

// ---------------- all-weights split (gate/up interleaved) ----------------
#define D2 262144u          /* DD*DD/4 */
#define F2 1048576u         /* FFN*DD/4 */
__global__ void split_weights(
    const float* __restrict__ wq, const float* __restrict__ wk,
    const float* __restrict__ wv, const float* __restrict__ wo,
    const float* __restrict__ gw, const float* __restrict__ uw,
    const float* __restrict__ dw, const float* __restrict__ kw,
    const float* __restrict__ vw, bf16* __restrict__ bh, bf16* __restrict__ bl)
{
    uint32_t i = blockIdx.x * 256 + threadIdx.x;
    const float* src;
    uint32_t oo;  // output float4 index
    if (i < 3*D2) {                       // qkv
        src = (i < D2) ? wq : (i < 2*D2) ? wk : wv;
        uint32_t loc = i - (i < D2 ? 0 : (i < 2*D2 ? D2 : 2*D2));
        (void)loc;
        src = (i < D2) ? wq + 4*(size_t)i : (i < 2*D2) ? wk + 4*(size_t)(i - D2) : wv + 4*(size_t)(i - 2*D2);
        oo = i;
    } else if (i < 4*D2) {                // wo
        src = wo + 4*(size_t)(i - 3*D2);
        oo = i;
    } else if (i < 4*D2 + F2) {           // gate -> even rows
        uint32_t loc = i - 4*D2;
        uint32_t r = loc >> 8, c = loc & 255;
        src = gw + 4*(size_t)loc;
        oo = 4*D2 + (2*r) * 256 + c;
    } else if (i < 4*D2 + 2*F2) {         // up -> odd rows
        uint32_t loc = i - 4*D2 - F2;
        uint32_t r = loc >> 8, c = loc & 255;
        src = uw + 4*(size_t)loc;
        oo = 4*D2 + (2*r + 1) * 256 + c;
    } else if (i < 4*D2 + 3*F2) {         // down
        src = dw + 4*(size_t)(i - 4*D2 - 2*F2);
        oo = i;
    } else if (i < 5*D2 + 3*F2) {         // key
        src = kw + 4*(size_t)(i - 4*D2 - 3*F2);
        oo = i;
    } else if (i < 6*D2 + 3*F2) {         // val
        src = vw + 4*(size_t)(i - 5*D2 - 3*F2);
        oo = i;
    } else return;
    float4 v = *(const float4*)src;
    uint32_t h0, l0, h1, l1;
    pack_split(v.x, v.y, h0, l0);
    pack_split(v.z, v.w, h1, l1);
    ((uint32_t*)bh)[(size_t)oo*2]   = h0; ((uint32_t*)bh)[(size_t)oo*2+1] = h1;
    ((uint32_t*)bl)[(size_t)oo*2]   = l0; ((uint32_t*)bl)[(size_t)oo*2+1] = l1;
}

// ---------------- RMSNorm (fp32 out optional + bf16 hi/lo) ----------------
__global__ void rmsnorm_k(const float* __restrict__ x, const float* __restrict__ w,
                          float* __restrict__ y, bf16* __restrict__ hi,
                          bf16* __restrict__ lo) {
    int row = blockIdx.x, tid = threadIdx.x;
    float4 xv = ((const float4*)(x + (size_t)row * DD))[tid];
    float ss = xv.x*xv.x + xv.y*xv.y + xv.z*xv.z + xv.w*xv.w;
    #pragma unroll
    for (int o = 16; o; o >>= 1) ss += __shfl_xor_sync(0xffffffffu, ss, o);
    __shared__ float red[8];
    if ((tid & 31) == 0) red[tid >> 5] = ss;
    __syncthreads();
    float tot = 0.f;
    #pragma unroll
    for (int i = 0; i < 8; i++) tot += red[i];
    float inv = rsqrtf(tot * (1.0f / DD) + 1e-6f);
    float4 wv = ((const float4*)w)[tid];
    float4 r;
    r.x = xv.x * inv * wv.x; r.y = xv.y * inv * wv.y;
    r.z = xv.z * inv * wv.z; r.w = xv.w * inv * wv.w;
    if (y) ((float4*)(y + (size_t)row * DD))[tid] = r;
    uint32_t h0, l0, h1, l1;
    pack_split(r.x, r.y, h0, l0);
    pack_split(r.z, r.w, h1, l1);
    size_t base = (size_t)row * DD;
    ((uint32_t*)(hi + base))[2*tid] = h0; ((uint32_t*)(hi + base))[2*tid+1] = h1;
    ((uint32_t*)(lo + base))[2*tid] = l0; ((uint32_t*)(lo + base))[2*tid+1] = l1;
}

// ---------------- Flash attention: bf16 split in, mma.sync, causal -------
#define FP 72
#define FTE (64*FP)
#define FLASH_SMEM (6*FTE*2)

__global__ void __launch_bounds__(128) flash_mma(
    const bf16* __restrict__ qkvh, const bf16* __restrict__ qkvl,
    bf16* __restrict__ ohi, bf16* __restrict__ olo)
{
    bf16* Qh = (bf16*)dynsmem;
    bf16* Ql = Qh + FTE;
    bf16* Kh = Ql + FTE;
    bf16* Kl = Kh + FTE;
    bf16* Vh = Kl + FTE;   // transposed [d][token]
    bf16* Vl = Vh + FTE;
    const uint32_t uQh = smem_u32(Qh), uQl = smem_u32(Ql);
    const uint32_t uKh = smem_u32(Kh), uKl = smem_u32(Kl);
    const uint32_t uVh = smem_u32(Vh), uVl = smem_u32(Vl);

    const int qt = blockIdx.x, bh = blockIdx.y;
    const int b = bh >> 4, h = bh & 15;
    const int q0 = qt * 64;
    const int tid = threadIdx.x;
    const int wid = tid >> 5, lane = tid & 31;
    const int g = lane >> 2, t2 = (lane & 3) * 2;

    const bf16* qbh = qkvh + ((size_t)(b * TT + q0)) * 3072 + h * 64;
    const bf16* qbl = qkvl + ((size_t)(b * TT + q0)) * 3072 + h * 64;
    for (int i = tid; i < 512; i += 128) {
        int m = i >> 3, c8 = (i & 7) * 8;
        *(uint4*)&Qh[m * FP + c8] = *(const uint4*)(qbh + (size_t)m * 3072 + c8);
        *(uint4*)&Ql[m * FP + c8] = *(const uint4*)(qbl + (size_t)m * 3072 + c8);
    }

    float m0r = -1e30f, m1r = -1e30f, l0r = 0.f, l1r = 0.f;
    float oacc[8][4];
    #pragma unroll
    for (int i = 0; i < 8; i++)
        #pragma unroll
        for (int j = 0; j < 4; j++) oacc[i][j] = 0.f;

    const int a_rb = (wid * 16 + (lane & 15)) * FP;
    const int a_cb = ((lane >> 4) << 3);
    const int b_rr = ((lane & 16) >> 1) + (lane & 7);
    const int b_cb = (lane & 8);

    for (int kt = 0; kt <= qt; kt++) {
        __syncthreads();
        {
            const bf16* kbh = qkvh + ((size_t)(b * TT + kt * 64)) * 3072 + 1024 + h * 64;
            const bf16* kbl = qkvl + ((size_t)(b * TT + kt * 64)) * 3072 + 1024 + h * 64;
            const bf16* vbh = qkvh + ((size_t)(b * TT + kt * 64)) * 3072 + 2048 + h * 64;
            const bf16* vbl = qkvl + ((size_t)(b * TT + kt * 64)) * 3072 + 2048 + h * 64;
            for (int i = tid; i < 512; i += 128) {
                int n = i >> 3, c8 = (i & 7) * 8;
                *(uint4*)&Kh[n * FP + c8] = *(const uint4*)(kbh + (size_t)n * 3072 + c8);
                *(uint4*)&Kl[n * FP + c8] = *(const uint4*)(kbl + (size_t)n * 3072 + c8);
                uint4 rh = *(const uint4*)(vbh + (size_t)n * 3072 + c8);
                uint4 rl = *(const uint4*)(vbl + (size_t)n * 3072 + c8);
                const bf16* eh = (const bf16*)&rh;
                const bf16* el = (const bf16*)&rl;
                #pragma unroll
                for (int j = 0; j < 8; j++) {
                    Vh[(c8 + j) * FP + n] = eh[j];
                    Vl[(c8 + j) * FP + n] = el[j];
                }
            }
        }
        __syncthreads();

        float sacc[8][4];
        #pragma unroll
        for (int i = 0; i < 8; i++)
            #pragma unroll
            for (int j = 0; j < 4; j++) sacc[i][j] = 0.f;
        #pragma unroll
        for (int k16 = 0; k16 < 4; k16++) {
            const int kof = k16 * 16;
            uint32_t ahf[4], alf[4];
            uint32_t oq = (uint32_t)(a_rb + kof + a_cb) * 2;
            ldsm4(ahf, uQh + oq);
            ldsm4(alf, uQl + oq);
            uint32_t bhf[4][4], blf[4][4];
            #pragma unroll
            for (int p = 0; p < 4; p++) {
                uint32_t ob = (uint32_t)((p * 16 + b_rr) * FP + kof + b_cb) * 2;
                ldsm4(bhf[p], uKh + ob);
                ldsm4(blf[p], uKl + ob);
            }
            #pragma unroll
            for (int nt = 0; nt < 8; nt++)
                mma16816(sacc[nt], ahf, &bhf[nt >> 1][(nt & 1) * 2]);
            #pragma unroll
            for (int nt = 0; nt < 8; nt++)
                mma16816(sacc[nt], ahf, &blf[nt >> 1][(nt & 1) * 2]);
            #pragma unroll
            for (int nt = 0; nt < 8; nt++)
                mma16816(sacc[nt], alf, &bhf[nt >> 1][(nt & 1) * 2]);
        }

        const int qrow0 = q0 + wid * 16 + g;
        const int qrow1 = qrow0 + 8;
        #pragma unroll
        for (int nt = 0; nt < 8; nt++) {
            int c0 = kt * 64 + nt * 8 + t2;
            float v0 = sacc[nt][0] * 0.125f;
            float v1 = sacc[nt][1] * 0.125f;
            float v2 = sacc[nt][2] * 0.125f;
            float v3 = sacc[nt][3] * 0.125f;
            if (c0 > qrow0) v0 = -1e30f;
            if (c0 + 1 > qrow0) v1 = -1e30f;
            if (c0 > qrow1) v2 = -1e30f;
            if (c0 + 1 > qrow1) v3 = -1e30f;
            sacc[nt][0] = v0; sacc[nt][1] = v1; sacc[nt][2] = v2; sacc[nt][3] = v3;
        }
        float rm0 = -1e30f, rm1 = -1e30f;
        #pragma unroll
        for (int nt = 0; nt < 8; nt++) {
            rm0 = fmaxf(rm0, fmaxf(sacc[nt][0], sacc[nt][1]));
            rm1 = fmaxf(rm1, fmaxf(sacc[nt][2], sacc[nt][3]));
        }
        rm0 = fmaxf(rm0, __shfl_xor_sync(0xffffffffu, rm0, 1));
        rm0 = fmaxf(rm0, __shfl_xor_sync(0xffffffffu, rm0, 2));
        rm1 = fmaxf(rm1, __shfl_xor_sync(0xffffffffu, rm1, 1));
        rm1 = fmaxf(rm1, __shfl_xor_sync(0xffffffffu, rm1, 2));
        float mn0 = fmaxf(m0r, rm0), mn1 = fmaxf(m1r, rm1);
        float cor0 = __expf(m0r - mn0), cor1 = __expf(m1r - mn1);
        float sum0 = 0.f, sum1 = 0.f;
        #pragma unroll
        for (int nt = 0; nt < 8; nt++) {
            sacc[nt][0] = __expf(sacc[nt][0] - mn0);
            sacc[nt][1] = __expf(sacc[nt][1] - mn0);
            sacc[nt][2] = __expf(sacc[nt][2] - mn1);
            sacc[nt][3] = __expf(sacc[nt][3] - mn1);
            sum0 += sacc[nt][0] + sacc[nt][1];
            sum1 += sacc[nt][2] + sacc[nt][3];
        }
        sum0 += __shfl_xor_sync(0xffffffffu, sum0, 1);
        sum0 += __shfl_xor_sync(0xffffffffu, sum0, 2);
        sum1 += __shfl_xor_sync(0xffffffffu, sum1, 1);
        sum1 += __shfl_xor_sync(0xffffffffu, sum1, 2);
        l0r = l0r * cor0 + sum0; m0r = mn0;
        l1r = l1r * cor1 + sum1; m1r = mn1;
        #pragma unroll
        for (int dt = 0; dt < 8; dt++) {
            oacc[dt][0] *= cor0; oacc[dt][1] *= cor0;
            oacc[dt][2] *= cor1; oacc[dt][3] *= cor1;
        }
        #pragma unroll
        for (int j = 0; j < 4; j++) {
            uint32_t ph[4], pl[4];
            pack_split(sacc[2*j][0],   sacc[2*j][1],   ph[0], pl[0]);
            pack_split(sacc[2*j][2],   sacc[2*j][3],   ph[1], pl[1]);
            pack_split(sacc[2*j+1][0], sacc[2*j+1][1], ph[2], pl[2]);
            pack_split(sacc[2*j+1][2], sacc[2*j+1][3], ph[3], pl[3]);
            #pragma unroll
            for (int dp = 0; dp < 4; dp++) {
                uint32_t ov = (uint32_t)((dp * 16 + b_rr) * FP + 16*j + b_cb) * 2;
                uint32_t vbh4[4], vbl4[4];
                ldsm4(vbh4, uVh + ov);
                ldsm4(vbl4, uVl + ov);
                mma16816(oacc[2*dp],   ph, &vbh4[0]);
                mma16816(oacc[2*dp+1], ph, &vbh4[2]);
                mma16816(oacc[2*dp],   ph, &vbl4[0]);
                mma16816(oacc[2*dp+1], ph, &vbl4[2]);
                mma16816(oacc[2*dp],   pl, &vbh4[0]);
                mma16816(oacc[2*dp+1], pl, &vbh4[2]);
            }
        }
    }

    float inv0 = 1.0f / l0r, inv1 = 1.0f / l1r;
    size_t ob0 = (size_t)b * TT * DD + (size_t)(q0 + wid * 16 + g) * DD + h * HDIM;
    size_t ob1 = ob0 + 8 * DD;
    #pragma unroll
    for (int dt = 0; dt < 8; dt++) {
        uint32_t hh, ll;
        pack_split(oacc[dt][0] * inv0, oacc[dt][1] * inv0, hh, ll);
        *(uint32_t*)(ohi + ob0 + dt*8 + t2) = hh;
        *(uint32_t*)(olo + ob0 + dt*8 + t2) = ll;
        pack_split(oacc[dt][2] * inv1, oacc[dt][3] * inv1, hh, ll);
        *(uint32_t*)(ohi + ob1 + dt*8 + t2) = hh;
        *(uint32_t*)(olo + ob1 + dt*8 + t2) = ll;
    }
}

// ---------------- engram hash + gather -> bf16 hi/lo ----------------
__global__ void gather_k(const int* __restrict__ ids, const float* __restrict__ tables,
                         const int* __restrict__ hm, bf16* __restrict__ hi,
                         bf16* __restrict__ lo) {
    int tok = blockIdx.x;
    int t = tok & (TT - 1);
    int id0 = ids[tok];
    int id1 = (t >= 1) ? ids[tok - 1] : 0;
    int id2 = (t >= 2) ? ids[tok - 2] : 0;
    unsigned m0 = (unsigned)hm[0], m1 = (unsigned)hm[1], m2 = (unsigned)hm[2];
    unsigned h2 = (unsigned)id0 * m0 ^ (unsigned)id1 * m1;
    unsigned h3 = h2 ^ (unsigned)id2 * m2;
    int tid = threadIdx.x;
    size_t ob = (size_t)tok * 1024;
    #pragma unroll
    for (int r = 0; r < 4; r++) {
        int e = tid + r * 256;
        int tt = e >> 6, ee = e & 63;
        int head = tt & 7;
        unsigned hh = ((tt < 8) ? h2 : h3) + (unsigned)(head * 7919);
        int sv = (int)hh;
        int idx = sv % NGV;
        if (idx < 0) idx += NGV;
        float f = tables[((size_t)tt * NGV + idx) * 64 + ee];
        bf16 hb, lb;
        split1(f, hb, lb);
        hi[ob + e] = hb;
        lo[ob + e] = lb;
    }
}

// ---------------- gate (keye/vale in one [BT,2048] buffer) ---------------
__global__ void gate_k(const float* __restrict__ hn, const float* __restrict__ kvb,
                       const float* __restrict__ nkw, const float* __restrict__ nqw,
                       float* __restrict__ value) {
    int row = blockIdx.x, tid = threadIdx.x;
    const float* keye = kvb + (size_t)row * 2048;
    const float* vale = keye + 1024;
    float4 kv = ((const float4*)keye)[tid];
    float4 hv = ((const float4*)(hn + (size_t)row * DD))[tid];
    float4 wk = ((const float4*)nkw)[tid];
    float4 wq = ((const float4*)nqw)[tid];
    float skk = kv.x*kv.x + kv.y*kv.y + kv.z*kv.z + kv.w*kv.w;
    float shh = hv.x*hv.x + hv.y*hv.y + hv.z*hv.z + hv.w*hv.w;
    float sdt = kv.x*wk.x*hv.x*wq.x + kv.y*wk.y*hv.y*wq.y
              + kv.z*wk.z*hv.z*wq.z + kv.w*wk.w*hv.w*wq.w;
    #pragma unroll
    for (int o = 16; o; o >>= 1) {
        skk += __shfl_xor_sync(0xffffffffu, skk, o);
        shh += __shfl_xor_sync(0xffffffffu, shh, o);
        sdt += __shfl_xor_sync(0xffffffffu, sdt, o);
    }
    __shared__ float r1[8], r2[8], r3[8];
    if ((tid & 31) == 0) { r1[tid>>5] = skk; r2[tid>>5] = shh; r3[tid>>5] = sdt; }
    __syncthreads();
    float tkk = 0, thh = 0, tdt = 0;
    #pragma unroll
    for (int i = 0; i < 8; i++) { tkk += r1[i]; thh += r2[i]; tdt += r3[i]; }
    float nk = rsqrtf(tkk * (1.0f / DD) + 1e-6f);
    float nh = rsqrtf(thh * (1.0f / DD) + 1e-6f);
    float gg = tdt * nk * nh * (1.0f / 32.0f);
    float ab = fabsf(gg);
    float rt = sqrtf(fmaxf(ab, 1e-6f));
    float sgn = (gg > 0.f) ? 1.f : ((gg < 0.f) ? -1.f : 0.f);
    float sig = 1.f / (1.f + expf(-rt * sgn));
    float4 vv = ((const float4*)vale)[tid];
    float4 r = make_float4(sig*vv.x, sig*vv.y, sig*vv.z, sig*vv.w);
    ((float4*)(value + (size_t)row * DD))[tid] = r;
}

// ---------------- final ----------------
__global__ void final_k(const float* __restrict__ value, const float* __restrict__ cw,
                        float* __restrict__ out) {
    int idx = blockIdx.x * 256 + threadIdx.x;
    int d = idx & (DD - 1);
    int bt = idx >> 10;
    int t = bt & (TT - 1);
    float c = 0.f;
    #pragma unroll
    for (int kk = 0; kk < 4; kk++) {
        int tt = t - 3 + kk;
        if (tt >= 0)
            c += value[(size_t)(bt - 3 + kk) * DD + d] * cw[d * 4 + kk];
    }
    float vv = value[idx];
    float sc = c / (1.f + expf(-c));
    out[idx] += vv + sc;
}

// ================= host =================
typedef CUresult (*PFN_encode)(CUtensorMap*, CUtensorMapDataType, cuuint32_t, void*,
                               const cuuint64_t*, const cuuint64_t*, const cuuint32_t*,
                               const cuuint32_t*, CUtensorMapInterleave, CUtensorMapSwizzle,
                               CUtensorMapL2promotion, CUtensorMapFloatOOBfill);
static PFN_encode get_encoder() {
    static PFN_encode fn = nullptr;
    if (!fn) {
        void* p = nullptr;
        cudaDriverEntryPointQueryResult qr;
        cudaGetDriverEntryPoint("cuTensorMapEncodeTiled", &p, cudaEnableDefault, &qr);
        fn = (PFN_encode)p;
    }
    return fn;
}
static void make_map(CUtensorMap* m, void* ptr, uint64_t Kdim, uint64_t Rows) {
    cuuint64_t dims[2] = {Kdim, Rows};
    cuuint64_t strides[1] = {Kdim * 2};
    cuuint32_t box[2] = {32, 128};
    cuuint32_t es[2] = {1, 1};
    get_encoder()(m, CU_TENSOR_MAP_DATA_TYPE_BFLOAT16, 2, ptr, dims, strides, box, es,
                  CU_TENSOR_MAP_INTERLEAVE_NONE, CU_TENSOR_MAP_SWIZZLE_64B,
                  CU_TENSOR_MAP_L2_PROMOTION_L2_128B, CU_TENSOR_MAP_FLOAT_OOB_FILL_NONE);
}
static float* symaddr(const void* sym) {
    void* p = nullptr;
    cudaGetSymbolAddress(&p, sym);
    return (float*)p;
}

template<int MODE>
static void run_gemm(bf16* ah, bf16* al, bf16* bh, bf16* bl,
                     float* C, const float* addC, const float* bias, const float* bias2,
                     bf16* outh, bf16* outl, int M, int N, int K) {
    CUtensorMap mah, mal, mbh, mbl;
    make_map(&mah, ah, K, M);
    make_map(&mal, al, K, M);
    make_map(&mbh, bh, K, N);
    make_map(&mbl, bl, K, N);
    dim3 grid(N / 128, M / 128);
    gemm_tma<MODE><<<grid, 256, GEMM_SMEM>>>(mah, mal, mbh, mbl, C, addC, bias, bias2,
                                             outh, outl, M, N, K);
}

extern "C" void kernel_launch(void* const* d_in, const int* in_sizes, int n_in,
                              void* d_out, int out_size) {
    const float* x     = (const float*)d_in[0];
    const int*   ids   = (const int*)d_in[1];
    const float* wq    = (const float*)d_in[3];
    const float* wk    = (const float*)d_in[4];
    const float* wv    = (const float*)d_in[5];
    const float* wo    = (const float*)d_in[6];
    const float* attnw = (const float*)d_in[7];
    const float* ffnw  = (const float*)d_in[8];
    const float* gatew = (const float*)d_in[9];
    const float* upw   = (const float*)d_in[10];
    const float* downw = (const float*)d_in[11];
    const float* embt  = (const float*)d_in[12];
    const float* keyw  = (const float*)d_in[13];
    const float* keyb  = (const float*)d_in[14];
    const float* valw  = (const float*)d_in[15];
    const float* valb  = (const float*)d_in[16];
    const float* normk = (const float*)d_in[17];
    const float* normq = (const float*)d_in[18];
    const float* convw = (const float*)d_in[19];
    const int*   hm    = (const int*)d_in[20];

    float* p_h    = symaddr(g_h);
    float* p_hn   = symaddr(g_hn);
    float* p_val  = symaddr(g_value);
    float* p_kv   = symaddr(g_kv);
    bf16* p_ah = (bf16*)symaddr(g_ah);
    bf16* p_al = (bf16*)symaddr(g_al);
    bf16* p_sh = (bf16*)symaddr(g_sh);
    bf16* p_sl = (bf16*)symaddr(g_sl);
    bf16* p_eh = (bf16*)symaddr(g_eh);
    bf16* p_el = (bf16*)symaddr(g_el);
    bf16* p_qh = (bf16*)symaddr(g_qh);
    bf16* p_ql = (bf16*)symaddr(g_ql);
    bf16* p_bh = (bf16*)symaddr(g_bh);
    bf16* p_bl = (bf16*)symaddr(g_bl);
    float* out = (float*)d_out;

    static bool attrs_set = false;
    if (!attrs_set) {
        cudaFuncSetAttribute(gemm_tma<0>, cudaFuncAttributeMaxDynamicSharedMemorySize, GEMM_SMEM);
        cudaFuncSetAttribute(gemm_tma<1>, cudaFuncAttributeMaxDynamicSharedMemorySize, GEMM_SMEM);
        cudaFuncSetAttribute(gemm_tma<2>, cudaFuncAttributeMaxDynamicSharedMemorySize, GEMM_SMEM);
        cudaFuncSetAttribute(flash_mma, cudaFuncAttributeMaxDynamicSharedMemorySize, FLASH_SMEM);
        attrs_set = true;
    }

    dim3 blk(256);

    // 0: all weights split (gate/up interleaved)
    split_weights<<<(6*D2 + 3*F2 + 255) / 256, blk>>>(wq, wk, wv, wo, gatew, upw, downw,
                                                      keyw, valw, p_bh, p_bl);
    // 1: engram gather
    gather_k<<<BT, blk>>>(ids, embt, hm, p_eh, p_el);
    // 2: attn rmsnorm
    rmsnorm_k<<<BT, blk>>>(x, attnw, nullptr, p_ah, p_al);
    // 3: fused QKV gemm + rope -> split bf16
    run_gemm<1>(p_ah, p_al, p_bh + WOFF_QKV, p_bl + WOFF_QKV,
                nullptr, nullptr, nullptr, nullptr, p_qh, p_ql, BT, 3072, DD);
    // 4: flash attention
    flash_mma<<<dim3(TT / 64, BB * NHEAD), 128, FLASH_SMEM>>>(p_qh, p_ql, p_ah, p_al);
    // 5: O projection + residual  (profiled launch)
    run_gemm<0>(p_ah, p_al, p_bh + WOFF_WO, p_bl + WOFF_WO,
                p_h, x, nullptr, nullptr, nullptr, nullptr, BT, DD, DD);
    // 6: ffn rmsnorm
    rmsnorm_k<<<BT, blk>>>(p_h, ffnw, p_hn, p_ah, p_al);
    // 7: fused gate/up gemm + silu -> split bf16
    run_gemm<2>(p_ah, p_al, p_bh + WOFF_GU, p_bl + WOFF_GU,
                nullptr, nullptr, nullptr, nullptr, p_sh, p_sl, BT, 2 * FFN, DD);
    // 8: down projection + residual -> out
    run_gemm<0>(p_sh, p_sl, p_bh + WOFF_DOWN, p_bl + WOFF_DOWN,
                out, p_h, nullptr, nullptr, nullptr, nullptr, BT, DD, FFN);
    // 9: key/val gemm (dual bias)
    run_gemm<0>(p_eh, p_el, p_bh + WOFF_KV, p_bl + WOFF_KV,
                p_kv, nullptr, keyb, valb, nullptr, nullptr, BT, 2048, DD);
    // 10: gate
    gate_k<<<BT, blk>>>(p_hn, p_kv, normk, normq, p_val);
    // 11: conv + silu + residual
    final_k<<<(BT * DD) / 256, blk>>>(p_val, convw, out);
}

// round 6
// speedup vs baseline: 4.7560x; 1.4701x over previous
#include <cuda_runtime.h>
#include <cuda_fp16.h>
#include <cuda.h>
#include <math.h>
#include <stdint.h>

#define BB 2
#define TT 2048
#define DD 1024
#define NHEAD 16
#define HDIM 64
#define FFN 4096
#define BT (BB*TT)
#define NGV 50000

typedef __half fp16;

// ---------------- scratch (device globals; no allocation) ----------------
__device__ float g_h[BT*DD];
__device__ float g_hn[BT*DD];
__device__ float g_value[BT*DD];
__device__ float g_kv[(size_t)BT*2048];
__device__ __align__(1024) fp16 g_a[BT*DD];            // activations: xn, O, hn
__device__ __align__(1024) fp16 g_s[(size_t)BT*FFN];   // silu output
__device__ __align__(1024) fp16 g_e[BT*DD];            // engram emb
__device__ __align__(1024) fp16 g_q3[(size_t)BT*3072]; // rope'd qkv
// weights split: [qkv 3M][wo 1M][gate/up interleaved 8M][down 4M][key 1M][val 1M]
#define WOFF_QKV 0
#define WOFF_WO   (3u*1024*1024)
#define WOFF_GU   (4u*1024*1024)
#define WOFF_DOWN (12u*1024*1024)
#define WOFF_KV   (16u*1024*1024)
__device__ __align__(1024) fp16 g_bh[18u*1024*1024];
__device__ __align__(1024) fp16 g_bl[18u*1024*1024];

extern __shared__ char dynsmem[];

// ================= low-level helpers =================
__device__ __forceinline__ uint32_t smem_u32(const void* p) {
    uint32_t a;
    asm("{ .reg .u64 t; cvta.to.shared.u64 t, %1; cvt.u32.u64 %0, t; }" : "=r"(a) : "l"(p));
    return a;
}
__device__ __forceinline__ uint32_t swz64(uint32_t o) { return o ^ ((o >> 3) & 0x30); }

#define MBAR_INIT(addr, cnt) \
    asm volatile("mbarrier.init.shared.b64 [%0], %1;" :: "r"((uint32_t)(addr)), "r"((uint32_t)(cnt)) : "memory")
#define MBAR_EXPECT_TX(addr, bytes) \
    asm volatile("mbarrier.arrive.expect_tx.shared.b64 _, [%0], %1;" :: "r"((uint32_t)(addr)), "r"((uint32_t)(bytes)) : "memory")
#define MBAR_WAIT(addr, parity) do { \
    uint32_t _m = (uint32_t)(addr); uint32_t _p = (uint32_t)(parity); uint32_t _d; \
    asm volatile("{\n\t.reg .pred p;\n\t" \
        "mbarrier.try_wait.parity.acquire.cta.shared::cta.b64 p, [%1], %2;\n\t" \
        "selp.b32 %0, 1, 0, p;\n\t}" : "=r"(_d) : "r"(_m), "r"(_p) : "memory"); \
    if (!_d) { \
        asm volatile("{\n\t.reg .pred P1;\n\t" \
            "WL_%=:\n\t" \
            "mbarrier.try_wait.parity.acquire.cta.shared::cta.b64 P1, [%0], %1, 0x989680;\n\t" \
            "@P1 bra.uni WD_%=;\n\t" \
            "bra.uni WL_%=;\n\t" \
            "WD_%=:\n\t}" :: "r"(_m), "r"(_p) : "memory"); \
    } \
} while (0)

#define TMA_LOAD2D(smem_addr, map_ptr, cx, cy, mbar) \
    asm volatile("cp.async.bulk.tensor.2d.shared::cta.global.tile.mbarrier::complete_tx::bytes " \
        "[%0], [%1, {%2, %3}], [%4];" \
        :: "r"((uint32_t)(smem_addr)), "l"(map_ptr), "r"((int)(cx)), "r"((int)(cy)), \
           "r"((uint32_t)(mbar)) : "memory")

__device__ __forceinline__ void ldsm4(uint32_t* r, uint32_t addr) {
    asm volatile("ldmatrix.sync.aligned.m8n8.x4.shared.b16 {%0,%1,%2,%3}, [%4];"
        : "=r"(r[0]), "=r"(r[1]), "=r"(r[2]), "=r"(r[3]) : "r"(addr));
}
__device__ __forceinline__ void mma16816(float* d, const uint32_t* a, const uint32_t* b) {
    asm volatile("mma.sync.aligned.m16n8k16.row.col.f32.f16.f16.f32 "
        "{%0,%1,%2,%3}, {%4,%5,%6,%7}, {%8,%9}, {%0,%1,%2,%3};"
        : "+f"(d[0]), "+f"(d[1]), "+f"(d[2]), "+f"(d[3])
        : "r"(a[0]), "r"(a[1]), "r"(a[2]), "r"(a[3]), "r"(b[0]), "r"(b[1]));
}
__device__ __forceinline__ uint32_t pack_h2(float x, float y) {
    __half2 h = __floats2half2_rn(x, y);
    return *(uint32_t*)&h;
}
__device__ __forceinline__ void split1h(float v, fp16& h, fp16& l) {
    h = __float2half_rn(v);
    l = __float2half_rn(v - __half2float(h));
}

// ================= TMA + mma.sync fp16 2-product GEMM ====================
// C[M,N] = A[M,K]*B[N,K]^T,  B = Bh + Bl (fp16 split), A single fp16.
// CTA 128x128, BK=32, 4 stages x 24KB. occ 2.
// MODE 0: fp32 C (+addC) (+dual bias split at N/2)
// MODE 1: QKV -> rope (cols<2048) -> fp16
// MODE 2: gate/up interleaved -> silu(g)*u -> fp16, stride N/2
#define NSTG 4
#define TIL 8192
#define STG_B (3*TIL)
#define GEMM_SMEM (1024 + NSTG*STG_B)

template<int MODE>
__global__ void __launch_bounds__(256, 2) gemm_tma(
    const __grid_constant__ CUtensorMap ma,
    const __grid_constant__ CUtensorMap mbh,
    const __grid_constant__ CUtensorMap mbl,
    float* __restrict__ C, const float* __restrict__ addC,
    const float* __restrict__ bias, const float* __restrict__ bias2,
    fp16* __restrict__ outp, int M, int N, int K)
{
    const uint32_t sb = smem_u32(dynsmem);
    const uint32_t fullb = sb;
    const uint32_t stg0 = sb + 1024;
    const int tid = threadIdx.x;
    const int wid = tid >> 5, lane = tid & 31;
    const int wm = wid & 3, wn = wid >> 2;
    const int m0 = blockIdx.y * 128, n0 = blockIdx.x * 128;
    const int NT = K >> 5;

    if (tid == 0) {
        #pragma unroll
        for (int s = 0; s < NSTG; s++) MBAR_INIT(fullb + 8*s, 1);
    }
    __syncthreads();
    if (tid == 0) {
        #pragma unroll
        for (int s = 0; s < 3; s++) {
            uint32_t st = stg0 + s * STG_B;
            MBAR_EXPECT_TX(fullb + 8*s, STG_B);
            TMA_LOAD2D(st,         &ma,  s*32, m0, fullb + 8*s);
            TMA_LOAD2D(st + TIL,   &mbh, s*32, n0, fullb + 8*s);
            TMA_LOAD2D(st + 2*TIL, &mbl, s*32, n0, fullb + 8*s);
        }
    }

    float acc[2][8][4];
    #pragma unroll
    for (int i = 0; i < 2; i++)
        #pragma unroll
        for (int j = 0; j < 8; j++)
            #pragma unroll
            for (int q = 0; q < 4; q++) acc[i][j][q] = 0.f;

    const int a_row0 = wm * 32 + (lane & 15);
    const int acbyte = (lane >> 4) * 16;
    const int b_rr = ((lane & 16) >> 1) + (lane & 7);
    const int bcbyte = (lane & 8) * 2;

    for (int kt = 0; kt < NT; kt++) {
        int s = kt % NSTG;
        MBAR_WAIT(fullb + 8*s, (kt / NSTG) & 1);
        uint32_t st = stg0 + s * STG_B;
        #pragma unroll
        for (int k16 = 0; k16 < 2; k16++) {
            const int kofb = k16 * 32;
            uint32_t a0[4], a1[4];
            uint32_t oa0 = swz64((uint32_t)(a_row0 * 64 + acbyte + kofb));
            uint32_t oa1 = swz64((uint32_t)((a_row0 + 16) * 64 + acbyte + kofb));
            ldsm4(a0, st + oa0);
            ldsm4(a1, st + oa1);
            #pragma unroll
            for (int p = 0; p < 4; p++) {
                uint32_t ob = swz64((uint32_t)((wn * 64 + p * 16 + b_rr) * 64 + bcbyte + kofb));
                uint32_t bh[4];
                ldsm4(bh, st + TIL + ob);
                mma16816(acc[0][2*p],   a0, bh);
                mma16816(acc[0][2*p+1], a0, bh + 2);
                mma16816(acc[1][2*p],   a1, bh);
                mma16816(acc[1][2*p+1], a1, bh + 2);
            }
            #pragma unroll
            for (int p = 0; p < 4; p++) {
                uint32_t ob = swz64((uint32_t)((wn * 64 + p * 16 + b_rr) * 64 + bcbyte + kofb));
                uint32_t bl[4];
                ldsm4(bl, st + 2*TIL + ob);
                mma16816(acc[0][2*p],   a0, bl);
                mma16816(acc[0][2*p+1], a0, bl + 2);
                mma16816(acc[1][2*p],   a1, bl);
                mma16816(acc[1][2*p+1], a1, bl + 2);
            }
        }
        __syncthreads();
        if (tid == 0 && kt + 3 < NT) {
            int s2 = (kt + 3) % NSTG;
            uint32_t st2 = stg0 + s2 * STG_B;
            MBAR_EXPECT_TX(fullb + 8*s2, STG_B);
            TMA_LOAD2D(st2,         &ma,  (kt+3)*32, m0, fullb + 8*s2);
            TMA_LOAD2D(st2 + TIL,   &mbh, (kt+3)*32, n0, fullb + 8*s2);
            TMA_LOAD2D(st2 + 2*TIL, &mbl, (kt+3)*32, n0, fullb + 8*s2);
        }
    }

    const int g = lane >> 2, t2 = (lane & 3) * 2;
    const int base_c = n0 + wn * 64;

    if (MODE == 0) {
        #pragma unroll
        for (int mt = 0; mt < 2; mt++)
            #pragma unroll
            for (int nt = 0; nt < 8; nt++) {
                int grow = m0 + wm * 32 + mt * 16 + g;
                int gcol = base_c + nt * 8 + t2;
                float2 v0 = make_float2(acc[mt][nt][0], acc[mt][nt][1]);
                float2 v1 = make_float2(acc[mt][nt][2], acc[mt][nt][3]);
                if (bias) {
                    const float* bp = (gcol < (N >> 1)) ? bias + gcol : bias2 + gcol - (N >> 1);
                    float2 bv = *(const float2*)bp;
                    v0.x += bv.x; v0.y += bv.y; v1.x += bv.x; v1.y += bv.y;
                }
                if (addC) {
                    float2 d0 = *(const float2*)(addC + (size_t)grow * N + gcol);
                    float2 d1 = *(const float2*)(addC + (size_t)(grow + 8) * N + gcol);
                    v0.x += d0.x; v0.y += d0.y; v1.x += d1.x; v1.y += d1.y;
                }
                *(float2*)(C + (size_t)grow * N + gcol) = v0;
                *(float2*)(C + (size_t)(grow + 8) * N + gcol) = v1;
            }
    } else if (MODE == 1) {
        #pragma unroll
        for (int mt = 0; mt < 2; mt++)
            #pragma unroll
            for (int rr = 0; rr < 2; rr++) {
                int row = m0 + wm * 32 + mt * 16 + g + rr * 8;
                float ft = (float)(row & (TT - 1));
                size_t rb = (size_t)row * N;
                if (base_c < 2048) {  // q or k: rope
                    #pragma unroll
                    for (int nt = 0; nt < 4; nt++) {
                        int cc = base_c + nt * 8 + t2;
                        int d0 = cc & 63;
                        float inv0 = expf(-(float)(2*d0)     * (1.0f/64.0f) * 9.2103403719761836f);
                        float inv1 = expf(-(float)(2*(d0+1)) * (1.0f/64.0f) * 9.2103403719761836f);
                        float s0, c0, s1, c1;
                        sincosf(ft * inv0, &s0, &c0);
                        sincosf(ft * inv1, &s1, &c1);
                        float vl0 = acc[mt][nt][rr*2],   vl1 = acc[mt][nt][rr*2+1];
                        float vh0 = acc[mt][nt+4][rr*2], vh1 = acc[mt][nt+4][rr*2+1];
                        float ol0 = vl0 * c0 - vh0 * s0, oh0 = vh0 * c0 + vl0 * s0;
                        float ol1 = vl1 * c1 - vh1 * s1, oh1 = vh1 * c1 + vl1 * s1;
                        *(uint32_t*)(outp + rb + cc)      = pack_h2(ol0, ol1);
                        *(uint32_t*)(outp + rb + cc + 32) = pack_h2(oh0, oh1);
                    }
                } else {  // v: plain
                    #pragma unroll
                    for (int nt = 0; nt < 8; nt++) {
                        int cc = base_c + nt * 8 + t2;
                        *(uint32_t*)(outp + rb + cc) =
                            pack_h2(acc[mt][nt][rr*2], acc[mt][nt][rr*2+1]);
                    }
                }
            }
    } else {  // MODE 2: silu(gate)*up, interleaved cols
        const int NO = N >> 1;
        #pragma unroll
        for (int mt = 0; mt < 2; mt++)
            #pragma unroll
            for (int rr = 0; rr < 2; rr++) {
                int row = m0 + wm * 32 + mt * 16 + g + rr * 8;
                size_t rb = (size_t)row * NO;
                #pragma unroll
                for (int nt = 0; nt < 8; nt++) {
                    float gg = acc[mt][nt][rr*2];
                    float uu = acc[mt][nt][rr*2+1];
                    float sv = gg / (1.f + expf(-gg)) * uu;
                    int j = (base_c + nt * 8 + t2) >> 1;
                    outp[rb + j] = __float2half_rn(sv);
                }
            }
    }
}

// ---------------- all-weights split (gate/up interleaved) ----------------
#define D2 262144u
#define F2 1048576u
__global__ void split_weights(
    const float* __restrict__ wq, const float* __restrict__ wk,
    const float* __restrict__ wv, const float* __restrict__ wo,
    const float* __restrict__ gw, const float* __restrict__ uw,
    const float* __restrict__ dw, const float* __restrict__ kw,
    const float* __restrict__ vw, fp16* __restrict__ bh, fp16* __restrict__ bl)
{
    uint32_t i = blockIdx.x * 256 + threadIdx.x;
    const float* src;
    uint32_t oo;
    if (i < 3*D2) {
        src = (i < D2) ? wq + 4*(size_t)i : (i < 2*D2) ? wk + 4*(size_t)(i - D2) : wv + 4*(size_t)(i - 2*D2);
        oo = i;
    } else if (i < 4*D2) {
        src = wo + 4*(size_t)(i - 3*D2);
        oo = i;
    } else if (i < 4*D2 + F2) {
        uint32_t loc = i - 4*D2;
        uint32_t r = loc >> 8, c = loc & 255;
        src = gw + 4*(size_t)loc;
        oo = 4*D2 + (2*r) * 256 + c;
    } else if (i < 4*D2 + 2*F2) {
        uint32_t loc = i - 4*D2 - F2;
        uint32_t r = loc >> 8, c = loc & 255;
        src = uw + 4*(size_t)loc;
        oo = 4*D2 + (2*r + 1) * 256 + c;
    } else if (i < 4*D2 + 3*F2) {
        src = dw + 4*(size_t)(i - 4*D2 - 2*F2);
        oo = i;
    } else if (i < 5*D2 + 3*F2) {
        src = kw + 4*(size_t)(i - 4*D2 - 3*F2);
        oo = i;
    } else if (i < 6*D2 + 3*F2) {
        src = vw + 4*(size_t)(i - 5*D2 - 3*F2);
        oo = i;
    } else return;
    float4 v = *(const float4*)src;
    fp16 h0,h1,h2,h3,l0,l1,l2,l3;
    split1h(v.x,h0,l0); split1h(v.y,h1,l1); split1h(v.z,h2,l2); split1h(v.w,h3,l3);
    __half2 hh0(h0,h1), hh1(h2,h3), ll0(l0,l1), ll1(l2,l3);
    ((uint32_t*)bh)[(size_t)oo*2]   = *(uint32_t*)&hh0;
    ((uint32_t*)bh)[(size_t)oo*2+1] = *(uint32_t*)&hh1;
    ((uint32_t*)bl)[(size_t)oo*2]   = *(uint32_t*)&ll0;
    ((uint32_t*)bl)[(size_t)oo*2+1] = *(uint32_t*)&ll1;
}

// ---------------- RMSNorm (optional fp32 out + fp16 out) ----------------
__global__ void rmsnorm_k(const float* __restrict__ x, const float* __restrict__ w,
                          float* __restrict__ y, fp16* __restrict__ o16) {
    int row = blockIdx.x, tid = threadIdx.x;
    float4 xv = ((const float4*)(x + (size_t)row * DD))[tid];
    float ss = xv.x*xv.x + xv.y*xv.y + xv.z*xv.z + xv.w*xv.w;
    #pragma unroll
    for (int o = 16; o; o >>= 1) ss += __shfl_xor_sync(0xffffffffu, ss, o);
    __shared__ float red[8];
    if ((tid & 31) == 0) red[tid >> 5] = ss;
    __syncthreads();
    float tot = 0.f;
    #pragma unroll
    for (int i = 0; i < 8; i++) tot += red[i];
    float inv = rsqrtf(tot * (1.0f / DD) + 1e-6f);
    float4 wv = ((const float4*)w)[tid];
    float4 r;
    r.x = xv.x * inv * wv.x; r.y = xv.y * inv * wv.y;
    r.z = xv.z * inv * wv.z; r.w = xv.w * inv * wv.w;
    if (y) ((float4*)(y + (size_t)row * DD))[tid] = r;
    size_t base = (size_t)row * DD;
    ((uint32_t*)(o16 + base))[2*tid]   = pack_h2(r.x, r.y);
    ((uint32_t*)(o16 + base))[2*tid+1] = pack_h2(r.z, r.w);
}

// ---------------- Flash attention: fp16 single-precision fragments -------
#define FP 72
#define FTE (64*FP)
#define FLASH_SMEM (3*FTE*2)

__global__ void __launch_bounds__(128) flash_mma(
    const fp16* __restrict__ qkv, fp16* __restrict__ o16)
{
    fp16* Qs = (fp16*)dynsmem;
    fp16* Ks = Qs + FTE;
    fp16* Vs = Ks + FTE;   // transposed [d][token]
    const uint32_t uQ = smem_u32(Qs), uK = smem_u32(Ks), uV = smem_u32(Vs);

    const int qt = blockIdx.x, bh = blockIdx.y;
    const int b = bh >> 4, h = bh & 15;
    const int q0 = qt * 64;
    const int tid = threadIdx.x;
    const int wid = tid >> 5, lane = tid & 31;
    const int g = lane >> 2, t2 = (lane & 3) * 2;

    const fp16* qb = qkv + ((size_t)(b * TT + q0)) * 3072 + h * 64;
    for (int i = tid; i < 512; i += 128) {
        int m = i >> 3, c8 = (i & 7) * 8;
        *(uint4*)&Qs[m * FP + c8] = *(const uint4*)(qb + (size_t)m * 3072 + c8);
    }

    float m0r = -1e30f, m1r = -1e30f, l0r = 0.f, l1r = 0.f;
    float oacc[8][4];
    #pragma unroll
    for (int i = 0; i < 8; i++)
        #pragma unroll
        for (int j = 0; j < 4; j++) oacc[i][j] = 0.f;

    const int a_rb = (wid * 16 + (lane & 15)) * FP;
    const int a_cb = ((lane >> 4) << 3);
    const int b_rr = ((lane & 16) >> 1) + (lane & 7);
    const int b_cb = (lane & 8);

    for (int kt = 0; kt <= qt; kt++) {
        __syncthreads();
        {
            const fp16* kb = qkv + ((size_t)(b * TT + kt * 64)) * 3072 + 1024 + h * 64;
            const fp16* vb = qkv + ((size_t)(b * TT + kt * 64)) * 3072 + 2048 + h * 64;
            for (int i = tid; i < 512; i += 128) {
                int n = i >> 3, c8 = (i & 7) * 8;
                *(uint4*)&Ks[n * FP + c8] = *(const uint4*)(kb + (size_t)n * 3072 + c8);
                uint4 rv = *(const uint4*)(vb + (size_t)n * 3072 + c8);
                const fp16* ev = (const fp16*)&rv;
                #pragma unroll
                for (int j = 0; j < 8; j++) Vs[(c8 + j) * FP + n] = ev[j];
            }
        }
        __syncthreads();

        float sacc[8][4];
        #pragma unroll
        for (int i = 0; i < 8; i++)
            #pragma unroll
            for (int j = 0; j < 4; j++) sacc[i][j] = 0.f;
        #pragma unroll
        for (int k16 = 0; k16 < 4; k16++) {
            const int kof = k16 * 16;
            uint32_t af[4];
            ldsm4(af, uQ + (uint32_t)(a_rb + kof + a_cb) * 2);
            uint32_t bf[4][4];
            #pragma unroll
            for (int p = 0; p < 4; p++)
                ldsm4(bf[p], uK + (uint32_t)((p * 16 + b_rr) * FP + kof + b_cb) * 2);
            #pragma unroll
            for (int nt = 0; nt < 8; nt++)
                mma16816(sacc[nt], af, &bf[nt >> 1][(nt & 1) * 2]);
        }

        const int qrow0 = q0 + wid * 16 + g;
        const int qrow1 = qrow0 + 8;
        #pragma unroll
        for (int nt = 0; nt < 8; nt++) {
            int c0 = kt * 64 + nt * 8 + t2;
            float v0 = sacc[nt][0] * 0.125f;
            float v1 = sacc[nt][1] * 0.125f;
            float v2 = sacc[nt][2] * 0.125f;
            float v3 = sacc[nt][3] * 0.125f;
            if (c0 > qrow0) v0 = -1e30f;
            if (c0 + 1 > qrow0) v1 = -1e30f;
            if (c0 > qrow1) v2 = -1e30f;
            if (c0 + 1 > qrow1) v3 = -1e30f;
            sacc[nt][0] = v0; sacc[nt][1] = v1; sacc[nt][2] = v2; sacc[nt][3] = v3;
        }
        float rm0 = -1e30f, rm1 = -1e30f;
        #pragma unroll
        for (int nt = 0; nt < 8; nt++) {
            rm0 = fmaxf(rm0, fmaxf(sacc[nt][0], sacc[nt][1]));
            rm1 = fmaxf(rm1, fmaxf(sacc[nt][2], sacc[nt][3]));
        }
        rm0 = fmaxf(rm0, __shfl_xor_sync(0xffffffffu, rm0, 1));
        rm0 = fmaxf(rm0, __shfl_xor_sync(0xffffffffu, rm0, 2));
        rm1 = fmaxf(rm1, __shfl_xor_sync(0xffffffffu, rm1, 1));
        rm1 = fmaxf(rm1, __shfl_xor_sync(0xffffffffu, rm1, 2));
        float mn0 = fmaxf(m0r, rm0), mn1 = fmaxf(m1r, rm1);
        float cor0 = __expf(m0r - mn0), cor1 = __expf(m1r - mn1);
        float sum0 = 0.f, sum1 = 0.f;
        #pragma unroll
        for (int nt = 0; nt < 8; nt++) {
            sacc[nt][0] = __expf(sacc[nt][0] - mn0);
            sacc[nt][1] = __expf(sacc[nt][1] - mn0);
            sacc[nt][2] = __expf(sacc[nt][2] - mn1);
            sacc[nt][3] = __expf(sacc[nt][3] - mn1);
            sum0 += sacc[nt][0] + sacc[nt][1];
            sum1 += sacc[nt][2] + sacc[nt][3];
        }
        sum0 += __shfl_xor_sync(0xffffffffu, sum0, 1);
        sum0 += __shfl_xor_sync(0xffffffffu, sum0, 2);
        sum1 += __shfl_xor_sync(0xffffffffu, sum1, 1);
        sum1 += __shfl_xor_sync(0xffffffffu, sum1, 2);
        l0r = l0r * cor0 + sum0; m0r = mn0;
        l1r = l1r * cor1 + sum1; m1r = mn1;
        #pragma unroll
        for (int dt = 0; dt < 8; dt++) {
            oacc[dt][0] *= cor0; oacc[dt][1] *= cor0;
            oacc[dt][2] *= cor1; oacc[dt][3] *= cor1;
        }
        #pragma unroll
        for (int j = 0; j < 4; j++) {
            uint32_t pf[4];
            pf[0] = pack_h2(sacc[2*j][0],   sacc[2*j][1]);
            pf[1] = pack_h2(sacc[2*j][2],   sacc[2*j][3]);
            pf[2] = pack_h2(sacc[2*j+1][0], sacc[2*j+1][1]);
            pf[3] = pack_h2(sacc[2*j+1][2], sacc[2*j+1][3]);
            #pragma unroll
            for (int dp = 0; dp < 4; dp++) {
                uint32_t vb4[4];
                ldsm4(vb4, uV + (uint32_t)((dp * 16 + b_rr) * FP + 16*j + b_cb) * 2);
                mma16816(oacc[2*dp],   pf, &vb4[0]);
                mma16816(oacc[2*dp+1], pf, &vb4[2]);
            }
        }
    }

    float inv0 = 1.0f / l0r, inv1 = 1.0f / l1r;
    size_t ob0 = (size_t)b * TT * DD + (size_t)(q0 + wid * 16 + g) * DD + h * HDIM;
    size_t ob1 = ob0 + 8 * DD;
    #pragma unroll
    for (int dt = 0; dt < 8; dt++) {
        *(uint32_t*)(o16 + ob0 + dt*8 + t2) = pack_h2(oacc[dt][0] * inv0, oacc[dt][1] * inv0);
        *(uint32_t*)(o16 + ob1 + dt*8 + t2) = pack_h2(oacc[dt][2] * inv1, oacc[dt][3] * inv1);
    }
}

// ---------------- engram hash + gather -> fp16 ----------------
__global__ void gather_k(const int* __restrict__ ids, const float* __restrict__ tables,
                         const int* __restrict__ hm, fp16* __restrict__ o16) {
    int tok = blockIdx.x;
    int t = tok & (TT - 1);
    int id0 = ids[tok];
    int id1 = (t >= 1) ? ids[tok - 1] : 0;
    int id2 = (t >= 2) ? ids[tok - 2] : 0;
    unsigned m0 = (unsigned)hm[0], m1 = (unsigned)hm[1], m2 = (unsigned)hm[2];
    unsigned h2 = (unsigned)id0 * m0 ^ (unsigned)id1 * m1;
    unsigned h3 = h2 ^ (unsigned)id2 * m2;
    int tid = threadIdx.x;
    size_t ob = (size_t)tok * 1024;
    #pragma unroll
    for (int r = 0; r < 4; r++) {
        int e = tid + r * 256;
        int tt = e >> 6, ee = e & 63;
        int head = tt & 7;
        unsigned hh = ((tt < 8) ? h2 : h3) + (unsigned)(head * 7919);
        int sv = (int)hh;
        int idx = sv % NGV;
        if (idx < 0) idx += NGV;
        o16[ob + e] = __float2half_rn(tables[((size_t)tt * NGV + idx) * 64 + ee]);
    }
}

// ---------------- gate ----------------
__global__ void gate_k(const float* __restrict__ hn, const float* __restrict__ kvb,
                       const float* __restrict__ nkw, const float* __restrict__ nqw,
                       float* __restrict__ value) {
    int row = blockIdx.x, tid = threadIdx.x;
    const float* keye = kvb + (size_t)row * 2048;
    const float* vale = keye + 1024;
    float4 kv = ((const float4*)keye)[tid];
    float4 hv = ((const float4*)(hn + (size_t)row * DD))[tid];
    float4 wk = ((const float4*)nkw)[tid];
    float4 wq = ((const float4*)nqw)[tid];
    float skk = kv.x*kv.x + kv.y*kv.y + kv.z*kv.z + kv.w*kv.w;
    float shh = hv.x*hv.x + hv.y*hv.y + hv.z*hv.z + hv.w*hv.w;
    float sdt = kv.x*wk.x*hv.x*wq.x + kv.y*wk.y*hv.y*wq.y
              + kv.z*wk.z*hv.z*wq.z + kv.w*wk.w*hv.w*wq.w;
    #pragma unroll
    for (int o = 16; o; o >>= 1) {
        skk += __shfl_xor_sync(0xffffffffu, skk, o);
        shh += __shfl_xor_sync(0xffffffffu, shh, o);
        sdt += __shfl_xor_sync(0xffffffffu, sdt, o);
    }
    __shared__ float r1[8], r2[8], r3[8];
    if ((tid & 31) == 0) { r1[tid>>5] = skk; r2[tid>>5] = shh; r3[tid>>5] = sdt; }
    __syncthreads();
    float tkk = 0, thh = 0, tdt = 0;
    #pragma unroll
    for (int i = 0; i < 8; i++) { tkk += r1[i]; thh += r2[i]; tdt += r3[i]; }
    float nk = rsqrtf(tkk * (1.0f / DD) + 1e-6f);
    float nh = rsqrtf(thh * (1.0f / DD) + 1e-6f);
    float gg = tdt * nk * nh * (1.0f / 32.0f);
    float ab = fabsf(gg);
    float rt = sqrtf(fmaxf(ab, 1e-6f));
    float sgn = (gg > 0.f) ? 1.f : ((gg < 0.f) ? -1.f : 0.f);
    float sig = 1.f / (1.f + expf(-rt * sgn));
    float4 vv = ((const float4*)vale)[tid];
    float4 r = make_float4(sig*vv.x, sig*vv.y, sig*vv.z, sig*vv.w);
    ((float4*)(value + (size_t)row * DD))[tid] = r;
}

// ---------------- final ----------------
__global__ void final_k(const float* __restrict__ value, const float* __restrict__ cw,
                        float* __restrict__ out) {
    int idx = blockIdx.x * 256 + threadIdx.x;
    int d = idx & (DD - 1);
    int bt = idx >> 10;
    int t = bt & (TT - 1);
    float c = 0.f;
    #pragma unroll
    for (int kk = 0; kk < 4; kk++) {
        int tt = t - 3 + kk;
        if (tt >= 0)
            c += value[(size_t)(bt - 3 + kk) * DD + d] * cw[d * 4 + kk];
    }
    float vv = value[idx];
    float sc = c / (1.f + expf(-c));
    out[idx] += vv + sc;
}

// ================= host =================
typedef CUresult (*PFN_encode)(CUtensorMap*, CUtensorMapDataType, cuuint32_t, void*,
                               const cuuint64_t*, const cuuint64_t*, const cuuint32_t*,
                               const cuuint32_t*, CUtensorMapInterleave, CUtensorMapSwizzle,
                               CUtensorMapL2promotion, CUtensorMapFloatOOBfill);
static PFN_encode get_encoder() {
    static PFN_encode fn = nullptr;
    if (!fn) {
        void* p = nullptr;
        cudaDriverEntryPointQueryResult qr;
        cudaGetDriverEntryPoint("cuTensorMapEncodeTiled", &p, cudaEnableDefault, &qr);
        fn = (PFN_encode)p;
    }
    return fn;
}
static void make_map(CUtensorMap* m, void* ptr, uint64_t Kdim, uint64_t Rows) {
    cuuint64_t dims[2] = {Kdim, Rows};
    cuuint64_t strides[1] = {Kdim * 2};
    cuuint32_t box[2] = {32, 128};
    cuuint32_t es[2] = {1, 1};
    get_encoder()(m, CU_TENSOR_MAP_DATA_TYPE_FLOAT16, 2, ptr, dims, strides, box, es,
                  CU_TENSOR_MAP_INTERLEAVE_NONE, CU_TENSOR_MAP_SWIZZLE_64B,
                  CU_TENSOR_MAP_L2_PROMOTION_L2_128B, CU_TENSOR_MAP_FLOAT_OOB_FILL_NONE);
}
static float* symaddr(const void* sym) {
    void* p = nullptr;
    cudaGetSymbolAddress(&p, sym);
    return (float*)p;
}

template<int MODE>
static void run_gemm(fp16* a, fp16* bh, fp16* bl,
                     float* C, const float* addC, const float* bias, const float* bias2,
                     fp16* outp, int M, int N, int K) {
    CUtensorMap ma, mbh, mbl;
    make_map(&ma, a, K, M);
    make_map(&mbh, bh, K, N);
    make_map(&mbl, bl, K, N);
    dim3 grid(N / 128, M / 128);
    gemm_tma<MODE><<<grid, 256, GEMM_SMEM>>>(ma, mbh, mbl, C, addC, bias, bias2, outp, M, N, K);
}

extern "C" void kernel_launch(void* const* d_in, const int* in_sizes, int n_in,
                              void* d_out, int out_size) {
    const float* x     = (const float*)d_in[0];
    const int*   ids   = (const int*)d_in[1];
    const float* wq    = (const float*)d_in[3];
    const float* wk    = (const float*)d_in[4];
    const float* wv    = (const float*)d_in[5];
    const float* wo    = (const float*)d_in[6];
    const float* attnw = (const float*)d_in[7];
    const float* ffnw  = (const float*)d_in[8];
    const float* gatew = (const float*)d_in[9];
    const float* upw   = (const float*)d_in[10];
    const float* downw = (const float*)d_in[11];
    const float* embt  = (const float*)d_in[12];
    const float* keyw  = (const float*)d_in[13];
    const float* keyb  = (const float*)d_in[14];
    const float* valw  = (const float*)d_in[15];
    const float* valb  = (const float*)d_in[16];
    const float* normk = (const float*)d_in[17];
    const float* normq = (const float*)d_in[18];
    const float* convw = (const float*)d_in[19];
    const int*   hm    = (const int*)d_in[20];

    float* p_h   = symaddr(g_h);
    float* p_hn  = symaddr(g_hn);
    float* p_val = symaddr(g_value);
    float* p_kv  = symaddr(g_kv);
    fp16* p_a  = (fp16*)symaddr(g_a);
    fp16* p_s  = (fp16*)symaddr(g_s);
    fp16* p_e  = (fp16*)symaddr(g_e);
    fp16* p_q3 = (fp16*)symaddr(g_q3);
    fp16* p_bh = (fp16*)symaddr(g_bh);
    fp16* p_bl = (fp16*)symaddr(g_bl);
    float* out = (float*)d_out;

    static bool attrs_set = false;
    if (!attrs_set) {
        cudaFuncSetAttribute(gemm_tma<0>, cudaFuncAttributeMaxDynamicSharedMemorySize, GEMM_SMEM);
        cudaFuncSetAttribute(gemm_tma<1>, cudaFuncAttributeMaxDynamicSharedMemorySize, GEMM_SMEM);
        cudaFuncSetAttribute(gemm_tma<2>, cudaFuncAttributeMaxDynamicSharedMemorySize, GEMM_SMEM);
        cudaFuncSetAttribute(flash_mma, cudaFuncAttributeMaxDynamicSharedMemorySize, FLASH_SMEM);
        attrs_set = true;
    }

    dim3 blk(256);

    // 0: weight split
    split_weights<<<(6*D2 + 3*F2 + 255) / 256, blk>>>(wq, wk, wv, wo, gatew, upw, downw,
                                                      keyw, valw, p_bh, p_bl);
    // 1: engram gather
    gather_k<<<BT, blk>>>(ids, embt, hm, p_e);
    // 2: attn rmsnorm
    rmsnorm_k<<<BT, blk>>>(x, attnw, nullptr, p_a);
    // 3: fused QKV gemm + rope
    run_gemm<1>(p_a, p_bh + WOFF_QKV, p_bl + WOFF_QKV,
                nullptr, nullptr, nullptr, nullptr, p_q3, BT, 3072, DD);
    // 4: flash attention
    flash_mma<<<dim3(TT / 64, BB * NHEAD), 128, FLASH_SMEM>>>(p_q3, p_a);
    // 5: O projection + residual
    run_gemm<0>(p_a, p_bh + WOFF_WO, p_bl + WOFF_WO,
                p_h, x, nullptr, nullptr, nullptr, BT, DD, DD);
    // 6: ffn rmsnorm
    rmsnorm_k<<<BT, blk>>>(p_h, ffnw, p_hn, p_a);
    // 7: fused gate/up gemm + silu
    run_gemm<2>(p_a, p_bh + WOFF_GU, p_bl + WOFF_GU,
                nullptr, nullptr, nullptr, nullptr, p_s, BT, 2 * FFN, DD);
    // 8: down projection + residual -> out
    run_gemm<0>(p_s, p_bh + WOFF_DOWN, p_bl + WOFF_DOWN,
                out, p_h, nullptr, nullptr, nullptr, BT, DD, FFN);
    // 9: key/val gemm (dual bias)
    run_gemm<0>(p_e, p_bh + WOFF_KV, p_bl + WOFF_KV,
                p_kv, nullptr, keyb, valb, nullptr, BT, 2048, DD);
    // 10: gate
    gate_k<<<BT, blk>>>(p_hn, p_kv, normk, normq, p_val);
    // 11: conv + silu + residual
    final_k<<<(BT * DD) / 256, blk>>>(p_val, convw, out);
}

// round 7
// speedup vs baseline: 7.0045x; 1.4728x over previous
#include <cuda_runtime.h>
#include <cuda_fp16.h>
#include <cuda.h>
#include <math.h>
#include <stdint.h>

#define BB 2
#define TT 2048
#define DD 1024
#define NHEAD 16
#define HDIM 64
#define FFN 4096
#define BT (BB*TT)
#define NGV 50000

typedef __half fp16;

// ---------------- scratch (device globals; no allocation) ----------------
__device__ float g_h[BT*DD];
__device__ float g_hn[BT*DD];
__device__ float g_value[BT*DD];
__device__ float g_kv[(size_t)BT*2048];
__device__ __align__(1024) fp16 g_a[BT*DD];            // activations: xn, O, hn
__device__ __align__(1024) fp16 g_s[(size_t)BT*FFN];   // silu output
__device__ __align__(1024) fp16 g_e[BT*DD];            // engram emb
__device__ __align__(1024) fp16 g_q3[(size_t)BT*3072]; // rope'd qkv
// weights fp16: [qkv 3M][wo 1M][gate/up interleaved 8M][down 4M][key 1M][val 1M]
#define WOFF_QKV 0
#define WOFF_WO   (3u*1024*1024)
#define WOFF_GU   (4u*1024*1024)
#define WOFF_DOWN (12u*1024*1024)
#define WOFF_KV   (16u*1024*1024)
__device__ __align__(1024) fp16 g_b[18u*1024*1024];

extern __shared__ char dynsmem[];

// ================= low-level helpers =================
__device__ __forceinline__ uint32_t smem_u32(const void* p) {
    uint32_t a;
    asm("{ .reg .u64 t; cvta.to.shared.u64 t, %1; cvt.u32.u64 %0, t; }" : "=r"(a) : "l"(p));
    return a;
}
__device__ __forceinline__ uint32_t swz64(uint32_t o) { return o ^ ((o >> 3) & 0x30); }

#define MBAR_INIT(addr, cnt) \
    asm volatile("mbarrier.init.shared.b64 [%0], %1;" :: "r"((uint32_t)(addr)), "r"((uint32_t)(cnt)) : "memory")
#define MBAR_EXPECT_TX(addr, bytes) \
    asm volatile("mbarrier.arrive.expect_tx.shared.b64 _, [%0], %1;" :: "r"((uint32_t)(addr)), "r"((uint32_t)(bytes)) : "memory")
#define MBAR_WAIT(addr, parity) do { \
    uint32_t _m = (uint32_t)(addr); uint32_t _p = (uint32_t)(parity); uint32_t _d; \
    asm volatile("{\n\t.reg .pred p;\n\t" \
        "mbarrier.try_wait.parity.acquire.cta.shared::cta.b64 p, [%1], %2;\n\t" \
        "selp.b32 %0, 1, 0, p;\n\t}" : "=r"(_d) : "r"(_m), "r"(_p) : "memory"); \
    if (!_d) { \
        asm volatile("{\n\t.reg .pred P1;\n\t" \
            "WL_%=:\n\t" \
            "mbarrier.try_wait.parity.acquire.cta.shared::cta.b64 P1, [%0], %1, 0x989680;\n\t" \
            "@P1 bra.uni WD_%=;\n\t" \
            "bra.uni WL_%=;\n\t" \
            "WD_%=:\n\t}" :: "r"(_m), "r"(_p) : "memory"); \
    } \
} while (0)

#define TMA_LOAD2D(smem_addr, map_ptr, cx, cy, mbar) \
    asm volatile("cp.async.bulk.tensor.2d.shared::cta.global.tile.mbarrier::complete_tx::bytes " \
        "[%0], [%1, {%2, %3}], [%4];" \
        :: "r"((uint32_t)(smem_addr)), "l"(map_ptr), "r"((int)(cx)), "r"((int)(cy)), \
           "r"((uint32_t)(mbar)) : "memory")

__device__ __forceinline__ void ldsm4(uint32_t* r, uint32_t addr) {
    asm volatile("ldmatrix.sync.aligned.m8n8.x4.shared.b16 {%0,%1,%2,%3}, [%4];"
        : "=r"(r[0]), "=r"(r[1]), "=r"(r[2]), "=r"(r[3]) : "r"(addr));
}
__device__ __forceinline__ void mma16816(float* d, const uint32_t* a, const uint32_t* b) {
    asm volatile("mma.sync.aligned.m16n8k16.row.col.f32.f16.f16.f32 "
        "{%0,%1,%2,%3}, {%4,%5,%6,%7}, {%8,%9}, {%0,%1,%2,%3};"
        : "+f"(d[0]), "+f"(d[1]), "+f"(d[2]), "+f"(d[3])
        : "r"(a[0]), "r"(a[1]), "r"(a[2]), "r"(a[3]), "r"(b[0]), "r"(b[1]));
}
__device__ __forceinline__ uint32_t pack_h2(float x, float y) {
    __half2 h = __floats2half2_rn(x, y);
    return *(uint32_t*)&h;
}

// ================= TMA + mma.sync fp16 GEMM ====================
// C[M,N] = A[M,K]*B[N,K]^T, all fp16 operands, fp32 accum.
// CTA 128x128, BK=32, 5 stages x 16KB, occ 2.
// MODE 0: fp32 C (+addC) (+dual bias split at N/2)
// MODE 1: QKV -> rope (cols<2048) -> fp16
// MODE 2: gate/up interleaved -> silu(g)*u -> fp16, stride N/2
#define NSTG 5
#define TIL 8192
#define STG_B (2*TIL)
#define GEMM_SMEM (1024 + NSTG*STG_B)

template<int MODE>
__global__ void __launch_bounds__(256, 2) gemm_tma(
    const __grid_constant__ CUtensorMap ma,
    const __grid_constant__ CUtensorMap mb,
    float* __restrict__ C, const float* __restrict__ addC,
    const float* __restrict__ bias, const float* __restrict__ bias2,
    fp16* __restrict__ outp, int M, int N, int K)
{
    const uint32_t sb = smem_u32(dynsmem);
    const uint32_t fullb = sb;
    const uint32_t stg0 = sb + 1024;
    const int tid = threadIdx.x;
    const int wid = tid >> 5, lane = tid & 31;
    const int wm = wid & 3, wn = wid >> 2;
    const int m0 = blockIdx.y * 128, n0 = blockIdx.x * 128;
    const int NT = K >> 5;

    if (tid == 0) {
        #pragma unroll
        for (int s = 0; s < NSTG; s++) MBAR_INIT(fullb + 8*s, 1);
    }
    __syncthreads();
    if (tid == 0) {
        #pragma unroll
        for (int s = 0; s < 4; s++) {
            uint32_t st = stg0 + s * STG_B;
            MBAR_EXPECT_TX(fullb + 8*s, STG_B);
            TMA_LOAD2D(st,       &ma, s*32, m0, fullb + 8*s);
            TMA_LOAD2D(st + TIL, &mb, s*32, n0, fullb + 8*s);
        }
    }

    float acc[2][8][4];
    #pragma unroll
    for (int i = 0; i < 2; i++)
        #pragma unroll
        for (int j = 0; j < 8; j++)
            #pragma unroll
            for (int q = 0; q < 4; q++) acc[i][j][q] = 0.f;

    const int a_row0 = wm * 32 + (lane & 15);
    const int acbyte = (lane >> 4) * 16;
    const int b_rr = ((lane & 16) >> 1) + (lane & 7);
    const int bcbyte = (lane & 8) * 2;

    for (int kt = 0; kt < NT; kt++) {
        int s = kt % NSTG;
        MBAR_WAIT(fullb + 8*s, (kt / NSTG) & 1);
        uint32_t st = stg0 + s * STG_B;
        #pragma unroll
        for (int k16 = 0; k16 < 2; k16++) {
            const int kofb = k16 * 32;
            uint32_t a0[4], a1[4];
            uint32_t oa0 = swz64((uint32_t)(a_row0 * 64 + acbyte + kofb));
            uint32_t oa1 = swz64((uint32_t)((a_row0 + 16) * 64 + acbyte + kofb));
            ldsm4(a0, st + oa0);
            ldsm4(a1, st + oa1);
            #pragma unroll
            for (int p = 0; p < 4; p++) {
                uint32_t ob = swz64((uint32_t)((wn * 64 + p * 16 + b_rr) * 64 + bcbyte + kofb));
                uint32_t bf[4];
                ldsm4(bf, st + TIL + ob);
                mma16816(acc[0][2*p],   a0, bf);
                mma16816(acc[0][2*p+1], a0, bf + 2);
                mma16816(acc[1][2*p],   a1, bf);
                mma16816(acc[1][2*p+1], a1, bf + 2);
            }
        }
        __syncthreads();
        if (tid == 0 && kt + 4 < NT) {
            int s2 = (kt + 4) % NSTG;
            uint32_t st2 = stg0 + s2 * STG_B;
            MBAR_EXPECT_TX(fullb + 8*s2, STG_B);
            TMA_LOAD2D(st2,       &ma, (kt+4)*32, m0, fullb + 8*s2);
            TMA_LOAD2D(st2 + TIL, &mb, (kt+4)*32, n0, fullb + 8*s2);
        }
    }

    const int g = lane >> 2, t2 = (lane & 3) * 2;
    const int base_c = n0 + wn * 64;

    if (MODE == 0) {
        #pragma unroll
        for (int mt = 0; mt < 2; mt++)
            #pragma unroll
            for (int nt = 0; nt < 8; nt++) {
                int grow = m0 + wm * 32 + mt * 16 + g;
                int gcol = base_c + nt * 8 + t2;
                float2 v0 = make_float2(acc[mt][nt][0], acc[mt][nt][1]);
                float2 v1 = make_float2(acc[mt][nt][2], acc[mt][nt][3]);
                if (bias) {
                    const float* bp = (gcol < (N >> 1)) ? bias + gcol : bias2 + gcol - (N >> 1);
                    float2 bv = *(const float2*)bp;
                    v0.x += bv.x; v0.y += bv.y; v1.x += bv.x; v1.y += bv.y;
                }
                if (addC) {
                    float2 d0 = *(const float2*)(addC + (size_t)grow * N + gcol);
                    float2 d1 = *(const float2*)(addC + (size_t)(grow + 8) * N + gcol);
                    v0.x += d0.x; v0.y += d0.y; v1.x += d1.x; v1.y += d1.y;
                }
                *(float2*)(C + (size_t)grow * N + gcol) = v0;
                *(float2*)(C + (size_t)(grow + 8) * N + gcol) = v1;
            }
    } else if (MODE == 1) {
        #pragma unroll
        for (int mt = 0; mt < 2; mt++)
            #pragma unroll
            for (int rr = 0; rr < 2; rr++) {
                int row = m0 + wm * 32 + mt * 16 + g + rr * 8;
                float ft = (float)(row & (TT - 1));
                size_t rb = (size_t)row * N;
                if (base_c < 2048) {  // q or k: rope
                    #pragma unroll
                    for (int nt = 0; nt < 4; nt++) {
                        int cc = base_c + nt * 8 + t2;
                        int d0 = cc & 63;
                        float inv0 = expf(-(float)(2*d0)     * (1.0f/64.0f) * 9.2103403719761836f);
                        float inv1 = expf(-(float)(2*(d0+1)) * (1.0f/64.0f) * 9.2103403719761836f);
                        float s0, c0, s1, c1;
                        sincosf(ft * inv0, &s0, &c0);
                        sincosf(ft * inv1, &s1, &c1);
                        float vl0 = acc[mt][nt][rr*2],   vl1 = acc[mt][nt][rr*2+1];
                        float vh0 = acc[mt][nt+4][rr*2], vh1 = acc[mt][nt+4][rr*2+1];
                        float ol0 = vl0 * c0 - vh0 * s0, oh0 = vh0 * c0 + vl0 * s0;
                        float ol1 = vl1 * c1 - vh1 * s1, oh1 = vh1 * c1 + vl1 * s1;
                        *(uint32_t*)(outp + rb + cc)      = pack_h2(ol0, ol1);
                        *(uint32_t*)(outp + rb + cc + 32) = pack_h2(oh0, oh1);
                    }
                } else {  // v: plain
                    #pragma unroll
                    for (int nt = 0; nt < 8; nt++) {
                        int cc = base_c + nt * 8 + t2;
                        *(uint32_t*)(outp + rb + cc) =
                            pack_h2(acc[mt][nt][rr*2], acc[mt][nt][rr*2+1]);
                    }
                }
            }
    } else {  // MODE 2: silu(gate)*up, interleaved cols
        const int NO = N >> 1;
        #pragma unroll
        for (int mt = 0; mt < 2; mt++)
            #pragma unroll
            for (int rr = 0; rr < 2; rr++) {
                int row = m0 + wm * 32 + mt * 16 + g + rr * 8;
                size_t rb = (size_t)row * NO;
                #pragma unroll
                for (int nt = 0; nt < 8; nt++) {
                    float gg = acc[mt][nt][rr*2];
                    float uu = acc[mt][nt][rr*2+1];
                    float sv = gg / (1.f + expf(-gg)) * uu;
                    int j = (base_c + nt * 8 + t2) >> 1;
                    outp[rb + j] = __float2half_rn(sv);
                }
            }
    }
}

// ---------------- all-weights convert to fp16 (gate/up interleaved) ------
#define D2 262144u
#define F2 1048576u
__global__ void split_weights(
    const float* __restrict__ wq, const float* __restrict__ wk,
    const float* __restrict__ wv, const float* __restrict__ wo,
    const float* __restrict__ gw, const float* __restrict__ uw,
    const float* __restrict__ dw, const float* __restrict__ kw,
    const float* __restrict__ vw, fp16* __restrict__ bh)
{
    uint32_t i = blockIdx.x * 256 + threadIdx.x;
    const float* src;
    uint32_t oo;
    if (i < 3*D2) {
        src = (i < D2) ? wq + 4*(size_t)i : (i < 2*D2) ? wk + 4*(size_t)(i - D2) : wv + 4*(size_t)(i - 2*D2);
        oo = i;
    } else if (i < 4*D2) {
        src = wo + 4*(size_t)(i - 3*D2);
        oo = i;
    } else if (i < 4*D2 + F2) {
        uint32_t loc = i - 4*D2;
        uint32_t r = loc >> 8, c = loc & 255;
        src = gw + 4*(size_t)loc;
        oo = 4*D2 + (2*r) * 256 + c;
    } else if (i < 4*D2 + 2*F2) {
        uint32_t loc = i - 4*D2 - F2;
        uint32_t r = loc >> 8, c = loc & 255;
        src = uw + 4*(size_t)loc;
        oo = 4*D2 + (2*r + 1) * 256 + c;
    } else if (i < 4*D2 + 3*F2) {
        src = dw + 4*(size_t)(i - 4*D2 - 2*F2);
        oo = i;
    } else if (i < 5*D2 + 3*F2) {
        src = kw + 4*(size_t)(i - 4*D2 - 3*F2);
        oo = i;
    } else if (i < 6*D2 + 3*F2) {
        src = vw + 4*(size_t)(i - 5*D2 - 3*F2);
        oo = i;
    } else return;
    float4 v = *(const float4*)src;
    ((uint32_t*)bh)[(size_t)oo*2]   = pack_h2(v.x, v.y);
    ((uint32_t*)bh)[(size_t)oo*2+1] = pack_h2(v.z, v.w);
}

// ---------------- RMSNorm (optional fp32 out + fp16 out) ----------------
__global__ void rmsnorm_k(const float* __restrict__ x, const float* __restrict__ w,
                          float* __restrict__ y, fp16* __restrict__ o16) {
    int row = blockIdx.x, tid = threadIdx.x;
    float4 xv = ((const float4*)(x + (size_t)row * DD))[tid];
    float ss = xv.x*xv.x + xv.y*xv.y + xv.z*xv.z + xv.w*xv.w;
    #pragma unroll
    for (int o = 16; o; o >>= 1) ss += __shfl_xor_sync(0xffffffffu, ss, o);
    __shared__ float red[8];
    if ((tid & 31) == 0) red[tid >> 5] = ss;
    __syncthreads();
    float tot = 0.f;
    #pragma unroll
    for (int i = 0; i < 8; i++) tot += red[i];
    float inv = rsqrtf(tot * (1.0f / DD) + 1e-6f);
    float4 wv = ((const float4*)w)[tid];
    float4 r;
    r.x = xv.x * inv * wv.x; r.y = xv.y * inv * wv.y;
    r.z = xv.z * inv * wv.z; r.w = xv.w * inv * wv.w;
    if (y) ((float4*)(y + (size_t)row * DD))[tid] = r;
    size_t base = (size_t)row * DD;
    ((uint32_t*)(o16 + base))[2*tid]   = pack_h2(r.x, r.y);
    ((uint32_t*)(o16 + base))[2*tid+1] = pack_h2(r.z, r.w);
}

// ---------------- Flash attention: fp16 fragments -------
#define FP 72
#define FTE (64*FP)
#define FLASH_SMEM (3*FTE*2)

__global__ void __launch_bounds__(128) flash_mma(
    const fp16* __restrict__ qkv, fp16* __restrict__ o16)
{
    fp16* Qs = (fp16*)dynsmem;
    fp16* Ks = Qs + FTE;
    fp16* Vs = Ks + FTE;   // transposed [d][token]
    const uint32_t uQ = smem_u32(Qs), uK = smem_u32(Ks), uV = smem_u32(Vs);

    const int qt = blockIdx.x, bh = blockIdx.y;
    const int b = bh >> 4, h = bh & 15;
    const int q0 = qt * 64;
    const int tid = threadIdx.x;
    const int wid = tid >> 5, lane = tid & 31;
    const int g = lane >> 2, t2 = (lane & 3) * 2;

    const fp16* qb = qkv + ((size_t)(b * TT + q0)) * 3072 + h * 64;
    for (int i = tid; i < 512; i += 128) {
        int m = i >> 3, c8 = (i & 7) * 8;
        *(uint4*)&Qs[m * FP + c8] = *(const uint4*)(qb + (size_t)m * 3072 + c8);
    }

    float m0r = -1e30f, m1r = -1e30f, l0r = 0.f, l1r = 0.f;
    float oacc[8][4];
    #pragma unroll
    for (int i = 0; i < 8; i++)
        #pragma unroll
        for (int j = 0; j < 4; j++) oacc[i][j] = 0.f;

    const int a_rb = (wid * 16 + (lane & 15)) * FP;
    const int a_cb = ((lane >> 4) << 3);
    const int b_rr = ((lane & 16) >> 1) + (lane & 7);
    const int b_cb = (lane & 8);

    for (int kt = 0; kt <= qt; kt++) {
        __syncthreads();
        {
            const fp16* kb = qkv + ((size_t)(b * TT + kt * 64)) * 3072 + 1024 + h * 64;
            const fp16* vb = qkv + ((size_t)(b * TT + kt * 64)) * 3072 + 2048 + h * 64;
            for (int i = tid; i < 512; i += 128) {
                int n = i >> 3, c8 = (i & 7) * 8;
                *(uint4*)&Ks[n * FP + c8] = *(const uint4*)(kb + (size_t)n * 3072 + c8);
                uint4 rv = *(const uint4*)(vb + (size_t)n * 3072 + c8);
                const fp16* ev = (const fp16*)&rv;
                #pragma unroll
                for (int j = 0; j < 8; j++) Vs[(c8 + j) * FP + n] = ev[j];
            }
        }
        __syncthreads();

        float sacc[8][4];
        #pragma unroll
        for (int i = 0; i < 8; i++)
            #pragma unroll
            for (int j = 0; j < 4; j++) sacc[i][j] = 0.f;
        #pragma unroll
        for (int k16 = 0; k16 < 4; k16++) {
            const int kof = k16 * 16;
            uint32_t af[4];
            ldsm4(af, uQ + (uint32_t)(a_rb + kof + a_cb) * 2);
            uint32_t bf[4][4];
            #pragma unroll
            for (int p = 0; p < 4; p++)
                ldsm4(bf[p], uK + (uint32_t)((p * 16 + b_rr) * FP + kof + b_cb) * 2);
            #pragma unroll
            for (int nt = 0; nt < 8; nt++)
                mma16816(sacc[nt], af, &bf[nt >> 1][(nt & 1) * 2]);
        }

        const int qrow0 = q0 + wid * 16 + g;
        const int qrow1 = qrow0 + 8;
        #pragma unroll
        for (int nt = 0; nt < 8; nt++) {
            int c0 = kt * 64 + nt * 8 + t2;
            float v0 = sacc[nt][0] * 0.125f;
            float v1 = sacc[nt][1] * 0.125f;
            float v2 = sacc[nt][2] * 0.125f;
            float v3 = sacc[nt][3] * 0.125f;
            if (c0 > qrow0) v0 = -1e30f;
            if (c0 + 1 > qrow0) v1 = -1e30f;
            if (c0 > qrow1) v2 = -1e30f;
            if (c0 + 1 > qrow1) v3 = -1e30f;
            sacc[nt][0] = v0; sacc[nt][1] = v1; sacc[nt][2] = v2; sacc[nt][3] = v3;
        }
        float rm0 = -1e30f, rm1 = -1e30f;
        #pragma unroll
        for (int nt = 0; nt < 8; nt++) {
            rm0 = fmaxf(rm0, fmaxf(sacc[nt][0], sacc[nt][1]));
            rm1 = fmaxf(rm1, fmaxf(sacc[nt][2], sacc[nt][3]));
        }
        rm0 = fmaxf(rm0, __shfl_xor_sync(0xffffffffu, rm0, 1));
        rm0 = fmaxf(rm0, __shfl_xor_sync(0xffffffffu, rm0, 2));
        rm1 = fmaxf(rm1, __shfl_xor_sync(0xffffffffu, rm1, 1));
        rm1 = fmaxf(rm1, __shfl_xor_sync(0xffffffffu, rm1, 2));
        float mn0 = fmaxf(m0r, rm0), mn1 = fmaxf(m1r, rm1);
        float cor0 = __expf(m0r - mn0), cor1 = __expf(m1r - mn1);
        float sum0 = 0.f, sum1 = 0.f;
        #pragma unroll
        for (int nt = 0; nt < 8; nt++) {
            sacc[nt][0] = __expf(sacc[nt][0] - mn0);
            sacc[nt][1] = __expf(sacc[nt][1] - mn0);
            sacc[nt][2] = __expf(sacc[nt][2] - mn1);
            sacc[nt][3] = __expf(sacc[nt][3] - mn1);
            sum0 += sacc[nt][0] + sacc[nt][1];
            sum1 += sacc[nt][2] + sacc[nt][3];
        }
        sum0 += __shfl_xor_sync(0xffffffffu, sum0, 1);
        sum0 += __shfl_xor_sync(0xffffffffu, sum0, 2);
        sum1 += __shfl_xor_sync(0xffffffffu, sum1, 1);
        sum1 += __shfl_xor_sync(0xffffffffu, sum1, 2);
        l0r = l0r * cor0 + sum0; m0r = mn0;
        l1r = l1r * cor1 + sum1; m1r = mn1;
        #pragma unroll
        for (int dt = 0; dt < 8; dt++) {
            oacc[dt][0] *= cor0; oacc[dt][1] *= cor0;
            oacc[dt][2] *= cor1; oacc[dt][3] *= cor1;
        }
        #pragma unroll
        for (int j = 0; j < 4; j++) {
            uint32_t pf[4];
            pf[0] = pack_h2(sacc[2*j][0],   sacc[2*j][1]);
            pf[1] = pack_h2(sacc[2*j][2],   sacc[2*j][3]);
            pf[2] = pack_h2(sacc[2*j+1][0], sacc[2*j+1][1]);
            pf[3] = pack_h2(sacc[2*j+1][2], sacc[2*j+1][3]);
            #pragma unroll
            for (int dp = 0; dp < 4; dp++) {
                uint32_t vb4[4];
                ldsm4(vb4, uV + (uint32_t)((dp * 16 + b_rr) * FP + 16*j + b_cb) * 2);
                mma16816(oacc[2*dp],   pf, &vb4[0]);
                mma16816(oacc[2*dp+1], pf, &vb4[2]);
            }
        }
    }

    float inv0 = 1.0f / l0r, inv1 = 1.0f / l1r;
    size_t ob0 = (size_t)b * TT * DD + (size_t)(q0 + wid * 16 + g) * DD + h * HDIM;
    size_t ob1 = ob0 + 8 * DD;
    #pragma unroll
    for (int dt = 0; dt < 8; dt++) {
        *(uint32_t*)(o16 + ob0 + dt*8 + t2) = pack_h2(oacc[dt][0] * inv0, oacc[dt][1] * inv0);
        *(uint32_t*)(o16 + ob1 + dt*8 + t2) = pack_h2(oacc[dt][2] * inv1, oacc[dt][3] * inv1);
    }
}

// ---------------- engram hash + gather -> fp16 ----------------
__global__ void gather_k(const int* __restrict__ ids, const float* __restrict__ tables,
                         const int* __restrict__ hm, fp16* __restrict__ o16) {
    int tok = blockIdx.x;
    int t = tok & (TT - 1);
    int id0 = ids[tok];
    int id1 = (t >= 1) ? ids[tok - 1] : 0;
    int id2 = (t >= 2) ? ids[tok - 2] : 0;
    unsigned m0 = (unsigned)hm[0], m1 = (unsigned)hm[1], m2 = (unsigned)hm[2];
    unsigned h2 = (unsigned)id0 * m0 ^ (unsigned)id1 * m1;
    unsigned h3 = h2 ^ (unsigned)id2 * m2;
    int tid = threadIdx.x;
    size_t ob = (size_t)tok * 1024;
    #pragma unroll
    for (int r = 0; r < 4; r++) {
        int e = tid + r * 256;
        int tt = e >> 6, ee = e & 63;
        int head = tt & 7;
        unsigned hh = ((tt < 8) ? h2 : h3) + (unsigned)(head * 7919);
        int sv = (int)hh;
        int idx = sv % NGV;
        if (idx < 0) idx += NGV;
        o16[ob + e] = __float2half_rn(tables[((size_t)tt * NGV + idx) * 64 + ee]);
    }
}

// ---------------- gate ----------------
__global__ void gate_k(const float* __restrict__ hn, const float* __restrict__ kvb,
                       const float* __restrict__ nkw, const float* __restrict__ nqw,
                       float* __restrict__ value) {
    int row = blockIdx.x, tid = threadIdx.x;
    const float* keye = kvb + (size_t)row * 2048;
    const float* vale = keye + 1024;
    float4 kv = ((const float4*)keye)[tid];
    float4 hv = ((const float4*)(hn + (size_t)row * DD))[tid];
    float4 wk = ((const float4*)nkw)[tid];
    float4 wq = ((const float4*)nqw)[tid];
    float skk = kv.x*kv.x + kv.y*kv.y + kv.z*kv.z + kv.w*kv.w;
    float shh = hv.x*hv.x + hv.y*hv.y + hv.z*hv.z + hv.w*hv.w;
    float sdt = kv.x*wk.x*hv.x*wq.x + kv.y*wk.y*hv.y*wq.y
              + kv.z*wk.z*hv.z*wq.z + kv.w*wk.w*hv.w*wq.w;
    #pragma unroll
    for (int o = 16; o; o >>= 1) {
        skk += __shfl_xor_sync(0xffffffffu, skk, o);
        shh += __shfl_xor_sync(0xffffffffu, shh, o);
        sdt += __shfl_xor_sync(0xffffffffu, sdt, o);
    }
    __shared__ float r1[8], r2[8], r3[8];
    if ((tid & 31) == 0) { r1[tid>>5] = skk; r2[tid>>5] = shh; r3[tid>>5] = sdt; }
    __syncthreads();
    float tkk = 0, thh = 0, tdt = 0;
    #pragma unroll
    for (int i = 0; i < 8; i++) { tkk += r1[i]; thh += r2[i]; tdt += r3[i]; }
    float nk = rsqrtf(tkk * (1.0f / DD) + 1e-6f);
    float nh = rsqrtf(thh * (1.0f / DD) + 1e-6f);
    float gg = tdt * nk * nh * (1.0f / 32.0f);
    float ab = fabsf(gg);
    float rt = sqrtf(fmaxf(ab, 1e-6f));
    float sgn = (gg > 0.f) ? 1.f : ((gg < 0.f) ? -1.f : 0.f);
    float sig = 1.f / (1.f + expf(-rt * sgn));
    float4 vv = ((const float4*)vale)[tid];
    float4 r = make_float4(sig*vv.x, sig*vv.y, sig*vv.z, sig*vv.w);
    ((float4*)(value + (size_t)row * DD))[tid] = r;
}

// ---------------- final ----------------
__global__ void final_k(const float* __restrict__ value, const float* __restrict__ cw,
                        float* __restrict__ out) {
    int idx = blockIdx.x * 256 + threadIdx.x;
    int d = idx & (DD - 1);
    int bt = idx >> 10;
    int t = bt & (TT - 1);
    float c = 0.f;
    #pragma unroll
    for (int kk = 0; kk < 4; kk++) {
        int tt = t - 3 + kk;
        if (tt >= 0)
            c += value[(size_t)(bt - 3 + kk) * DD + d] * cw[d * 4 + kk];
    }
    float vv = value[idx];
    float sc = c / (1.f + expf(-c));
    out[idx] += vv + sc;
}

// ================= host =================
typedef CUresult (*PFN_encode)(CUtensorMap*, CUtensorMapDataType, cuuint32_t, void*,
                               const cuuint64_t*, const cuuint64_t*, const cuuint32_t*,
                               const cuuint32_t*, CUtensorMapInterleave, CUtensorMapSwizzle,
                               CUtensorMapL2promotion, CUtensorMapFloatOOBfill);
static PFN_encode get_encoder() {
    static PFN_encode fn = nullptr;
    if (!fn) {
        void* p = nullptr;
        cudaDriverEntryPointQueryResult qr;
        cudaGetDriverEntryPoint("cuTensorMapEncodeTiled", &p, cudaEnableDefault, &qr);
        fn = (PFN_encode)p;
    }
    return fn;
}
static void make_map(CUtensorMap* m, void* ptr, uint64_t Kdim, uint64_t Rows) {
    cuuint64_t dims[2] = {Kdim, Rows};
    cuuint64_t strides[1] = {Kdim * 2};
    cuuint32_t box[2] = {32, 128};
    cuuint32_t es[2] = {1, 1};
    get_encoder()(m, CU_TENSOR_MAP_DATA_TYPE_FLOAT16, 2, ptr, dims, strides, box, es,
                  CU_TENSOR_MAP_INTERLEAVE_NONE, CU_TENSOR_MAP_SWIZZLE_64B,
                  CU_TENSOR_MAP_L2_PROMOTION_L2_128B, CU_TENSOR_MAP_FLOAT_OOB_FILL_NONE);
}
static float* symaddr(const void* sym) {
    void* p = nullptr;
    cudaGetSymbolAddress(&p, sym);
    return (float*)p;
}

template<int MODE>
static void run_gemm(fp16* a, fp16* b,
                     float* C, const float* addC, const float* bias, const float* bias2,
                     fp16* outp, int M, int N, int K) {
    CUtensorMap ma, mb;
    make_map(&ma, a, K, M);
    make_map(&mb, b, K, N);
    dim3 grid(N / 128, M / 128);
    gemm_tma<MODE><<<grid, 256, GEMM_SMEM>>>(ma, mb, C, addC, bias, bias2, outp, M, N, K);
}

extern "C" void kernel_launch(void* const* d_in, const int* in_sizes, int n_in,
                              void* d_out, int out_size) {
    const float* x     = (const float*)d_in[0];
    const int*   ids   = (const int*)d_in[1];
    const float* wq    = (const float*)d_in[3];
    const float* wk    = (const float*)d_in[4];
    const float* wv    = (const float*)d_in[5];
    const float* wo    = (const float*)d_in[6];
    const float* attnw = (const float*)d_in[7];
    const float* ffnw  = (const float*)d_in[8];
    const float* gatew = (const float*)d_in[9];
    const float* upw   = (const float*)d_in[10];
    const float* downw = (const float*)d_in[11];
    const float* embt  = (const float*)d_in[12];
    const float* keyw  = (const float*)d_in[13];
    const float* keyb  = (const float*)d_in[14];
    const float* valw  = (const float*)d_in[15];
    const float* valb  = (const float*)d_in[16];
    const float* normk = (const float*)d_in[17];
    const float* normq = (const float*)d_in[18];
    const float* convw = (const float*)d_in[19];
    const int*   hm    = (const int*)d_in[20];

    float* p_h   = symaddr(g_h);
    float* p_hn  = symaddr(g_hn);
    float* p_val = symaddr(g_value);
    float* p_kv  = symaddr(g_kv);
    fp16* p_a  = (fp16*)symaddr(g_a);
    fp16* p_s  = (fp16*)symaddr(g_s);
    fp16* p_e  = (fp16*)symaddr(g_e);
    fp16* p_q3 = (fp16*)symaddr(g_q3);
    fp16* p_b  = (fp16*)symaddr(g_b);
    float* out = (float*)d_out;

    static bool attrs_set = false;
    if (!attrs_set) {
        cudaFuncSetAttribute(gemm_tma<0>, cudaFuncAttributeMaxDynamicSharedMemorySize, GEMM_SMEM);
        cudaFuncSetAttribute(gemm_tma<1>, cudaFuncAttributeMaxDynamicSharedMemorySize, GEMM_SMEM);
        cudaFuncSetAttribute(gemm_tma<2>, cudaFuncAttributeMaxDynamicSharedMemorySize, GEMM_SMEM);
        cudaFuncSetAttribute(flash_mma, cudaFuncAttributeMaxDynamicSharedMemorySize, FLASH_SMEM);
        attrs_set = true;
    }

    dim3 blk(256);

    // 0: weight convert
    split_weights<<<(6*D2 + 3*F2 + 255) / 256, blk>>>(wq, wk, wv, wo, gatew, upw, downw,
                                                      keyw, valw, p_b);
    // 1: engram gather
    gather_k<<<BT, blk>>>(ids, embt, hm, p_e);
    // 2: attn rmsnorm
    rmsnorm_k<<<BT, blk>>>(x, attnw, nullptr, p_a);
    // 3: fused QKV gemm + rope
    run_gemm<1>(p_a, p_b + WOFF_QKV, nullptr, nullptr, nullptr, nullptr, p_q3, BT, 3072, DD);
    // 4: flash attention
    flash_mma<<<dim3(TT / 64, BB * NHEAD), 128, FLASH_SMEM>>>(p_q3, p_a);
    // 5: O projection + residual
    run_gemm<0>(p_a, p_b + WOFF_WO, p_h, x, nullptr, nullptr, nullptr, BT, DD, DD);
    // 6: ffn rmsnorm
    rmsnorm_k<<<BT, blk>>>(p_h, ffnw, p_hn, p_a);
    // 7: fused gate/up gemm + silu
    run_gemm<2>(p_a, p_b + WOFF_GU, nullptr, nullptr, nullptr, nullptr, p_s, BT, 2 * FFN, DD);
    // 8: down projection + residual -> out
    run_gemm<0>(p_s, p_b + WOFF_DOWN, out, p_h, nullptr, nullptr, nullptr, BT, DD, FFN);
    // 9: key/val gemm (dual bias)
    run_gemm<0>(p_e, p_b + WOFF_KV, p_kv, nullptr, keyb, valb, nullptr, BT, 2048, DD);
    // 10: gate
    gate_k<<<BT, blk>>>(p_hn, p_kv, normk, normq, p_val);
    // 11: conv + silu + residual
    final_k<<<(BT * DD) / 256, blk>>>(p_val, convw, out);
}

// round 8
// speedup vs baseline: 7.5667x; 1.0803x over previous
#include <cuda_runtime.h>
#include <cuda_fp16.h>
#include <cuda.h>
#include <math.h>
#include <stdint.h>

#define BB 2
#define TT 2048
#define DD 1024
#define NHEAD 16
#define HDIM 64
#define FFN 4096
#define BT (BB*TT)
#define NGV 50000

typedef __half fp16;

// ---------------- scratch (device globals; no allocation) ----------------
__device__ float g_h[BT*DD];
__device__ float g_hn[BT*DD];
__device__ float g_value[BT*DD];
__device__ float g_kv[(size_t)BT*2048];
__device__ __align__(1024) fp16 g_a[BT*DD];            // activations: xn, O, hn
__device__ __align__(1024) fp16 g_s[(size_t)BT*FFN];   // silu output
__device__ __align__(1024) fp16 g_e[BT*DD];            // engram emb
__device__ __align__(1024) fp16 g_q3[(size_t)BT*3072]; // rope'd qkv
// weights fp16: [qkv 3M][wo 1M][gate/up interleaved 8M][down 4M][key 1M][val 1M]
#define WOFF_QKV 0
#define WOFF_WO   (3u*1024*1024)
#define WOFF_GU   (4u*1024*1024)
#define WOFF_DOWN (12u*1024*1024)
#define WOFF_KV   (16u*1024*1024)
__device__ __align__(1024) fp16 g_b[18u*1024*1024];

extern __shared__ char dynsmem[];

// ================= low-level helpers =================
__device__ __forceinline__ uint32_t smem_u32(const void* p) {
    uint32_t a;
    asm("{ .reg .u64 t; cvta.to.shared.u64 t, %1; cvt.u32.u64 %0, t; }" : "=r"(a) : "l"(p));
    return a;
}
__device__ __forceinline__ uint32_t swz128(uint32_t o) { return o ^ ((o >> 3) & 0x70); }

#define MBAR_INIT(addr, cnt) \
    asm volatile("mbarrier.init.shared.b64 [%0], %1;" :: "r"((uint32_t)(addr)), "r"((uint32_t)(cnt)) : "memory")
#define MBAR_EXPECT_TX(addr, bytes) \
    asm volatile("mbarrier.arrive.expect_tx.shared.b64 _, [%0], %1;" :: "r"((uint32_t)(addr)), "r"((uint32_t)(bytes)) : "memory")
#define MBAR_WAIT(addr, parity) do { \
    uint32_t _m = (uint32_t)(addr); uint32_t _p = (uint32_t)(parity); uint32_t _d; \
    asm volatile("{\n\t.reg .pred p;\n\t" \
        "mbarrier.try_wait.parity.acquire.cta.shared::cta.b64 p, [%1], %2;\n\t" \
        "selp.b32 %0, 1, 0, p;\n\t}" : "=r"(_d) : "r"(_m), "r"(_p) : "memory"); \
    if (!_d) { \
        asm volatile("{\n\t.reg .pred P1;\n\t" \
            "WL_%=:\n\t" \
            "mbarrier.try_wait.parity.acquire.cta.shared::cta.b64 P1, [%0], %1, 0x989680;\n\t" \
            "@P1 bra.uni WD_%=;\n\t" \
            "bra.uni WL_%=;\n\t" \
            "WD_%=:\n\t}" :: "r"(_m), "r"(_p) : "memory"); \
    } \
} while (0)

#define TMA_LOAD2D(smem_addr, map_ptr, cx, cy, mbar) \
    asm volatile("cp.async.bulk.tensor.2d.shared::cta.global.tile.mbarrier::complete_tx::bytes " \
        "[%0], [%1, {%2, %3}], [%4];" \
        :: "r"((uint32_t)(smem_addr)), "l"(map_ptr), "r"((int)(cx)), "r"((int)(cy)), \
           "r"((uint32_t)(mbar)) : "memory")

__device__ __forceinline__ void ldsm4(uint32_t* r, uint32_t addr) {
    asm volatile("ldmatrix.sync.aligned.m8n8.x4.shared.b16 {%0,%1,%2,%3}, [%4];"
        : "=r"(r[0]), "=r"(r[1]), "=r"(r[2]), "=r"(r[3]) : "r"(addr));
}
__device__ __forceinline__ void mma16816(float* d, const uint32_t* a, const uint32_t* b) {
    asm volatile("mma.sync.aligned.m16n8k16.row.col.f32.f16.f16.f32 "
        "{%0,%1,%2,%3}, {%4,%5,%6,%7}, {%8,%9}, {%0,%1,%2,%3};"
        : "+f"(d[0]), "+f"(d[1]), "+f"(d[2]), "+f"(d[3])
        : "r"(a[0]), "r"(a[1]), "r"(a[2]), "r"(a[3]), "r"(b[0]), "r"(b[1]));
}
__device__ __forceinline__ uint32_t pack_h2(float x, float y) {
    __half2 h = __floats2half2_rn(x, y);
    return *(uint32_t*)&h;
}

// ================= TMA + mma.sync fp16 GEMM ====================
// C[M,N] = A[M,K]*B[N,K]^T, fp16 operands, fp32 accum.
// CTA 128x128, BK=64 (SW128, 128B rows), 3 stages x 32KB, occ 2.
// MODE 0: fp32 C (+addC) (+dual bias split at N/2)
// MODE 1: QKV -> rope (cols<2048) -> fp16
// MODE 2: gate/up interleaved -> silu(g)*u -> fp16, stride N/2
#define NSTG 3
#define TIL 16384
#define STG_B (2*TIL)
#define GEMM_SMEM (1024 + NSTG*STG_B)

template<int MODE>
__global__ void __launch_bounds__(256, 2) gemm_tma(
    const __grid_constant__ CUtensorMap ma,
    const __grid_constant__ CUtensorMap mb,
    float* __restrict__ C, const float* __restrict__ addC,
    const float* __restrict__ bias, const float* __restrict__ bias2,
    fp16* __restrict__ outp, int M, int N, int K)
{
    const uint32_t sb = smem_u32(dynsmem);
    const uint32_t fullb = sb;
    const uint32_t stg0 = sb + 1024;
    const int tid = threadIdx.x;
    const int wid = tid >> 5, lane = tid & 31;
    const int wm = wid & 3, wn = wid >> 2;
    const int m0 = blockIdx.y * 128, n0 = blockIdx.x * 128;
    const int NT = K >> 6;

    if (tid == 0) {
        #pragma unroll
        for (int s = 0; s < NSTG; s++) MBAR_INIT(fullb + 8*s, 1);
    }
    __syncthreads();
    if (tid == 0) {
        #pragma unroll
        for (int s = 0; s < 2; s++) {
            uint32_t st = stg0 + s * STG_B;
            MBAR_EXPECT_TX(fullb + 8*s, STG_B);
            TMA_LOAD2D(st,       &ma, s*64, m0, fullb + 8*s);
            TMA_LOAD2D(st + TIL, &mb, s*64, n0, fullb + 8*s);
        }
    }

    float acc[2][8][4];
    #pragma unroll
    for (int i = 0; i < 2; i++)
        #pragma unroll
        for (int j = 0; j < 8; j++)
            #pragma unroll
            for (int q = 0; q < 4; q++) acc[i][j][q] = 0.f;

    const int a_row0 = wm * 32 + (lane & 15);
    const int acbyte = (lane >> 4) * 16;
    const int b_rr = ((lane & 16) >> 1) + (lane & 7);
    const int bcbyte = (lane & 8) * 2;

    for (int kt = 0; kt < NT; kt++) {
        int s = kt % NSTG;
        MBAR_WAIT(fullb + 8*s, (kt / NSTG) & 1);
        uint32_t st = stg0 + s * STG_B;
        #pragma unroll
        for (int k16 = 0; k16 < 4; k16++) {
            const int kofb = k16 * 32;
            uint32_t a0[4], a1[4];
            uint32_t oa0 = swz128((uint32_t)(a_row0 * 128 + acbyte + kofb));
            uint32_t oa1 = swz128((uint32_t)((a_row0 + 16) * 128 + acbyte + kofb));
            ldsm4(a0, st + oa0);
            ldsm4(a1, st + oa1);
            #pragma unroll
            for (int p = 0; p < 4; p++) {
                uint32_t ob = swz128((uint32_t)((wn * 64 + p * 16 + b_rr) * 128 + bcbyte + kofb));
                uint32_t bf[4];
                ldsm4(bf, st + TIL + ob);
                mma16816(acc[0][2*p],   a0, bf);
                mma16816(acc[0][2*p+1], a0, bf + 2);
                mma16816(acc[1][2*p],   a1, bf);
                mma16816(acc[1][2*p+1], a1, bf + 2);
            }
        }
        __syncthreads();
        if (tid == 0 && kt + 2 < NT) {
            int s2 = (kt + 2) % NSTG;
            uint32_t st2 = stg0 + s2 * STG_B;
            MBAR_EXPECT_TX(fullb + 8*s2, STG_B);
            TMA_LOAD2D(st2,       &ma, (kt+2)*64, m0, fullb + 8*s2);
            TMA_LOAD2D(st2 + TIL, &mb, (kt+2)*64, n0, fullb + 8*s2);
        }
    }

    const int g = lane >> 2, t2 = (lane & 3) * 2;
    const int base_c = n0 + wn * 64;

    if (MODE == 0) {
        #pragma unroll
        for (int mt = 0; mt < 2; mt++)
            #pragma unroll
            for (int nt = 0; nt < 8; nt++) {
                int grow = m0 + wm * 32 + mt * 16 + g;
                int gcol = base_c + nt * 8 + t2;
                float2 v0 = make_float2(acc[mt][nt][0], acc[mt][nt][1]);
                float2 v1 = make_float2(acc[mt][nt][2], acc[mt][nt][3]);
                if (bias) {
                    const float* bp = (gcol < (N >> 1)) ? bias + gcol : bias2 + gcol - (N >> 1);
                    float2 bv = *(const float2*)bp;
                    v0.x += bv.x; v0.y += bv.y; v1.x += bv.x; v1.y += bv.y;
                }
                if (addC) {
                    float2 d0 = *(const float2*)(addC + (size_t)grow * N + gcol);
                    float2 d1 = *(const float2*)(addC + (size_t)(grow + 8) * N + gcol);
                    v0.x += d0.x; v0.y += d0.y; v1.x += d1.x; v1.y += d1.y;
                }
                *(float2*)(C + (size_t)grow * N + gcol) = v0;
                *(float2*)(C + (size_t)(grow + 8) * N + gcol) = v1;
            }
    } else if (MODE == 1) {
        #pragma unroll
        for (int mt = 0; mt < 2; mt++)
            #pragma unroll
            for (int rr = 0; rr < 2; rr++) {
                int row = m0 + wm * 32 + mt * 16 + g + rr * 8;
                float ft = (float)(row & (TT - 1));
                size_t rb = (size_t)row * N;
                if (base_c < 2048) {  // q or k: rope
                    #pragma unroll
                    for (int nt = 0; nt < 4; nt++) {
                        int cc = base_c + nt * 8 + t2;
                        int d0 = cc & 63;
                        float inv0 = expf(-(float)(2*d0)     * (1.0f/64.0f) * 9.2103403719761836f);
                        float inv1 = expf(-(float)(2*(d0+1)) * (1.0f/64.0f) * 9.2103403719761836f);
                        float s0, c0, s1, c1;
                        sincosf(ft * inv0, &s0, &c0);
                        sincosf(ft * inv1, &s1, &c1);
                        float vl0 = acc[mt][nt][rr*2],   vl1 = acc[mt][nt][rr*2+1];
                        float vh0 = acc[mt][nt+4][rr*2], vh1 = acc[mt][nt+4][rr*2+1];
                        float ol0 = vl0 * c0 - vh0 * s0, oh0 = vh0 * c0 + vl0 * s0;
                        float ol1 = vl1 * c1 - vh1 * s1, oh1 = vh1 * c1 + vl1 * s1;
                        *(uint32_t*)(outp + rb + cc)      = pack_h2(ol0, ol1);
                        *(uint32_t*)(outp + rb + cc + 32) = pack_h2(oh0, oh1);
                    }
                } else {  // v: plain
                    #pragma unroll
                    for (int nt = 0; nt < 8; nt++) {
                        int cc = base_c + nt * 8 + t2;
                        *(uint32_t*)(outp + rb + cc) =
                            pack_h2(acc[mt][nt][rr*2], acc[mt][nt][rr*2+1]);
                    }
                }
            }
    } else {  // MODE 2: silu(gate)*up, interleaved cols
        const int NO = N >> 1;
        #pragma unroll
        for (int mt = 0; mt < 2; mt++)
            #pragma unroll
            for (int rr = 0; rr < 2; rr++) {
                int row = m0 + wm * 32 + mt * 16 + g + rr * 8;
                size_t rb = (size_t)row * NO;
                #pragma unroll
                for (int nt = 0; nt < 8; nt++) {
                    float gg = acc[mt][nt][rr*2];
                    float uu = acc[mt][nt][rr*2+1];
                    float sv = gg / (1.f + expf(-gg)) * uu;
                    int j = (base_c + nt * 8 + t2) >> 1;
                    outp[rb + j] = __float2half_rn(sv);
                }
            }
    }
}

// ---------------- all-weights convert to fp16 (gate/up interleaved) ------
#define D2 262144u
#define F2 1048576u
__global__ void split_weights(
    const float* __restrict__ wq, const float* __restrict__ wk,
    const float* __restrict__ wv, const float* __restrict__ wo,
    const float* __restrict__ gw, const float* __restrict__ uw,
    const float* __restrict__ dw, const float* __restrict__ kw,
    const float* __restrict__ vw, fp16* __restrict__ bh)
{
    uint32_t i = blockIdx.x * 256 + threadIdx.x;
    const float* src;
    uint32_t oo;
    if (i < 3*D2) {
        src = (i < D2) ? wq + 4*(size_t)i : (i < 2*D2) ? wk + 4*(size_t)(i - D2) : wv + 4*(size_t)(i - 2*D2);
        oo = i;
    } else if (i < 4*D2) {
        src = wo + 4*(size_t)(i - 3*D2);
        oo = i;
    } else if (i < 4*D2 + F2) {
        uint32_t loc = i - 4*D2;
        uint32_t r = loc >> 8, c = loc & 255;
        src = gw + 4*(size_t)loc;
        oo = 4*D2 + (2*r) * 256 + c;
    } else if (i < 4*D2 + 2*F2) {
        uint32_t loc = i - 4*D2 - F2;
        uint32_t r = loc >> 8, c = loc & 255;
        src = uw + 4*(size_t)loc;
        oo = 4*D2 + (2*r + 1) * 256 + c;
    } else if (i < 4*D2 + 3*F2) {
        src = dw + 4*(size_t)(i - 4*D2 - 2*F2);
        oo = i;
    } else if (i < 5*D2 + 3*F2) {
        src = kw + 4*(size_t)(i - 4*D2 - 3*F2);
        oo = i;
    } else if (i < 6*D2 + 3*F2) {
        src = vw + 4*(size_t)(i - 5*D2 - 3*F2);
        oo = i;
    } else return;
    float4 v = *(const float4*)src;
    ((uint32_t*)bh)[(size_t)oo*2]   = pack_h2(v.x, v.y);
    ((uint32_t*)bh)[(size_t)oo*2+1] = pack_h2(v.z, v.w);
}

// ---------------- RMSNorm (optional fp32 out + fp16 out) ----------------
__global__ void rmsnorm_k(const float* __restrict__ x, const float* __restrict__ w,
                          float* __restrict__ y, fp16* __restrict__ o16) {
    int row = blockIdx.x, tid = threadIdx.x;
    float4 xv = ((const float4*)(x + (size_t)row * DD))[tid];
    float ss = xv.x*xv.x + xv.y*xv.y + xv.z*xv.z + xv.w*xv.w;
    #pragma unroll
    for (int o = 16; o; o >>= 1) ss += __shfl_xor_sync(0xffffffffu, ss, o);
    __shared__ float red[8];
    if ((tid & 31) == 0) red[tid >> 5] = ss;
    __syncthreads();
    float tot = 0.f;
    #pragma unroll
    for (int i = 0; i < 8; i++) tot += red[i];
    float inv = rsqrtf(tot * (1.0f / DD) + 1e-6f);
    float4 wv = ((const float4*)w)[tid];
    float4 r;
    r.x = xv.x * inv * wv.x; r.y = xv.y * inv * wv.y;
    r.z = xv.z * inv * wv.z; r.w = xv.w * inv * wv.w;
    if (y) ((float4*)(y + (size_t)row * DD))[tid] = r;
    size_t base = (size_t)row * DD;
    ((uint32_t*)(o16 + base))[2*tid]   = pack_h2(r.x, r.y);
    ((uint32_t*)(o16 + base))[2*tid+1] = pack_h2(r.z, r.w);
}

// ---------------- Flash attention: fp16 fragments -------
#define FP 72
#define FTE (64*FP)
#define FLASH_SMEM (3*FTE*2)

__global__ void __launch_bounds__(128) flash_mma(
    const fp16* __restrict__ qkv, fp16* __restrict__ o16)
{
    fp16* Qs = (fp16*)dynsmem;
    fp16* Ks = Qs + FTE;
    fp16* Vs = Ks + FTE;   // transposed [d][token]
    const uint32_t uQ = smem_u32(Qs), uK = smem_u32(Ks), uV = smem_u32(Vs);

    const int qt = blockIdx.x, bh = blockIdx.y;
    const int b = bh >> 4, h = bh & 15;
    const int q0 = qt * 64;
    const int tid = threadIdx.x;
    const int wid = tid >> 5, lane = tid & 31;
    const int g = lane >> 2, t2 = (lane & 3) * 2;

    const fp16* qb = qkv + ((size_t)(b * TT + q0)) * 3072 + h * 64;
    for (int i = tid; i < 512; i += 128) {
        int m = i >> 3, c8 = (i & 7) * 8;
        *(uint4*)&Qs[m * FP + c8] = *(const uint4*)(qb + (size_t)m * 3072 + c8);
    }

    float m0r = -1e30f, m1r = -1e30f, l0r = 0.f, l1r = 0.f;
    float oacc[8][4];
    #pragma unroll
    for (int i = 0; i < 8; i++)
        #pragma unroll
        for (int j = 0; j < 4; j++) oacc[i][j] = 0.f;

    const int a_rb = (wid * 16 + (lane & 15)) * FP;
    const int a_cb = ((lane >> 4) << 3);
    const int b_rr = ((lane & 16) >> 1) + (lane & 7);
    const int b_cb = (lane & 8);

    for (int kt = 0; kt <= qt; kt++) {
        __syncthreads();
        {
            const fp16* kb = qkv + ((size_t)(b * TT + kt * 64)) * 3072 + 1024 + h * 64;
            const fp16* vb = qkv + ((size_t)(b * TT + kt * 64)) * 3072 + 2048 + h * 64;
            for (int i = tid; i < 512; i += 128) {
                int n = i >> 3, c8 = (i & 7) * 8;
                *(uint4*)&Ks[n * FP + c8] = *(const uint4*)(kb + (size_t)n * 3072 + c8);
                uint4 rv = *(const uint4*)(vb + (size_t)n * 3072 + c8);
                const fp16* ev = (const fp16*)&rv;
                #pragma unroll
                for (int j = 0; j < 8; j++) Vs[(c8 + j) * FP + n] = ev[j];
            }
        }
        __syncthreads();

        float sacc[8][4];
        #pragma unroll
        for (int i = 0; i < 8; i++)
            #pragma unroll
            for (int j = 0; j < 4; j++) sacc[i][j] = 0.f;
        #pragma unroll
        for (int k16 = 0; k16 < 4; k16++) {
            const int kof = k16 * 16;
            uint32_t af[4];
            ldsm4(af, uQ + (uint32_t)(a_rb + kof + a_cb) * 2);
            uint32_t bf[4][4];
            #pragma unroll
            for (int p = 0; p < 4; p++)
                ldsm4(bf[p], uK + (uint32_t)((p * 16 + b_rr) * FP + kof + b_cb) * 2);
            #pragma unroll
            for (int nt = 0; nt < 8; nt++)
                mma16816(sacc[nt], af, &bf[nt >> 1][(nt & 1) * 2]);
        }

        const int qrow0 = q0 + wid * 16 + g;
        const int qrow1 = qrow0 + 8;
        #pragma unroll
        for (int nt = 0; nt < 8; nt++) {
            int c0 = kt * 64 + nt * 8 + t2;
            float v0 = sacc[nt][0] * 0.125f;
            float v1 = sacc[nt][1] * 0.125f;
            float v2 = sacc[nt][2] * 0.125f;
            float v3 = sacc[nt][3] * 0.125f;
            if (c0 > qrow0) v0 = -1e30f;
            if (c0 + 1 > qrow0) v1 = -1e30f;
            if (c0 > qrow1) v2 = -1e30f;
            if (c0 + 1 > qrow1) v3 = -1e30f;
            sacc[nt][0] = v0; sacc[nt][1] = v1; sacc[nt][2] = v2; sacc[nt][3] = v3;
        }
        float rm0 = -1e30f, rm1 = -1e30f;
        #pragma unroll
        for (int nt = 0; nt < 8; nt++) {
            rm0 = fmaxf(rm0, fmaxf(sacc[nt][0], sacc[nt][1]));
            rm1 = fmaxf(rm1, fmaxf(sacc[nt][2], sacc[nt][3]));
        }
        rm0 = fmaxf(rm0, __shfl_xor_sync(0xffffffffu, rm0, 1));
        rm0 = fmaxf(rm0, __shfl_xor_sync(0xffffffffu, rm0, 2));
        rm1 = fmaxf(rm1, __shfl_xor_sync(0xffffffffu, rm1, 1));
        rm1 = fmaxf(rm1, __shfl_xor_sync(0xffffffffu, rm1, 2));
        float mn0 = fmaxf(m0r, rm0), mn1 = fmaxf(m1r, rm1);
        float cor0 = __expf(m0r - mn0), cor1 = __expf(m1r - mn1);
        float sum0 = 0.f, sum1 = 0.f;
        #pragma unroll
        for (int nt = 0; nt < 8; nt++) {
            sacc[nt][0] = __expf(sacc[nt][0] - mn0);
            sacc[nt][1] = __expf(sacc[nt][1] - mn0);
            sacc[nt][2] = __expf(sacc[nt][2] - mn1);
            sacc[nt][3] = __expf(sacc[nt][3] - mn1);
            sum0 += sacc[nt][0] + sacc[nt][1];
            sum1 += sacc[nt][2] + sacc[nt][3];
        }
        sum0 += __shfl_xor_sync(0xffffffffu, sum0, 1);
        sum0 += __shfl_xor_sync(0xffffffffu, sum0, 2);
        sum1 += __shfl_xor_sync(0xffffffffu, sum1, 1);
        sum1 += __shfl_xor_sync(0xffffffffu, sum1, 2);
        l0r = l0r * cor0 + sum0; m0r = mn0;
        l1r = l1r * cor1 + sum1; m1r = mn1;
        #pragma unroll
        for (int dt = 0; dt < 8; dt++) {
            oacc[dt][0] *= cor0; oacc[dt][1] *= cor0;
            oacc[dt][2] *= cor1; oacc[dt][3] *= cor1;
        }
        #pragma unroll
        for (int j = 0; j < 4; j++) {
            uint32_t pf[4];
            pf[0] = pack_h2(sacc[2*j][0],   sacc[2*j][1]);
            pf[1] = pack_h2(sacc[2*j][2],   sacc[2*j][3]);
            pf[2] = pack_h2(sacc[2*j+1][0], sacc[2*j+1][1]);
            pf[3] = pack_h2(sacc[2*j+1][2], sacc[2*j+1][3]);
            #pragma unroll
            for (int dp = 0; dp < 4; dp++) {
                uint32_t vb4[4];
                ldsm4(vb4, uV + (uint32_t)((dp * 16 + b_rr) * FP + 16*j + b_cb) * 2);
                mma16816(oacc[2*dp],   pf, &vb4[0]);
                mma16816(oacc[2*dp+1], pf, &vb4[2]);
            }
        }
    }

    float inv0 = 1.0f / l0r, inv1 = 1.0f / l1r;
    size_t ob0 = (size_t)b * TT * DD + (size_t)(q0 + wid * 16 + g) * DD + h * HDIM;
    size_t ob1 = ob0 + 8 * DD;
    #pragma unroll
    for (int dt = 0; dt < 8; dt++) {
        *(uint32_t*)(o16 + ob0 + dt*8 + t2) = pack_h2(oacc[dt][0] * inv0, oacc[dt][1] * inv0);
        *(uint32_t*)(o16 + ob1 + dt*8 + t2) = pack_h2(oacc[dt][2] * inv1, oacc[dt][3] * inv1);
    }
}

// ---------------- engram hash + gather -> fp16 ----------------
__global__ void gather_k(const int* __restrict__ ids, const float* __restrict__ tables,
                         const int* __restrict__ hm, fp16* __restrict__ o16) {
    int tok = blockIdx.x;
    int t = tok & (TT - 1);
    int id0 = ids[tok];
    int id1 = (t >= 1) ? ids[tok - 1] : 0;
    int id2 = (t >= 2) ? ids[tok - 2] : 0;
    unsigned m0 = (unsigned)hm[0], m1 = (unsigned)hm[1], m2 = (unsigned)hm[2];
    unsigned h2 = (unsigned)id0 * m0 ^ (unsigned)id1 * m1;
    unsigned h3 = h2 ^ (unsigned)id2 * m2;
    int tid = threadIdx.x;
    size_t ob = (size_t)tok * 1024;
    #pragma unroll
    for (int r = 0; r < 4; r++) {
        int e = tid + r * 256;
        int tt = e >> 6, ee = e & 63;
        int head = tt & 7;
        unsigned hh = ((tt < 8) ? h2 : h3) + (unsigned)(head * 7919);
        int sv = (int)hh;
        int idx = sv % NGV;
        if (idx < 0) idx += NGV;
        o16[ob + e] = __float2half_rn(tables[((size_t)tt * NGV + idx) * 64 + ee]);
    }
}

// ---------------- gate ----------------
__global__ void gate_k(const float* __restrict__ hn, const float* __restrict__ kvb,
                       const float* __restrict__ nkw, const float* __restrict__ nqw,
                       float* __restrict__ value) {
    int row = blockIdx.x, tid = threadIdx.x;
    const float* keye = kvb + (size_t)row * 2048;
    const float* vale = keye + 1024;
    float4 kv = ((const float4*)keye)[tid];
    float4 hv = ((const float4*)(hn + (size_t)row * DD))[tid];
    float4 wk = ((const float4*)nkw)[tid];
    float4 wq = ((const float4*)nqw)[tid];
    float skk = kv.x*kv.x + kv.y*kv.y + kv.z*kv.z + kv.w*kv.w;
    float shh = hv.x*hv.x + hv.y*hv.y + hv.z*hv.z + hv.w*hv.w;
    float sdt = kv.x*wk.x*hv.x*wq.x + kv.y*wk.y*hv.y*wq.y
              + kv.z*wk.z*hv.z*wq.z + kv.w*wk.w*hv.w*wq.w;
    #pragma unroll
    for (int o = 16; o; o >>= 1) {
        skk += __shfl_xor_sync(0xffffffffu, skk, o);
        shh += __shfl_xor_sync(0xffffffffu, shh, o);
        sdt += __shfl_xor_sync(0xffffffffu, sdt, o);
    }
    __shared__ float r1[8], r2[8], r3[8];
    if ((tid & 31) == 0) { r1[tid>>5] = skk; r2[tid>>5] = shh; r3[tid>>5] = sdt; }
    __syncthreads();
    float tkk = 0, thh = 0, tdt = 0;
    #pragma unroll
    for (int i = 0; i < 8; i++) { tkk += r1[i]; thh += r2[i]; tdt += r3[i]; }
    float nk = rsqrtf(tkk * (1.0f / DD) + 1e-6f);
    float nh = rsqrtf(thh * (1.0f / DD) + 1e-6f);
    float gg = tdt * nk * nh * (1.0f / 32.0f);
    float ab = fabsf(gg);
    float rt = sqrtf(fmaxf(ab, 1e-6f));
    float sgn = (gg > 0.f) ? 1.f : ((gg < 0.f) ? -1.f : 0.f);
    float sig = 1.f / (1.f + expf(-rt * sgn));
    float4 vv = ((const float4*)vale)[tid];
    float4 r = make_float4(sig*vv.x, sig*vv.y, sig*vv.z, sig*vv.w);
    ((float4*)(value + (size_t)row * DD))[tid] = r;
}

// ---------------- final ----------------
__global__ void final_k(const float* __restrict__ value, const float* __restrict__ cw,
                        float* __restrict__ out) {
    int idx = blockIdx.x * 256 + threadIdx.x;
    int d = idx & (DD - 1);
    int bt = idx >> 10;
    int t = bt & (TT - 1);
    float c = 0.f;
    #pragma unroll
    for (int kk = 0; kk < 4; kk++) {
        int tt = t - 3 + kk;
        if (tt >= 0)
            c += value[(size_t)(bt - 3 + kk) * DD + d] * cw[d * 4 + kk];
    }
    float vv = value[idx];
    float sc = c / (1.f + expf(-c));
    out[idx] += vv + sc;
}

// ================= host =================
typedef CUresult (*PFN_encode)(CUtensorMap*, CUtensorMapDataType, cuuint32_t, void*,
                               const cuuint64_t*, const cuuint64_t*, const cuuint32_t*,
                               const cuuint32_t*, CUtensorMapInterleave, CUtensorMapSwizzle,
                               CUtensorMapL2promotion, CUtensorMapFloatOOBfill);
static PFN_encode get_encoder() {
    static PFN_encode fn = nullptr;
    if (!fn) {
        void* p = nullptr;
        cudaDriverEntryPointQueryResult qr;
        cudaGetDriverEntryPoint("cuTensorMapEncodeTiled", &p, cudaEnableDefault, &qr);
        fn = (PFN_encode)p;
    }
    return fn;
}
static void make_map(CUtensorMap* m, void* ptr, uint64_t Kdim, uint64_t Rows) {
    cuuint64_t dims[2] = {Kdim, Rows};
    cuuint64_t strides[1] = {Kdim * 2};
    cuuint32_t box[2] = {64, 128};
    cuuint32_t es[2] = {1, 1};
    get_encoder()(m, CU_TENSOR_MAP_DATA_TYPE_FLOAT16, 2, ptr, dims, strides, box, es,
                  CU_TENSOR_MAP_INTERLEAVE_NONE, CU_TENSOR_MAP_SWIZZLE_128B,
                  CU_TENSOR_MAP_L2_PROMOTION_L2_128B, CU_TENSOR_MAP_FLOAT_OOB_FILL_NONE);
}
static float* symaddr(const void* sym) {
    void* p = nullptr;
    cudaGetSymbolAddress(&p, sym);
    return (float*)p;
}

template<int MODE>
static void run_gemm(fp16* a, fp16* b,
                     float* C, const float* addC, const float* bias, const float* bias2,
                     fp16* outp, int M, int N, int K, cudaStream_t st) {
    CUtensorMap ma, mb;
    make_map(&ma, a, K, M);
    make_map(&mb, b, K, N);
    dim3 grid(N / 128, M / 128);
    gemm_tma<MODE><<<grid, 256, GEMM_SMEM, st>>>(ma, mb, C, addC, bias, bias2, outp, M, N, K);
}

extern "C" void kernel_launch(void* const* d_in, const int* in_sizes, int n_in,
                              void* d_out, int out_size) {
    const float* x     = (const float*)d_in[0];
    const int*   ids   = (const int*)d_in[1];
    const float* wq    = (const float*)d_in[3];
    const float* wk    = (const float*)d_in[4];
    const float* wv    = (const float*)d_in[5];
    const float* wo    = (const float*)d_in[6];
    const float* attnw = (const float*)d_in[7];
    const float* ffnw  = (const float*)d_in[8];
    const float* gatew = (const float*)d_in[9];
    const float* upw   = (const float*)d_in[10];
    const float* downw = (const float*)d_in[11];
    const float* embt  = (const float*)d_in[12];
    const float* keyw  = (const float*)d_in[13];
    const float* keyb  = (const float*)d_in[14];
    const float* valw  = (const float*)d_in[15];
    const float* valb  = (const float*)d_in[16];
    const float* normk = (const float*)d_in[17];
    const float* normq = (const float*)d_in[18];
    const float* convw = (const float*)d_in[19];
    const int*   hm    = (const int*)d_in[20];

    float* p_h   = symaddr(g_h);
    float* p_hn  = symaddr(g_hn);
    float* p_val = symaddr(g_value);
    float* p_kv  = symaddr(g_kv);
    fp16* p_a  = (fp16*)symaddr(g_a);
    fp16* p_s  = (fp16*)symaddr(g_s);
    fp16* p_e  = (fp16*)symaddr(g_e);
    fp16* p_q3 = (fp16*)symaddr(g_q3);
    fp16* p_b  = (fp16*)symaddr(g_b);
    float* out = (float*)d_out;

    static bool init_done = false;
    static cudaStream_t s2;
    static cudaEvent_t evStart, evW, evHn, evSide;
    if (!init_done) {
        cudaFuncSetAttribute(gemm_tma<0>, cudaFuncAttributeMaxDynamicSharedMemorySize, GEMM_SMEM);
        cudaFuncSetAttribute(gemm_tma<1>, cudaFuncAttributeMaxDynamicSharedMemorySize, GEMM_SMEM);
        cudaFuncSetAttribute(gemm_tma<2>, cudaFuncAttributeMaxDynamicSharedMemorySize, GEMM_SMEM);
        cudaFuncSetAttribute(flash_mma, cudaFuncAttributeMaxDynamicSharedMemorySize, FLASH_SMEM);
        cudaStreamCreateWithFlags(&s2, cudaStreamNonBlocking);
        cudaEventCreateWithFlags(&evStart, cudaEventDisableTiming);
        cudaEventCreateWithFlags(&evW, cudaEventDisableTiming);
        cudaEventCreateWithFlags(&evHn, cudaEventDisableTiming);
        cudaEventCreateWithFlags(&evSide, cudaEventDisableTiming);
        init_done = true;
    }

    dim3 blk(256);
    cudaStream_t s0 = 0;

    // ---- main stream: weight convert ----
    split_weights<<<(6*D2 + 3*F2 + 255) / 256, blk, 0, s0>>>(
        wq, wk, wv, wo, gatew, upw, downw, keyw, valw, p_b);
    cudaEventRecord(evStart, s0);   // fork point (after weights: side needs them)
    cudaEventRecord(evW, s0);

    // ---- side stream: engram branch ----
    cudaStreamWaitEvent(s2, evStart, 0);
    gather_k<<<BT, blk, 0, s2>>>(ids, embt, hm, p_e);
    cudaStreamWaitEvent(s2, evW, 0);
    run_gemm<0>(p_e, p_b + WOFF_KV, p_kv, nullptr, keyb, valb, nullptr, BT, 2048, DD, s2);

    // ---- main chain ----
    rmsnorm_k<<<BT, blk, 0, s0>>>(x, attnw, nullptr, p_a);
    run_gemm<1>(p_a, p_b + WOFF_QKV, nullptr, nullptr, nullptr, nullptr, p_q3, BT, 3072, DD, s0);
    flash_mma<<<dim3(TT / 64, BB * NHEAD), 128, FLASH_SMEM, s0>>>(p_q3, p_a);
    run_gemm<0>(p_a, p_b + WOFF_WO, p_h, x, nullptr, nullptr, nullptr, BT, DD, DD, s0);
    rmsnorm_k<<<BT, blk, 0, s0>>>(p_h, ffnw, p_hn, p_a);
    cudaEventRecord(evHn, s0);
    run_gemm<2>(p_a, p_b + WOFF_GU, nullptr, nullptr, nullptr, nullptr, p_s, BT, 2 * FFN, DD, s0);
    run_gemm<0>(p_s, p_b + WOFF_DOWN, out, p_h, nullptr, nullptr, nullptr, BT, DD, FFN, s0);

    // ---- side stream: gate (needs hn + kv) ----
    cudaStreamWaitEvent(s2, evHn, 0);
    gate_k<<<BT, blk, 0, s2>>>(p_hn, p_kv, normk, normq, p_val);
    cudaEventRecord(evSide, s2);

    // ---- join + final ----
    cudaStreamWaitEvent(s0, evSide, 0);
    final_k<<<(BT * DD) / 256, blk, 0, s0>>>(p_val, convw, out);
}

// round 9
// speedup vs baseline: 8.3081x; 1.0980x over previous
#include <cuda_runtime.h>
#include <cuda_fp16.h>
#include <cuda.h>
#include <math.h>
#include <stdint.h>

#define BB 2
#define TT 2048
#define DD 1024
#define NHEAD 16
#define HDIM 64
#define FFN 4096
#define BT (BB*TT)
#define NGV 50000

typedef __half fp16;

// ---------------- scratch (device globals; no allocation) ----------------
__device__ float g_h[BT*DD];
__device__ float g_hn[BT*DD];
__device__ float g_value[BT*DD];
__device__ float g_kv[(size_t)BT*2048];
__device__ __align__(1024) fp16 g_a[BT*DD];            // activations: xn, O, hn
__device__ __align__(1024) fp16 g_s[(size_t)BT*FFN];   // silu output
__device__ __align__(1024) fp16 g_e[BT*DD];            // engram emb
__device__ __align__(1024) fp16 g_q3[(size_t)BT*3072]; // rope'd qkv
// weights fp16: [qkv 3M][wo 1M][gate/up interleaved 8M][down 4M][key 1M][val 1M]
#define WOFF_QKV 0
#define WOFF_WO   (3u*1024*1024)
#define WOFF_GU   (4u*1024*1024)
#define WOFF_DOWN (12u*1024*1024)
#define WOFF_KV   (16u*1024*1024)
__device__ __align__(1024) fp16 g_b[18u*1024*1024];

extern __shared__ char dynsmem[];

// ================= low-level helpers =================
__device__ __forceinline__ uint32_t smem_u32(const void* p) {
    uint32_t a;
    asm("{ .reg .u64 t; cvta.to.shared.u64 t, %1; cvt.u32.u64 %0, t; }" : "=r"(a) : "l"(p));
    return a;
}
__device__ __forceinline__ uint32_t swz128(uint32_t o) { return o ^ ((o >> 3) & 0x70); }

#define MBAR_INIT(addr, cnt) \
    asm volatile("mbarrier.init.shared.b64 [%0], %1;" :: "r"((uint32_t)(addr)), "r"((uint32_t)(cnt)) : "memory")
#define MBAR_EXPECT_TX(addr, bytes) \
    asm volatile("mbarrier.arrive.expect_tx.shared.b64 _, [%0], %1;" :: "r"((uint32_t)(addr)), "r"((uint32_t)(bytes)) : "memory")
#define MBAR_WAIT(addr, parity) do { \
    uint32_t _m = (uint32_t)(addr); uint32_t _p = (uint32_t)(parity); uint32_t _d; \
    asm volatile("{\n\t.reg .pred p;\n\t" \
        "mbarrier.try_wait.parity.acquire.cta.shared::cta.b64 p, [%1], %2;\n\t" \
        "selp.b32 %0, 1, 0, p;\n\t}" : "=r"(_d) : "r"(_m), "r"(_p) : "memory"); \
    if (!_d) { \
        asm volatile("{\n\t.reg .pred P1;\n\t" \
            "WL_%=:\n\t" \
            "mbarrier.try_wait.parity.acquire.cta.shared::cta.b64 P1, [%0], %1, 0x989680;\n\t" \
            "@P1 bra.uni WD_%=;\n\t" \
            "bra.uni WL_%=;\n\t" \
            "WD_%=:\n\t}" :: "r"(_m), "r"(_p) : "memory"); \
    } \
} while (0)

#define TMA_LOAD2D(smem_addr, map_ptr, cx, cy, mbar) \
    asm volatile("cp.async.bulk.tensor.2d.shared::cta.global.tile.mbarrier::complete_tx::bytes " \
        "[%0], [%1, {%2, %3}], [%4];" \
        :: "r"((uint32_t)(smem_addr)), "l"(map_ptr), "r"((int)(cx)), "r"((int)(cy)), \
           "r"((uint32_t)(mbar)) : "memory")

__device__ __forceinline__ void ldsm4(uint32_t* r, uint32_t addr) {
    asm volatile("ldmatrix.sync.aligned.m8n8.x4.shared.b16 {%0,%1,%2,%3}, [%4];"
        : "=r"(r[0]), "=r"(r[1]), "=r"(r[2]), "=r"(r[3]) : "r"(addr));
}
__device__ __forceinline__ void ldsm4t(uint32_t* r, uint32_t addr) {
    asm volatile("ldmatrix.sync.aligned.m8n8.x4.trans.shared.b16 {%0,%1,%2,%3}, [%4];"
        : "=r"(r[0]), "=r"(r[1]), "=r"(r[2]), "=r"(r[3]) : "r"(addr));
}
__device__ __forceinline__ void mma16816(float* d, const uint32_t* a, const uint32_t* b) {
    asm volatile("mma.sync.aligned.m16n8k16.row.col.f32.f16.f16.f32 "
        "{%0,%1,%2,%3}, {%4,%5,%6,%7}, {%8,%9}, {%0,%1,%2,%3};"
        : "+f"(d[0]), "+f"(d[1]), "+f"(d[2]), "+f"(d[3])
        : "r"(a[0]), "r"(a[1]), "r"(a[2]), "r"(a[3]), "r"(b[0]), "r"(b[1]));
}
__device__ __forceinline__ uint32_t pack_h2(float x, float y) {
    __half2 h = __floats2half2_rn(x, y);
    return *(uint32_t*)&h;
}

// ================= TMA + mma.sync fp16 GEMM ====================
// CTA 128x128, BK=64 (SW128), 3 stages x 32KB, occ 2.
#define NSTG 3
#define TIL 16384
#define STG_B (2*TIL)
#define GEMM_SMEM (1024 + NSTG*STG_B)

template<int MODE>
__global__ void __launch_bounds__(256, 2) gemm_tma(
    const __grid_constant__ CUtensorMap ma,
    const __grid_constant__ CUtensorMap mb,
    float* __restrict__ C, const float* __restrict__ addC,
    const float* __restrict__ bias, const float* __restrict__ bias2,
    fp16* __restrict__ outp, int M, int N, int K)
{
    const uint32_t sb = smem_u32(dynsmem);
    const uint32_t fullb = sb;
    const uint32_t stg0 = sb + 1024;
    const int tid = threadIdx.x;
    const int wid = tid >> 5, lane = tid & 31;
    const int wm = wid & 3, wn = wid >> 2;
    const int m0 = blockIdx.y * 128, n0 = blockIdx.x * 128;
    const int NT = K >> 6;

    if (tid == 0) {
        #pragma unroll
        for (int s = 0; s < NSTG; s++) MBAR_INIT(fullb + 8*s, 1);
    }
    __syncthreads();
    if (tid == 0) {
        #pragma unroll
        for (int s = 0; s < 2; s++) {
            uint32_t st = stg0 + s * STG_B;
            MBAR_EXPECT_TX(fullb + 8*s, STG_B);
            TMA_LOAD2D(st,       &ma, s*64, m0, fullb + 8*s);
            TMA_LOAD2D(st + TIL, &mb, s*64, n0, fullb + 8*s);
        }
    }

    float acc[2][8][4];
    #pragma unroll
    for (int i = 0; i < 2; i++)
        #pragma unroll
        for (int j = 0; j < 8; j++)
            #pragma unroll
            for (int q = 0; q < 4; q++) acc[i][j][q] = 0.f;

    const int a_row0 = wm * 32 + (lane & 15);
    const int acbyte = (lane >> 4) * 16;
    const int b_rr = ((lane & 16) >> 1) + (lane & 7);
    const int bcbyte = (lane & 8) * 2;

    for (int kt = 0; kt < NT; kt++) {
        int s = kt % NSTG;
        MBAR_WAIT(fullb + 8*s, (kt / NSTG) & 1);
        uint32_t st = stg0 + s * STG_B;
        #pragma unroll
        for (int k16 = 0; k16 < 4; k16++) {
            const int kofb = k16 * 32;
            uint32_t a0[4], a1[4];
            uint32_t oa0 = swz128((uint32_t)(a_row0 * 128 + acbyte + kofb));
            uint32_t oa1 = swz128((uint32_t)((a_row0 + 16) * 128 + acbyte + kofb));
            ldsm4(a0, st + oa0);
            ldsm4(a1, st + oa1);
            #pragma unroll
            for (int p = 0; p < 4; p++) {
                uint32_t ob = swz128((uint32_t)((wn * 64 + p * 16 + b_rr) * 128 + bcbyte + kofb));
                uint32_t bf[4];
                ldsm4(bf, st + TIL + ob);
                mma16816(acc[0][2*p],   a0, bf);
                mma16816(acc[0][2*p+1], a0, bf + 2);
                mma16816(acc[1][2*p],   a1, bf);
                mma16816(acc[1][2*p+1], a1, bf + 2);
            }
        }
        __syncthreads();
        if (tid == 0 && kt + 2 < NT) {
            int s2 = (kt + 2) % NSTG;
            uint32_t st2 = stg0 + s2 * STG_B;
            MBAR_EXPECT_TX(fullb + 8*s2, STG_B);
            TMA_LOAD2D(st2,       &ma, (kt+2)*64, m0, fullb + 8*s2);
            TMA_LOAD2D(st2 + TIL, &mb, (kt+2)*64, n0, fullb + 8*s2);
        }
    }

    const int g = lane >> 2, t2 = (lane & 3) * 2;
    const int base_c = n0 + wn * 64;

    if (MODE == 0) {
        #pragma unroll
        for (int mt = 0; mt < 2; mt++)
            #pragma unroll
            for (int nt = 0; nt < 8; nt++) {
                int grow = m0 + wm * 32 + mt * 16 + g;
                int gcol = base_c + nt * 8 + t2;
                float2 v0 = make_float2(acc[mt][nt][0], acc[mt][nt][1]);
                float2 v1 = make_float2(acc[mt][nt][2], acc[mt][nt][3]);
                if (bias) {
                    const float* bp = (gcol < (N >> 1)) ? bias + gcol : bias2 + gcol - (N >> 1);
                    float2 bv = *(const float2*)bp;
                    v0.x += bv.x; v0.y += bv.y; v1.x += bv.x; v1.y += bv.y;
                }
                if (addC) {
                    float2 d0 = *(const float2*)(addC + (size_t)grow * N + gcol);
                    float2 d1 = *(const float2*)(addC + (size_t)(grow + 8) * N + gcol);
                    v0.x += d0.x; v0.y += d0.y; v1.x += d1.x; v1.y += d1.y;
                }
                *(float2*)(C + (size_t)grow * N + gcol) = v0;
                *(float2*)(C + (size_t)(grow + 8) * N + gcol) = v1;
            }
    } else if (MODE == 1) {
        #pragma unroll
        for (int mt = 0; mt < 2; mt++)
            #pragma unroll
            for (int rr = 0; rr < 2; rr++) {
                int row = m0 + wm * 32 + mt * 16 + g + rr * 8;
                float ft = (float)(row & (TT - 1));
                size_t rb = (size_t)row * N;
                if (base_c < 2048) {  // q or k: rope
                    #pragma unroll
                    for (int nt = 0; nt < 4; nt++) {
                        int cc = base_c + nt * 8 + t2;
                        int d0 = cc & 63;
                        float inv0 = expf(-(float)(2*d0)     * (1.0f/64.0f) * 9.2103403719761836f);
                        float inv1 = expf(-(float)(2*(d0+1)) * (1.0f/64.0f) * 9.2103403719761836f);
                        float s0, c0, s1, c1;
                        sincosf(ft * inv0, &s0, &c0);
                        sincosf(ft * inv1, &s1, &c1);
                        float vl0 = acc[mt][nt][rr*2],   vl1 = acc[mt][nt][rr*2+1];
                        float vh0 = acc[mt][nt+4][rr*2], vh1 = acc[mt][nt+4][rr*2+1];
                        float ol0 = vl0 * c0 - vh0 * s0, oh0 = vh0 * c0 + vl0 * s0;
                        float ol1 = vl1 * c1 - vh1 * s1, oh1 = vh1 * c1 + vl1 * s1;
                        *(uint32_t*)(outp + rb + cc)      = pack_h2(ol0, ol1);
                        *(uint32_t*)(outp + rb + cc + 32) = pack_h2(oh0, oh1);
                    }
                } else {  // v: plain
                    #pragma unroll
                    for (int nt = 0; nt < 8; nt++) {
                        int cc = base_c + nt * 8 + t2;
                        *(uint32_t*)(outp + rb + cc) =
                            pack_h2(acc[mt][nt][rr*2], acc[mt][nt][rr*2+1]);
                    }
                }
            }
    } else {  // MODE 2: silu(gate)*up, interleaved cols
        const int NO = N >> 1;
        #pragma unroll
        for (int mt = 0; mt < 2; mt++)
            #pragma unroll
            for (int rr = 0; rr < 2; rr++) {
                int row = m0 + wm * 32 + mt * 16 + g + rr * 8;
                size_t rb = (size_t)row * NO;
                #pragma unroll
                for (int nt = 0; nt < 8; nt++) {
                    float gg = acc[mt][nt][rr*2];
                    float uu = acc[mt][nt][rr*2+1];
                    float sv = gg / (1.f + expf(-gg)) * uu;
                    int j = (base_c + nt * 8 + t2) >> 1;
                    outp[rb + j] = __float2half_rn(sv);
                }
            }
    }
}

// ---------------- all-weights convert to fp16 (gate/up interleaved) ------
#define D2 262144u
#define F2 1048576u
__global__ void split_weights(
    const float* __restrict__ wq, const float* __restrict__ wk,
    const float* __restrict__ wv, const float* __restrict__ wo,
    const float* __restrict__ gw, const float* __restrict__ uw,
    const float* __restrict__ dw, const float* __restrict__ kw,
    const float* __restrict__ vw, fp16* __restrict__ bh)
{
    uint32_t i = blockIdx.x * 256 + threadIdx.x;
    const float* src;
    uint32_t oo;
    if (i < 3*D2) {
        src = (i < D2) ? wq + 4*(size_t)i : (i < 2*D2) ? wk + 4*(size_t)(i - D2) : wv + 4*(size_t)(i - 2*D2);
        oo = i;
    } else if (i < 4*D2) {
        src = wo + 4*(size_t)(i - 3*D2);
        oo = i;
    } else if (i < 4*D2 + F2) {
        uint32_t loc = i - 4*D2;
        uint32_t r = loc >> 8, c = loc & 255;
        src = gw + 4*(size_t)loc;
        oo = 4*D2 + (2*r) * 256 + c;
    } else if (i < 4*D2 + 2*F2) {
        uint32_t loc = i - 4*D2 - F2;
        uint32_t r = loc >> 8, c = loc & 255;
        src = uw + 4*(size_t)loc;
        oo = 4*D2 + (2*r + 1) * 256 + c;
    } else if (i < 4*D2 + 3*F2) {
        src = dw + 4*(size_t)(i - 4*D2 - 2*F2);
        oo = i;
    } else if (i < 5*D2 + 3*F2) {
        src = kw + 4*(size_t)(i - 4*D2 - 3*F2);
        oo = i;
    } else if (i < 6*D2 + 3*F2) {
        src = vw + 4*(size_t)(i - 5*D2 - 3*F2);
        oo = i;
    } else return;
    float4 v = *(const float4*)src;
    ((uint32_t*)bh)[(size_t)oo*2]   = pack_h2(v.x, v.y);
    ((uint32_t*)bh)[(size_t)oo*2+1] = pack_h2(v.z, v.w);
}

// ---------------- RMSNorm (optional fp32 out + fp16 out) ----------------
__global__ void rmsnorm_k(const float* __restrict__ x, const float* __restrict__ w,
                          float* __restrict__ y, fp16* __restrict__ o16) {
    int row = blockIdx.x, tid = threadIdx.x;
    float4 xv = ((const float4*)(x + (size_t)row * DD))[tid];
    float ss = xv.x*xv.x + xv.y*xv.y + xv.z*xv.z + xv.w*xv.w;
    #pragma unroll
    for (int o = 16; o; o >>= 1) ss += __shfl_xor_sync(0xffffffffu, ss, o);
    __shared__ float red[8];
    if ((tid & 31) == 0) red[tid >> 5] = ss;
    __syncthreads();
    float tot = 0.f;
    #pragma unroll
    for (int i = 0; i < 8; i++) tot += red[i];
    float inv = rsqrtf(tot * (1.0f / DD) + 1e-6f);
    float4 wv = ((const float4*)w)[tid];
    float4 r;
    r.x = xv.x * inv * wv.x; r.y = xv.y * inv * wv.y;
    r.z = xv.z * inv * wv.z; r.w = xv.w * inv * wv.w;
    if (y) ((float4*)(y + (size_t)row * DD))[tid] = r;
    size_t base = (size_t)row * DD;
    ((uint32_t*)(o16 + base))[2*tid]   = pack_h2(r.x, r.y);
    ((uint32_t*)(o16 + base))[2*tid+1] = pack_h2(r.z, r.w);
}

// ---------------- Flash attention: Q-tile 128, trans-V, fp16 -------
#define FP 72
#define FLASH_SMEM ((128 + 64 + 64) * FP * 2)

__global__ void __launch_bounds__(256) flash_mma(
    const fp16* __restrict__ qkv, fp16* __restrict__ o16)
{
    fp16* Qs = (fp16*)dynsmem;            // [128][FP]
    fp16* Ks = Qs + 128 * FP;             // [64][FP]
    fp16* Vs = Ks + 64 * FP;              // [64][FP] row-major (token, d)
    const uint32_t uQ = smem_u32(Qs), uK = smem_u32(Ks), uV = smem_u32(Vs);

    const int qt = gridDim.x - 1 - blockIdx.x;   // heavy tiles first
    const int bh = blockIdx.y;
    const int b = bh >> 4, h = bh & 15;
    const int q0 = qt * 128;
    const int tid = threadIdx.x;
    const int wid = tid >> 5, lane = tid & 31;
    const int g = lane >> 2, t2 = (lane & 3) * 2;

    const fp16* qb = qkv + ((size_t)(b * TT + q0)) * 3072 + h * 64;
    for (int i = tid; i < 1024; i += 256) {
        int m = i >> 3, c8 = (i & 7) * 8;
        *(uint4*)&Qs[m * FP + c8] = *(const uint4*)(qb + (size_t)m * 3072 + c8);
    }

    float m0r = -1e30f, m1r = -1e30f, l0r = 0.f, l1r = 0.f;
    float oacc[8][4];
    #pragma unroll
    for (int i = 0; i < 8; i++)
        #pragma unroll
        for (int j = 0; j < 4; j++) oacc[i][j] = 0.f;

    const int a_rb = (wid * 16 + (lane & 15)) * FP;
    const int a_cb = ((lane >> 4) << 3);
    const int b_rr = ((lane & 16) >> 1) + (lane & 7);
    const int b_cb = (lane & 8);
    const int v_rr = lane & 15;             // trans-V: token row within 16-group
    const int v_cb = (lane & 16) >> 1;      // trans-V: d col offset (0 or 8)

    const int NKT = 2 * qt + 2;             // k-tiles of 64 tokens
    for (int kt = 0; kt < NKT; kt++) {
        __syncthreads();
        {
            const fp16* kb = qkv + ((size_t)(b * TT + kt * 64)) * 3072 + 1024 + h * 64;
            const fp16* vb = qkv + ((size_t)(b * TT + kt * 64)) * 3072 + 2048 + h * 64;
            for (int i = tid; i < 512; i += 256) {
                int n = i >> 3, c8 = (i & 7) * 8;
                *(uint4*)&Ks[n * FP + c8] = *(const uint4*)(kb + (size_t)n * 3072 + c8);
                *(uint4*)&Vs[n * FP + c8] = *(const uint4*)(vb + (size_t)n * 3072 + c8);
            }
        }
        __syncthreads();

        float sacc[8][4];
        #pragma unroll
        for (int i = 0; i < 8; i++)
            #pragma unroll
            for (int j = 0; j < 4; j++) sacc[i][j] = 0.f;
        #pragma unroll
        for (int k16 = 0; k16 < 4; k16++) {
            const int kof = k16 * 16;
            uint32_t af[4];
            ldsm4(af, uQ + (uint32_t)(a_rb + kof + a_cb) * 2);
            uint32_t bf[4][4];
            #pragma unroll
            for (int p = 0; p < 4; p++)
                ldsm4(bf[p], uK + (uint32_t)((p * 16 + b_rr) * FP + kof + b_cb) * 2);
            #pragma unroll
            for (int nt = 0; nt < 8; nt++)
                mma16816(sacc[nt], af, &bf[nt >> 1][(nt & 1) * 2]);
        }

        const int qrow0 = q0 + wid * 16 + g;
        const int qrow1 = qrow0 + 8;
        #pragma unroll
        for (int nt = 0; nt < 8; nt++) {
            int c0 = kt * 64 + nt * 8 + t2;
            float v0 = sacc[nt][0] * 0.125f;
            float v1 = sacc[nt][1] * 0.125f;
            float v2 = sacc[nt][2] * 0.125f;
            float v3 = sacc[nt][3] * 0.125f;
            if (c0 > qrow0) v0 = -1e30f;
            if (c0 + 1 > qrow0) v1 = -1e30f;
            if (c0 > qrow1) v2 = -1e30f;
            if (c0 + 1 > qrow1) v3 = -1e30f;
            sacc[nt][0] = v0; sacc[nt][1] = v1; sacc[nt][2] = v2; sacc[nt][3] = v3;
        }
        float rm0 = -1e30f, rm1 = -1e30f;
        #pragma unroll
        for (int nt = 0; nt < 8; nt++) {
            rm0 = fmaxf(rm0, fmaxf(sacc[nt][0], sacc[nt][1]));
            rm1 = fmaxf(rm1, fmaxf(sacc[nt][2], sacc[nt][3]));
        }
        rm0 = fmaxf(rm0, __shfl_xor_sync(0xffffffffu, rm0, 1));
        rm0 = fmaxf(rm0, __shfl_xor_sync(0xffffffffu, rm0, 2));
        rm1 = fmaxf(rm1, __shfl_xor_sync(0xffffffffu, rm1, 1));
        rm1 = fmaxf(rm1, __shfl_xor_sync(0xffffffffu, rm1, 2));
        float mn0 = fmaxf(m0r, rm0), mn1 = fmaxf(m1r, rm1);
        float cor0 = __expf(m0r - mn0), cor1 = __expf(m1r - mn1);
        float sum0 = 0.f, sum1 = 0.f;
        #pragma unroll
        for (int nt = 0; nt < 8; nt++) {
            sacc[nt][0] = __expf(sacc[nt][0] - mn0);
            sacc[nt][1] = __expf(sacc[nt][1] - mn0);
            sacc[nt][2] = __expf(sacc[nt][2] - mn1);
            sacc[nt][3] = __expf(sacc[nt][3] - mn1);
            sum0 += sacc[nt][0] + sacc[nt][1];
            sum1 += sacc[nt][2] + sacc[nt][3];
        }
        sum0 += __shfl_xor_sync(0xffffffffu, sum0, 1);
        sum0 += __shfl_xor_sync(0xffffffffu, sum0, 2);
        sum1 += __shfl_xor_sync(0xffffffffu, sum1, 1);
        sum1 += __shfl_xor_sync(0xffffffffu, sum1, 2);
        l0r = l0r * cor0 + sum0; m0r = mn0;
        l1r = l1r * cor1 + sum1; m1r = mn1;
        #pragma unroll
        for (int dt = 0; dt < 8; dt++) {
            oacc[dt][0] *= cor0; oacc[dt][1] *= cor0;
            oacc[dt][2] *= cor1; oacc[dt][3] *= cor1;
        }
        #pragma unroll
        for (int j = 0; j < 4; j++) {
            uint32_t pf[4];
            pf[0] = pack_h2(sacc[2*j][0],   sacc[2*j][1]);
            pf[1] = pack_h2(sacc[2*j][2],   sacc[2*j][3]);
            pf[2] = pack_h2(sacc[2*j+1][0], sacc[2*j+1][1]);
            pf[3] = pack_h2(sacc[2*j+1][2], sacc[2*j+1][3]);
            #pragma unroll
            for (int dp = 0; dp < 4; dp++) {
                uint32_t vb4[4];
                ldsm4t(vb4, uV + (uint32_t)((16*j + v_rr) * FP + dp*16 + v_cb) * 2);
                mma16816(oacc[2*dp],   pf, &vb4[0]);
                mma16816(oacc[2*dp+1], pf, &vb4[2]);
            }
        }
    }

    float inv0 = 1.0f / l0r, inv1 = 1.0f / l1r;
    size_t ob0 = (size_t)b * TT * DD + (size_t)(q0 + wid * 16 + g) * DD + h * HDIM;
    size_t ob1 = ob0 + 8 * DD;
    #pragma unroll
    for (int dt = 0; dt < 8; dt++) {
        *(uint32_t*)(o16 + ob0 + dt*8 + t2) = pack_h2(oacc[dt][0] * inv0, oacc[dt][1] * inv0);
        *(uint32_t*)(o16 + ob1 + dt*8 + t2) = pack_h2(oacc[dt][2] * inv1, oacc[dt][3] * inv1);
    }
}

// ---------------- engram hash + gather -> fp16 ----------------
__global__ void gather_k(const int* __restrict__ ids, const float* __restrict__ tables,
                         const int* __restrict__ hm, fp16* __restrict__ o16) {
    int tok = blockIdx.x;
    int t = tok & (TT - 1);
    int id0 = ids[tok];
    int id1 = (t >= 1) ? ids[tok - 1] : 0;
    int id2 = (t >= 2) ? ids[tok - 2] : 0;
    unsigned m0 = (unsigned)hm[0], m1 = (unsigned)hm[1], m2 = (unsigned)hm[2];
    unsigned h2 = (unsigned)id0 * m0 ^ (unsigned)id1 * m1;
    unsigned h3 = h2 ^ (unsigned)id2 * m2;
    int tid = threadIdx.x;
    size_t ob = (size_t)tok * 1024;
    #pragma unroll
    for (int r = 0; r < 4; r++) {
        int e = tid + r * 256;
        int tt = e >> 6, ee = e & 63;
        int head = tt & 7;
        unsigned hh = ((tt < 8) ? h2 : h3) + (unsigned)(head * 7919);
        int sv = (int)hh;
        int idx = sv % NGV;
        if (idx < 0) idx += NGV;
        o16[ob + e] = __float2half_rn(tables[((size_t)tt * NGV + idx) * 64 + ee]);
    }
}

// ---------------- gate ----------------
__global__ void gate_k(const float* __restrict__ hn, const float* __restrict__ kvb,
                       const float* __restrict__ nkw, const float* __restrict__ nqw,
                       float* __restrict__ value) {
    int row = blockIdx.x, tid = threadIdx.x;
    const float* keye = kvb + (size_t)row * 2048;
    const float* vale = keye + 1024;
    float4 kv = ((const float4*)keye)[tid];
    float4 hv = ((const float4*)(hn + (size_t)row * DD))[tid];
    float4 wk = ((const float4*)nkw)[tid];
    float4 wq = ((const float4*)nqw)[tid];
    float skk = kv.x*kv.x + kv.y*kv.y + kv.z*kv.z + kv.w*kv.w;
    float shh = hv.x*hv.x + hv.y*hv.y + hv.z*hv.z + hv.w*hv.w;
    float sdt = kv.x*wk.x*hv.x*wq.x + kv.y*wk.y*hv.y*wq.y
              + kv.z*wk.z*hv.z*wq.z + kv.w*wk.w*hv.w*wq.w;
    #pragma unroll
    for (int o = 16; o; o >>= 1) {
        skk += __shfl_xor_sync(0xffffffffu, skk, o);
        shh += __shfl_xor_sync(0xffffffffu, shh, o);
        sdt += __shfl_xor_sync(0xffffffffu, sdt, o);
    }
    __shared__ float r1[8], r2[8], r3[8];
    if ((tid & 31) == 0) { r1[tid>>5] = skk; r2[tid>>5] = shh; r3[tid>>5] = sdt; }
    __syncthreads();
    float tkk = 0, thh = 0, tdt = 0;
    #pragma unroll
    for (int i = 0; i < 8; i++) { tkk += r1[i]; thh += r2[i]; tdt += r3[i]; }
    float nk = rsqrtf(tkk * (1.0f / DD) + 1e-6f);
    float nh = rsqrtf(thh * (1.0f / DD) + 1e-6f);
    float gg = tdt * nk * nh * (1.0f / 32.0f);
    float ab = fabsf(gg);
    float rt = sqrtf(fmaxf(ab, 1e-6f));
    float sgn = (gg > 0.f) ? 1.f : ((gg < 0.f) ? -1.f : 0.f);
    float sig = 1.f / (1.f + expf(-rt * sgn));
    float4 vv = ((const float4*)vale)[tid];
    float4 r = make_float4(sig*vv.x, sig*vv.y, sig*vv.z, sig*vv.w);
    ((float4*)(value + (size_t)row * DD))[tid] = r;
}

// ---------------- final ----------------
__global__ void final_k(const float* __restrict__ value, const float* __restrict__ cw,
                        float* __restrict__ out) {
    int idx = blockIdx.x * 256 + threadIdx.x;
    int d = idx & (DD - 1);
    int bt = idx >> 10;
    int t = bt & (TT - 1);
    float c = 0.f;
    #pragma unroll
    for (int kk = 0; kk < 4; kk++) {
        int tt = t - 3 + kk;
        if (tt >= 0)
            c += value[(size_t)(bt - 3 + kk) * DD + d] * cw[d * 4 + kk];
    }
    float vv = value[idx];
    float sc = c / (1.f + expf(-c));
    out[idx] += vv + sc;
}

// ================= host =================
typedef CUresult (*PFN_encode)(CUtensorMap*, CUtensorMapDataType, cuuint32_t, void*,
                               const cuuint64_t*, const cuuint64_t*, const cuuint32_t*,
                               const cuuint32_t*, CUtensorMapInterleave, CUtensorMapSwizzle,
                               CUtensorMapL2promotion, CUtensorMapFloatOOBfill);
static PFN_encode get_encoder() {
    static PFN_encode fn = nullptr;
    if (!fn) {
        void* p = nullptr;
        cudaDriverEntryPointQueryResult qr;
        cudaGetDriverEntryPoint("cuTensorMapEncodeTiled", &p, cudaEnableDefault, &qr);
        fn = (PFN_encode)p;
    }
    return fn;
}
static void make_map(CUtensorMap* m, void* ptr, uint64_t Kdim, uint64_t Rows) {
    cuuint64_t dims[2] = {Kdim, Rows};
    cuuint64_t strides[1] = {Kdim * 2};
    cuuint32_t box[2] = {64, 128};
    cuuint32_t es[2] = {1, 1};
    get_encoder()(m, CU_TENSOR_MAP_DATA_TYPE_FLOAT16, 2, ptr, dims, strides, box, es,
                  CU_TENSOR_MAP_INTERLEAVE_NONE, CU_TENSOR_MAP_SWIZZLE_128B,
                  CU_TENSOR_MAP_L2_PROMOTION_L2_128B, CU_TENSOR_MAP_FLOAT_OOB_FILL_NONE);
}
static float* symaddr(const void* sym) {
    void* p = nullptr;
    cudaGetSymbolAddress(&p, sym);
    return (float*)p;
}

template<int MODE>
static void run_gemm(fp16* a, fp16* b,
                     float* C, const float* addC, const float* bias, const float* bias2,
                     fp16* outp, int M, int N, int K, cudaStream_t st) {
    CUtensorMap ma, mb;
    make_map(&ma, a, K, M);
    make_map(&mb, b, K, N);
    dim3 grid(N / 128, M / 128);
    gemm_tma<MODE><<<grid, 256, GEMM_SMEM, st>>>(ma, mb, C, addC, bias, bias2, outp, M, N, K);
}

extern "C" void kernel_launch(void* const* d_in, const int* in_sizes, int n_in,
                              void* d_out, int out_size) {
    const float* x     = (const float*)d_in[0];
    const int*   ids   = (const int*)d_in[1];
    const float* wq    = (const float*)d_in[3];
    const float* wk    = (const float*)d_in[4];
    const float* wv    = (const float*)d_in[5];
    const float* wo    = (const float*)d_in[6];
    const float* attnw = (const float*)d_in[7];
    const float* ffnw  = (const float*)d_in[8];
    const float* gatew = (const float*)d_in[9];
    const float* upw   = (const float*)d_in[10];
    const float* downw = (const float*)d_in[11];
    const float* embt  = (const float*)d_in[12];
    const float* keyw  = (const float*)d_in[13];
    const float* keyb  = (const float*)d_in[14];
    const float* valw  = (const float*)d_in[15];
    const float* valb  = (const float*)d_in[16];
    const float* normk = (const float*)d_in[17];
    const float* normq = (const float*)d_in[18];
    const float* convw = (const float*)d_in[19];
    const int*   hm    = (const int*)d_in[20];

    float* p_h   = symaddr(g_h);
    float* p_hn  = symaddr(g_hn);
    float* p_val = symaddr(g_value);
    float* p_kv  = symaddr(g_kv);
    fp16* p_a  = (fp16*)symaddr(g_a);
    fp16* p_s  = (fp16*)symaddr(g_s);
    fp16* p_e  = (fp16*)symaddr(g_e);
    fp16* p_q3 = (fp16*)symaddr(g_q3);
    fp16* p_b  = (fp16*)symaddr(g_b);
    float* out = (float*)d_out;

    static bool init_done = false;
    static cudaStream_t s2;
    static cudaEvent_t evStart, evW, evHn, evSide;
    if (!init_done) {
        cudaFuncSetAttribute(gemm_tma<0>, cudaFuncAttributeMaxDynamicSharedMemorySize, GEMM_SMEM);
        cudaFuncSetAttribute(gemm_tma<1>, cudaFuncAttributeMaxDynamicSharedMemorySize, GEMM_SMEM);
        cudaFuncSetAttribute(gemm_tma<2>, cudaFuncAttributeMaxDynamicSharedMemorySize, GEMM_SMEM);
        cudaFuncSetAttribute(flash_mma, cudaFuncAttributeMaxDynamicSharedMemorySize, FLASH_SMEM);
        cudaStreamCreateWithFlags(&s2, cudaStreamNonBlocking);
        cudaEventCreateWithFlags(&evStart, cudaEventDisableTiming);
        cudaEventCreateWithFlags(&evW, cudaEventDisableTiming);
        cudaEventCreateWithFlags(&evHn, cudaEventDisableTiming);
        cudaEventCreateWithFlags(&evSide, cudaEventDisableTiming);
        init_done = true;
    }

    dim3 blk(256);
    cudaStream_t s0 = 0;

    // fork point FIRST so gather overlaps the weight convert
    cudaEventRecord(evStart, s0);
    cudaStreamWaitEvent(s2, evStart, 0);
    gather_k<<<BT, blk, 0, s2>>>(ids, embt, hm, p_e);

    // main stream: weight convert
    split_weights<<<(6*D2 + 3*F2 + 255) / 256, blk, 0, s0>>>(
        wq, wk, wv, wo, gatew, upw, downw, keyw, valw, p_b);
    cudaEventRecord(evW, s0);

    // side stream: kv GEMM (needs weights + emb)
    cudaStreamWaitEvent(s2, evW, 0);
    run_gemm<0>(p_e, p_b + WOFF_KV, p_kv, nullptr, keyb, valb, nullptr, BT, 2048, DD, s2);

    // main chain
    rmsnorm_k<<<BT, blk, 0, s0>>>(x, attnw, nullptr, p_a);
    run_gemm<1>(p_a, p_b + WOFF_QKV, nullptr, nullptr, nullptr, nullptr, p_q3, BT, 3072, DD, s0);
    flash_mma<<<dim3(TT / 128, BB * NHEAD), 256, FLASH_SMEM, s0>>>(p_q3, p_a);
    run_gemm<0>(p_a, p_b + WOFF_WO, p_h, x, nullptr, nullptr, nullptr, BT, DD, DD, s0);
    rmsnorm_k<<<BT, blk, 0, s0>>>(p_h, ffnw, p_hn, p_a);
    cudaEventRecord(evHn, s0);
    run_gemm<2>(p_a, p_b + WOFF_GU, nullptr, nullptr, nullptr, nullptr, p_s, BT, 2 * FFN, DD, s0);
    run_gemm<0>(p_s, p_b + WOFF_DOWN, out, p_h, nullptr, nullptr, nullptr, BT, DD, FFN, s0);

    // side stream: gate (needs hn + kv)
    cudaStreamWaitEvent(s2, evHn, 0);
    gate_k<<<BT, blk, 0, s2>>>(p_hn, p_kv, normk, normq, p_val);
    cudaEventRecord(evSide, s2);

    // join + final
    cudaStreamWaitEvent(s0, evSide, 0);
    final_k<<<(BT * DD) / 256, blk, 0, s0>>>(p_val, convw, out);
}